// round 8
// baseline (speedup 1.0000x reference)
#include <cuda_runtime.h>
#include <cuda_bf16.h>
#include <cstdint>
#include <cstddef>

#define NTOK 16384
#define DDIM 512
#define KCB  1024
#define NB   8

// ---------------- scratch (static device globals; no allocations) ----------
__device__ float g_h  [NTOK * DDIM];    // pre-LN MLP temp
__device__ float g_z  [NTOK * DDIM];    // encoder output (post-LN)
__device__ float g_zq [NTOK * DDIM];    // quantized
__device__ float g_dot[NTOK * KCB];     // z @ codebook^T
__device__ __align__(128) __nv_bfloat16 g_ah[NTOK * KCB];   // A-side split hi
__device__ __align__(128) __nv_bfloat16 g_al[NTOK * KCB];   // A-side split lo
__device__ __align__(128) __nv_bfloat16 g_wh[4 * DDIM * DDIM]; // transposed weights hi
__device__ __align__(128) __nv_bfloat16 g_wl[4 * DDIM * DDIM];
__device__ __align__(128) __nv_bfloat16 g_cbh [KCB * DDIM];    // codebook split
__device__ __align__(128) __nv_bfloat16 g_cbl [KCB * DDIM];
__device__ __align__(128) __nv_bfloat16 g_cbth[DDIM * KCB];    // codebook^T split
__device__ __align__(128) __nv_bfloat16 g_cbtl[DDIM * KCB];
__device__ float  g_zz [NTOK];
__device__ float  g_cc [KCB];
__device__ float  g_avgp[KCB];
__device__ double g_kldd;
__device__ double g_kldc;

// ---------------- PTX helpers ----------------------------------------------
__device__ __forceinline__ uint32_t smem_u32(const void* p) {
    uint32_t a;
    asm("{ .reg .u64 t; cvta.to.shared.u64 t, %1; cvt.u32.u64 %0, t; }"
        : "=r"(a) : "l"(p));
    return a;
}

#define CP_ASYNC16(s, g) \
    asm volatile("cp.async.cg.shared.global [%0], [%1], 16;" :: "r"(s), "l"(g))
#define CP_COMMIT() asm volatile("cp.async.commit_group;" ::: "memory")
#define CP_WAIT(n)  asm volatile("cp.async.wait_group %0;" :: "n"(n) : "memory")

#define LDSM4(r, addr) \
    asm volatile("ldmatrix.sync.aligned.m8n8.x4.shared.b16 {%0,%1,%2,%3}, [%4];" \
        : "=r"((r)[0]), "=r"((r)[1]), "=r"((r)[2]), "=r"((r)[3]) : "r"(addr) : "memory")

#define MMA_BF16(D, A, B0, B1) \
    asm volatile("mma.sync.aligned.m16n8k16.row.col.f32.bf16.bf16.f32 " \
        "{%0,%1,%2,%3}, {%4,%5,%6,%7}, {%8,%9}, {%0,%1,%2,%3};" \
        : "+f"((D)[0]), "+f"((D)[1]), "+f"((D)[2]), "+f"((D)[3]) \
        : "r"((A)[0]), "r"((A)[1]), "r"((A)[2]), "r"((A)[3]), "r"(B0), "r"(B1))

__device__ __forceinline__ uint32_t sw128(uint32_t off) {
    return off ^ ((off >> 3) & 0x70);
}

// ---------------- tile loader: 128 rows x 64 bf16 cols, SW128 swizzled ------
// 512 threads: each thread loads 2 x 16B chunks per tile
__device__ __forceinline__ void load_tile(uint32_t tb, const __nv_bfloat16* __restrict__ src,
                                          int r0, int k0, int K, int tid)
{
    #pragma unroll
    for (int i = 0; i < 2; i++) {
        int u = tid + (i << 9);
        int row = u >> 3, col8 = (u & 7) << 3;
        const __nv_bfloat16* gp = src + (size_t)(r0 + row) * K + k0 + col8;
        uint32_t off = (uint32_t)((row << 7) + (col8 << 1));
        CP_ASYNC16(tb + sw128(off), gp);
    }
}

// ---------------- mma.sync bf16x3 GEMM: C = (Ah+Al)@(Bh+Bl)^T ---------------
// 512 threads, 16 warps in 4x4, each warp 32x32. 3-stage cp.async pipeline.
#define SMEM_STAGE 65536
#define SMEM_GEMM  (3 * SMEM_STAGE)

template<bool BIASRELU>
__global__ void __launch_bounds__(512, 1) mma_gemm(
    const __nv_bfloat16* __restrict__ Ah, const __nv_bfloat16* __restrict__ Al,
    const __nv_bfloat16* __restrict__ Bh, const __nv_bfloat16* __restrict__ Bl,
    const float* __restrict__ bias, float* __restrict__ C,
    int M, int N, int K)
{
    extern __shared__ char smem[];
    const int tid  = threadIdx.x;
    const int wid  = tid >> 5, lane = tid & 31;
    const int wm   = wid & 3, wn = wid >> 2;      // 4x4 warp grid: 32x32 per warp
    const uint32_t sb = smem_u32(smem);

    const int row0 = blockIdx.y << 7, col0 = blockIdx.x << 7;
    const int nk = K >> 6;

    float acc[2][4][4];
    #pragma unroll
    for (int i = 0; i < 2; i++)
        #pragma unroll
        for (int j = 0; j < 4; j++)
            #pragma unroll
            for (int r = 0; r < 4; r++) acc[i][j][r] = 0.f;

    // per-lane ldmatrix bases within a 128x64 bf16 tile (128B rows)
    const uint32_t a_row  = (uint32_t)(lane & 15);
    const uint32_t a_koff = (uint32_t)((lane >> 4) << 4);
    const uint32_t b_row  = (uint32_t)(((lane >> 4) << 3) + (lane & 7));
    const uint32_t b_koff = (uint32_t)(((lane >> 3) & 1) << 4);

    // prologue: stages 0, 1
    load_tile(sb + 0,     Ah, row0, 0, K, tid);
    load_tile(sb + 16384, Al, row0, 0, K, tid);
    load_tile(sb + 32768, Bh, col0, 0, K, tid);
    load_tile(sb + 49152, Bl, col0, 0, K, tid);
    CP_COMMIT();
    if (nk > 1) {
        load_tile(sb + SMEM_STAGE + 0,     Ah, row0, 64, K, tid);
        load_tile(sb + SMEM_STAGE + 16384, Al, row0, 64, K, tid);
        load_tile(sb + SMEM_STAGE + 32768, Bh, col0, 64, K, tid);
        load_tile(sb + SMEM_STAGE + 49152, Bl, col0, 64, K, tid);
        CP_COMMIT();
    }

    int buf = 0;
    for (int kt = 0; kt < nk; kt++) {
        if (kt + 1 < nk) CP_WAIT(1); else CP_WAIT(0);
        __syncthreads();

        // issue loads for stage kt+2 (buffer freed by the sync above)
        if (kt + 2 < nk) {
            const int k0 = (kt + 2) << 6;
            int nbuf = buf + 2; if (nbuf >= 3) nbuf -= 3;
            const uint32_t st = sb + nbuf * SMEM_STAGE;
            load_tile(st + 0,     Ah, row0, k0, K, tid);
            load_tile(st + 16384, Al, row0, k0, K, tid);
            load_tile(st + 32768, Bh, col0, k0, K, tid);
            load_tile(st + 49152, Bl, col0, k0, K, tid);
            CP_COMMIT();
        }

        const uint32_t stA_h = sb + buf * SMEM_STAGE;
        const uint32_t stA_l = stA_h + 16384;
        const uint32_t stB_h = stA_h + 32768;
        const uint32_t stB_l = stA_h + 49152;

        #pragma unroll
        for (int ks = 0; ks < 4; ks++) {
            const uint32_t k0b = (uint32_t)(ks << 5);
            uint32_t ah[2][4], al[2][4], bh[2][4], bl[2][4];
            #pragma unroll
            for (int mt = 0; mt < 2; mt++) {
                uint32_t off = ((uint32_t)(wm * 32 + mt * 16) + a_row) * 128 + k0b + a_koff;
                uint32_t s = sw128(off);
                LDSM4(ah[mt], stA_h + s);
                LDSM4(al[mt], stA_l + s);
            }
            #pragma unroll
            for (int np = 0; np < 2; np++) {
                uint32_t off = ((uint32_t)(wn * 32 + np * 16) + b_row) * 128 + k0b + b_koff;
                uint32_t s = sw128(off);
                LDSM4(bh[np], stB_h + s);
                LDSM4(bl[np], stB_l + s);
            }
            #pragma unroll
            for (int mt = 0; mt < 2; mt++) {
                #pragma unroll
                for (int nt = 0; nt < 4; nt++) {
                    const int np = nt >> 1, pr = (nt & 1) << 1;
                    MMA_BF16(acc[mt][nt], ah[mt], bh[np][pr], bh[np][pr + 1]);
                    MMA_BF16(acc[mt][nt], ah[mt], bl[np][pr], bl[np][pr + 1]);
                    MMA_BF16(acc[mt][nt], al[mt], bh[np][pr], bh[np][pr + 1]);
                }
            }
        }
        if (++buf == 3) buf = 0;
    }

    // epilogue: each warp owns 32x32 at (wm*32, wn*32)
    const int erow = row0 + wm * 32 + (lane >> 2);
    const int ecol = col0 + wn * 32 + ((lane & 3) << 1);
    #pragma unroll
    for (int mt = 0; mt < 2; mt++) {
        #pragma unroll
        for (int nt = 0; nt < 4; nt++) {
            const int r0 = erow + mt * 16;
            const int c  = ecol + nt * 8;
            float v0 = acc[mt][nt][0], v1 = acc[mt][nt][1];
            float v2 = acc[mt][nt][2], v3 = acc[mt][nt][3];
            if (BIASRELU) {
                float b0 = bias[c], b1 = bias[c + 1];
                v0 = fmaxf(v0 + b0, 0.f); v1 = fmaxf(v1 + b1, 0.f);
                v2 = fmaxf(v2 + b0, 0.f); v3 = fmaxf(v3 + b1, 0.f);
            }
            *reinterpret_cast<float2*>(C + (size_t)r0 * N + c)       = make_float2(v0, v1);
            *reinterpret_cast<float2*>(C + (size_t)(r0 + 8) * N + c) = make_float2(v2, v3);
        }
    }
}

// ---------------- fused prep: weight/cb transposes+splits, x split, norms ----
__global__ void __launch_bounds__(256) prep_kernel(
    const float* __restrict__ x,
    const float* __restrict__ ew1, const float* __restrict__ ew2,
    const float* __restrict__ dw1, const float* __restrict__ dw2,
    const float* __restrict__ cb)
{
    __shared__ float t[32][33];
    const int blk = blockIdx.x, tid = threadIdx.x;

    if (blk < 1536) {
        const float* in; __nv_bfloat16 *oh, *ol; int R, C, bx, by;
        if (blk < 1024) {
            int w = blk >> 8, idx = blk & 255;
            const float* ws[4] = {ew1, ew2, dw1, dw2};
            in = ws[w];
            oh = g_wh + (size_t)w * DDIM * DDIM;
            ol = g_wl + (size_t)w * DDIM * DDIM;
            R = DDIM; C = DDIM; bx = idx & 15; by = idx >> 4;
        } else {
            int idx = blk - 1024;
            in = cb; oh = g_cbth; ol = g_cbtl;
            R = KCB; C = DDIM; bx = idx & 15; by = idx >> 4;
        }
        const int txx = tid & 31, tyy = tid >> 5;
        #pragma unroll
        for (int i = tyy; i < 32; i += 8)
            t[i][txx] = in[(size_t)(by * 32 + i) * C + bx * 32 + txx];
        __syncthreads();
        #pragma unroll
        for (int i = tyy; i < 32; i += 8) {
            float v = t[txx][i];
            size_t o = (size_t)(bx * 32 + i) * R + by * 32 + txx;
            __nv_bfloat16 h = __float2bfloat16(v);
            oh[o] = h;
            ol[o] = __float2bfloat16(v - __bfloat162float(h));
        }
    } else if (blk < 2048) {
        int lb = blk - 1536;
        const int n = KCB * DDIM;
        for (int i = lb * 256 + tid; i < n; i += 512 * 256) {
            float v = cb[i];
            __nv_bfloat16 h = __float2bfloat16(v);
            g_cbh[i] = h;
            g_cbl[i] = __float2bfloat16(v - __bfloat162float(h));
        }
    } else if (blk < 4096) {
        int lb = blk - 2048;
        const int n = NTOK * DDIM;
        for (int i = lb * 256 + tid; i < n; i += 2048 * 256) {
            float v = x[i];
            __nv_bfloat16 h = __float2bfloat16(v);
            g_ah[i] = h;
            g_al[i] = __float2bfloat16(v - __bfloat162float(h));
        }
    } else {
        int lb = blk - 4096;
        int lane = tid & 31, wrp = tid >> 5;
        int gw = lb * 8 + wrp;
        for (int r = gw; r < KCB; r += 256) {
            const float* p = cb + (size_t)r * DDIM;
            float s = 0.f;
            for (int i = lane; i < DDIM; i += 32) { float v = p[i]; s += v * v; }
            #pragma unroll
            for (int o = 16; o; o >>= 1) s += __shfl_xor_sync(0xffffffffu, s, o);
            if (!lane) g_cc[r] = s;
        }
        int g = lb * 256 + tid;
        if (g < KCB) g_avgp[g] = 0.f;
        if (g == 0) { g_kldd = 0.0; g_kldc = 0.0; }
    }
}

// ---------------- LayerNorm (row 512) + optional fp32 out + bf16 splits ------
__global__ void __launch_bounds__(256) ln_kernel(
    const float* __restrict__ in, const float* __restrict__ g,
    const float* __restrict__ be, float* __restrict__ out,
    __nv_bfloat16* __restrict__ oh, __nv_bfloat16* __restrict__ ol,
    float* __restrict__ zz)
{
    __shared__ float sm[8];
    const int row = blockIdx.x, tid = threadIdx.x;
    const int lane = tid & 31, wrp = tid >> 5;
    const float* p = in + (size_t)row * DDIM;
    float x0 = p[tid], x1 = p[tid + 256];

    float s = x0 + x1;
    #pragma unroll
    for (int o = 16; o; o >>= 1) s += __shfl_xor_sync(0xffffffffu, s, o);
    if (!lane) sm[wrp] = s;
    __syncthreads();
    float mean = (sm[0] + sm[1] + sm[2] + sm[3] + sm[4] + sm[5] + sm[6] + sm[7]) * (1.f / DDIM);
    __syncthreads();

    float d0 = x0 - mean, d1 = x1 - mean;
    float v = d0 * d0 + d1 * d1;
    #pragma unroll
    for (int o = 16; o; o >>= 1) v += __shfl_xor_sync(0xffffffffu, v, o);
    if (!lane) sm[wrp] = v;
    __syncthreads();
    float rstd = rsqrtf((sm[0] + sm[1] + sm[2] + sm[3] + sm[4] + sm[5] + sm[6] + sm[7]) * (1.f / DDIM) + 1e-5f);

    float y0 = d0 * rstd * g[tid]       + be[tid];
    float y1 = d1 * rstd * g[tid + 256] + be[tid + 256];
    if (out) {
        float* q = out + (size_t)row * DDIM;
        q[tid] = y0; q[tid + 256] = y1;
    }
    if (oh) {
        size_t b = (size_t)row * DDIM;
        __nv_bfloat16 h0 = __float2bfloat16(y0);
        __nv_bfloat16 h1 = __float2bfloat16(y1);
        oh[b + tid]       = h0; ol[b + tid]       = __float2bfloat16(y0 - __bfloat162float(h0));
        oh[b + tid + 256] = h1; ol[b + tid + 256] = __float2bfloat16(y1 - __bfloat162float(h1));
    }
    if (zz) {
        float q = y0 * y0 + y1 * y1;
        #pragma unroll
        for (int o = 16; o; o >>= 1) q += __shfl_xor_sync(0xffffffffu, q, o);
        __syncthreads();
        if (!lane) sm[wrp] = q;
        __syncthreads();
        if (!tid) zz[row] = sm[0] + sm[1] + sm[2] + sm[3] + sm[4] + sm[5] + sm[6] + sm[7];
    }
}

// ---------------- quantizer: writes encodings as bf16 splits -----------------
__global__ void __launch_bounds__(256) quant_kernel(
    const float* __restrict__ gum, const float* __restrict__ lpq)
{
    __shared__ float s_cc[KCB];
    __shared__ float s_avg[8][KCB];
    const int tid = threadIdx.x, lane = tid & 31, wid = tid >> 5;
    const float w = 0.5f / fmaxf(__expf(lpq[0]), 1e-10f);

    for (int j = tid; j < KCB; j += 256) s_cc[j] = g_cc[j];
    for (int j = tid; j < 8 * KCB; j += 256) (&s_avg[0][0])[j] = 0.f;
    __syncthreads();

    double kd = 0.0;
    const int row0 = blockIdx.x * 64;
    for (int r = wid; r < 64; r += 8) {
        const int row = row0 + r;
        const float* dp = g_dot + (size_t)row * KCB;
        const float* up = gum   + (size_t)row * KCB;
        const float zzr = g_zz[row];

        float lg[32];
        float mx = -1e30f;
        #pragma unroll
        for (int q = 0; q < 32; q++) {
            int j = lane + (q << 5);
            float l = w * (2.f * dp[j] - zzr - s_cc[j]);
            lg[q] = l;
            mx = fmaxf(mx, l);
        }
        #pragma unroll
        for (int o = 16; o; o >>= 1) mx = fmaxf(mx, __shfl_xor_sync(0xffffffffu, mx, o));

        float se = 0.f;
        #pragma unroll
        for (int q = 0; q < 32; q++) se += __expf(lg[q] - mx);
        #pragma unroll
        for (int o = 16; o; o >>= 1) se += __shfl_xor_sync(0xffffffffu, se, o);
        const float lse = __logf(se);

        float pd = 0.f;
        #pragma unroll
        for (int q = 0; q < 32; q++) {
            int j = lane + (q << 5);
            float lp = lg[q] - mx - lse;
            float p = __expf(lp);
            pd += p * lp;
            s_avg[wid][j] += p;
        }
        #pragma unroll
        for (int o = 16; o; o >>= 1) pd += __shfl_xor_sync(0xffffffffu, pd, o);
        if (!lane) kd += (double)pd;

        float mx2 = -1e30f;
        #pragma unroll
        for (int q = 0; q < 32; q++) {
            int j = lane + (q << 5);
            float u = up[j];
            float gn = -__logf(-__logf(u + 1e-10f) + 1e-10f);
            float a = lg[q] + gn;
            lg[q] = a;
            mx2 = fmaxf(mx2, a);
        }
        #pragma unroll
        for (int o = 16; o; o >>= 1) mx2 = fmaxf(mx2, __shfl_xor_sync(0xffffffffu, mx2, o));

        float s2 = 0.f;
        #pragma unroll
        for (int q = 0; q < 32; q++) { float e = __expf(lg[q] - mx2); lg[q] = e; s2 += e; }
        #pragma unroll
        for (int o = 16; o; o >>= 1) s2 += __shfl_xor_sync(0xffffffffu, s2, o);
        const float inv = 1.f / s2;

        __nv_bfloat16* eph = g_ah + (size_t)row * KCB;
        __nv_bfloat16* epl = g_al + (size_t)row * KCB;
        #pragma unroll
        for (int q = 0; q < 32; q++) {
            int j = lane + (q << 5);
            float e = lg[q] * inv;
            __nv_bfloat16 h = __float2bfloat16(e);
            eph[j] = h;
            epl[j] = __float2bfloat16(e - __bfloat162float(h));
        }
    }
    __syncthreads();

    for (int j = tid; j < KCB; j += 256) {
        float s = 0.f;
        #pragma unroll
        for (int ww = 0; ww < 8; ww++) s += s_avg[ww][j];
        atomicAdd(&g_avgp[j], s);
    }
    if (!lane) atomicAdd(&g_kldd, kd);
}

// ---------------- sum((z - z_q)^2) + split z_q for decoder -------------------
__global__ void __launch_bounds__(256) sq_kernel()
{
    size_t gid = (size_t)blockIdx.x * 256 + threadIdx.x;
    size_t stride = (size_t)gridDim.x * 256;
    float acc = 0.f;
    for (size_t i = gid; i < (size_t)NTOK * DDIM; i += stride) {
        float qv = g_zq[i];
        float d = g_z[i] - qv;
        acc += d * d;
        __nv_bfloat16 h = __float2bfloat16(qv);
        g_ah[i] = h;
        g_al[i] = __float2bfloat16(qv - __bfloat162float(h));
    }
    #pragma unroll
    for (int o = 16; o; o >>= 1) acc += __shfl_xor_sync(0xffffffffu, acc, o);
    __shared__ double sred[8];
    int lane = threadIdx.x & 31, wid = threadIdx.x >> 5;
    if (!lane) sred[wid] = (double)acc;
    __syncthreads();
    if (threadIdx.x == 0) {
        double s = 0.0;
        #pragma unroll
        for (int i = 0; i < 8; i++) s += sred[i];
        atomicAdd(&g_kldc, s);
    }
}

// ---------------- finalize ----------------------------------------------------
__global__ void __launch_bounds__(256) fin_kernel(
    const float* __restrict__ lpq, float* __restrict__ out)
{
    __shared__ double red[256];
    const int tid = threadIdx.x;
    double h = 0.0;
    for (int j = tid; j < KCB; j += 256) {
        float a = g_avgp[j] * (1.f / NTOK);
        h += (double)(a * __logf(a + 1e-7f));
    }
    red[tid] = h; __syncthreads();
    #pragma unroll
    for (int o = 128; o; o >>= 1) { if (tid < o) red[tid] += red[tid + o]; __syncthreads(); }
    if (!tid) {
        float w = 0.5f / fmaxf(__expf(lpq[0]), 1e-10f);
        double loss = g_kldd / (double)NB + g_kldc * (double)w / (double)NB;
        out[(size_t)NTOK * DDIM]     = (float)loss;
        out[(size_t)NTOK * DDIM + 1] = __expf((float)(-red[0]));
    }
}

// ---------------- launch ------------------------------------------------------
extern "C" void kernel_launch(void* const* d_in, const int* in_sizes, int n_in,
                              void* d_out, int out_size)
{
    (void)in_sizes; (void)n_in; (void)out_size;
    const float* x    = (const float*)d_in[0];
    const float* gum  = (const float*)d_in[1];
    const float* ew1  = (const float*)d_in[2];  const float* eb1  = (const float*)d_in[3];
    const float* eg1  = (const float*)d_in[4];  const float* ebe1 = (const float*)d_in[5];
    const float* ew2  = (const float*)d_in[6];  const float* eb2  = (const float*)d_in[7];
    const float* eg2  = (const float*)d_in[8];  const float* ebe2 = (const float*)d_in[9];
    const float* dw1  = (const float*)d_in[10]; const float* db1  = (const float*)d_in[11];
    const float* dg1  = (const float*)d_in[12]; const float* dbe1 = (const float*)d_in[13];
    const float* dw2  = (const float*)d_in[14]; const float* db2  = (const float*)d_in[15];
    const float* dg2  = (const float*)d_in[16]; const float* dbe2 = (const float*)d_in[17];
    const float* cb   = (const float*)d_in[18];
    const float* lpq  = (const float*)d_in[19];
    float* out = (float*)d_out;

    float *p_h, *p_z, *p_zq, *p_dot, *p_zz;
    __nv_bfloat16 *p_ah, *p_al, *p_wh, *p_wl, *p_cbh, *p_cbl, *p_cbth, *p_cbtl;
    cudaGetSymbolAddress((void**)&p_h,    g_h);
    cudaGetSymbolAddress((void**)&p_z,    g_z);
    cudaGetSymbolAddress((void**)&p_zq,   g_zq);
    cudaGetSymbolAddress((void**)&p_dot,  g_dot);
    cudaGetSymbolAddress((void**)&p_zz,   g_zz);
    cudaGetSymbolAddress((void**)&p_ah,   g_ah);
    cudaGetSymbolAddress((void**)&p_al,   g_al);
    cudaGetSymbolAddress((void**)&p_wh,   g_wh);
    cudaGetSymbolAddress((void**)&p_wl,   g_wl);
    cudaGetSymbolAddress((void**)&p_cbh,  g_cbh);
    cudaGetSymbolAddress((void**)&p_cbl,  g_cbl);
    cudaGetSymbolAddress((void**)&p_cbth, g_cbth);
    cudaGetSymbolAddress((void**)&p_cbtl, g_cbtl);

    cudaFuncSetAttribute(mma_gemm<true>,  cudaFuncAttributeMaxDynamicSharedMemorySize, SMEM_GEMM);
    cudaFuncSetAttribute(mma_gemm<false>, cudaFuncAttributeMaxDynamicSharedMemorySize, SMEM_GEMM);

    const int WSZ = DDIM * DDIM;
    dim3 gD(DDIM / 128, NTOK / 128);   // (4, 128)
    dim3 gK(KCB  / 128, NTOK / 128);   // (8, 128)

    // 1: fused prep
    prep_kernel<<<4128, 256>>>(x, ew1, ew2, dw1, dw2, cb);

    // 2-5: encoder
    mma_gemm<true ><<<gD, 512, SMEM_GEMM>>>(p_ah, p_al, p_wh + 0 * WSZ, p_wl + 0 * WSZ, eb1, p_h, NTOK, DDIM, DDIM);
    ln_kernel<<<NTOK, 256>>>(p_h, eg1, ebe1, nullptr, p_ah, p_al, nullptr);
    mma_gemm<true ><<<gD, 512, SMEM_GEMM>>>(p_ah, p_al, p_wh + 1 * WSZ, p_wl + 1 * WSZ, eb2, p_h, NTOK, DDIM, DDIM);
    ln_kernel<<<NTOK, 256>>>(p_h, eg2, ebe2, p_z, p_ah, p_al, p_zz);

    // 6: quantizer logits GEMM  (launch #6 -> ncu -s 5 profiles this)
    mma_gemm<false><<<gK, 512, SMEM_GEMM>>>(p_ah, p_al, p_cbh, p_cbl, nullptr, p_dot, NTOK, KCB, DDIM);
    quant_kernel<<<256, 256>>>(gum, lpq);
    mma_gemm<false><<<gD, 512, SMEM_GEMM>>>(p_ah, p_al, p_cbth, p_cbtl, nullptr, p_zq, NTOK, DDIM, KCB);
    sq_kernel<<<512, 256>>>();

    // decoder
    mma_gemm<true ><<<gD, 512, SMEM_GEMM>>>(p_ah, p_al, p_wh + 2 * WSZ, p_wl + 2 * WSZ, db1, p_h, NTOK, DDIM, DDIM);
    ln_kernel<<<NTOK, 256>>>(p_h, dg1, dbe1, nullptr, p_ah, p_al, nullptr);
    mma_gemm<true ><<<gD, 512, SMEM_GEMM>>>(p_ah, p_al, p_wh + 3 * WSZ, p_wl + 3 * WSZ, db2, p_h, NTOK, DDIM, DDIM);
    ln_kernel<<<NTOK, 256>>>(p_h, dg2, dbe2, out, nullptr, nullptr, nullptr);

    fin_kernel<<<1, 256>>>(lpq, out);
}

// round 9
// speedup vs baseline: 1.0021x; 1.0021x over previous
#include <cuda_runtime.h>
#include <cuda_bf16.h>
#include <cstdint>
#include <cstddef>

#define NTOK 16384
#define DDIM 512
#define KCB  1024
#define NB   8

// ---------------- scratch (static device globals; no allocations) ----------
__device__ float g_h  [NTOK * DDIM];    // pre-LN MLP temp
__device__ float g_z  [NTOK * DDIM];    // encoder output (post-LN)
__device__ float g_zq [NTOK * DDIM];    // quantized
__device__ float g_dot[NTOK * KCB];     // z @ codebook^T
__device__ __align__(128) __nv_bfloat16 g_ah[NTOK * KCB];   // A-side split hi
__device__ __align__(128) __nv_bfloat16 g_al[NTOK * KCB];   // A-side split lo
__device__ __align__(128) __nv_bfloat16 g_wh[4 * DDIM * DDIM]; // transposed weights hi
__device__ __align__(128) __nv_bfloat16 g_wl[4 * DDIM * DDIM];
__device__ __align__(128) __nv_bfloat16 g_cbh [KCB * DDIM];    // codebook split
__device__ __align__(128) __nv_bfloat16 g_cbl [KCB * DDIM];
__device__ __align__(128) __nv_bfloat16 g_cbth[DDIM * KCB];    // codebook^T split
__device__ __align__(128) __nv_bfloat16 g_cbtl[DDIM * KCB];
__device__ float  g_zz [NTOK];
__device__ float  g_cc [KCB];
__device__ float  g_avgp[KCB];
__device__ double g_kldd;
__device__ double g_kldc;

// ---------------- PTX helpers ----------------------------------------------
__device__ __forceinline__ uint32_t smem_u32(const void* p) {
    uint32_t a;
    asm("{ .reg .u64 t; cvta.to.shared.u64 t, %1; cvt.u32.u64 %0, t; }"
        : "=r"(a) : "l"(p));
    return a;
}

#define CP_ASYNC16(s, g) \
    asm volatile("cp.async.cg.shared.global [%0], [%1], 16;" :: "r"(s), "l"(g))
#define CP_COMMIT() asm volatile("cp.async.commit_group;" ::: "memory")
#define CP_WAIT(n)  asm volatile("cp.async.wait_group %0;" :: "n"(n) : "memory")

#define LDSM4(r, addr) \
    asm volatile("ldmatrix.sync.aligned.m8n8.x4.shared.b16 {%0,%1,%2,%3}, [%4];" \
        : "=r"((r)[0]), "=r"((r)[1]), "=r"((r)[2]), "=r"((r)[3]) : "r"(addr) : "memory")

#define MMA_BF16(D, A, B0, B1) \
    asm volatile("mma.sync.aligned.m16n8k16.row.col.f32.bf16.bf16.f32 " \
        "{%0,%1,%2,%3}, {%4,%5,%6,%7}, {%8,%9}, {%0,%1,%2,%3};" \
        : "+f"((D)[0]), "+f"((D)[1]), "+f"((D)[2]), "+f"((D)[3]) \
        : "r"((A)[0]), "r"((A)[1]), "r"((A)[2]), "r"((A)[3]), "r"(B0), "r"(B1))

__device__ __forceinline__ uint32_t sw128(uint32_t off) {
    return off ^ ((off >> 3) & 0x70);
}

// ---------------- tile loader: 128 rows x 64 bf16 cols, SW128 swizzled ------
// 512 threads: each thread loads 2 x 16B chunks per tile
__device__ __forceinline__ void load_tile(uint32_t tb, const __nv_bfloat16* __restrict__ src,
                                          int r0, int k0, int K, int tid)
{
    #pragma unroll
    for (int i = 0; i < 2; i++) {
        int u = tid + (i << 9);
        int row = u >> 3, col8 = (u & 7) << 3;
        const __nv_bfloat16* gp = src + (size_t)(r0 + row) * K + k0 + col8;
        uint32_t off = (uint32_t)((row << 7) + (col8 << 1));
        CP_ASYNC16(tb + sw128(off), gp);
    }
}

// ---------------- mma.sync bf16x3 GEMM: C = (Ah+Al)@(Bh+Bl)^T ---------------
// 512 threads, 16 warps in 4x4, each warp 32x32. 3-stage cp.async pipeline.
// MMA schedule is TERM-MAJOR: all (mt,nt) of term1, then term2, then term3,
// so same-accumulator MMAs are separated by 8 independent MMAs (no RAW stall).
#define SMEM_STAGE 65536
#define SMEM_GEMM  (3 * SMEM_STAGE)

template<bool BIASRELU>
__global__ void __launch_bounds__(512, 1) mma_gemm(
    const __nv_bfloat16* __restrict__ Ah, const __nv_bfloat16* __restrict__ Al,
    const __nv_bfloat16* __restrict__ Bh, const __nv_bfloat16* __restrict__ Bl,
    const float* __restrict__ bias, float* __restrict__ C,
    int M, int N, int K)
{
    extern __shared__ char smem[];
    const int tid  = threadIdx.x;
    const int wid  = tid >> 5, lane = tid & 31;
    const int wm   = wid & 3, wn = wid >> 2;      // 4x4 warp grid: 32x32 per warp
    const uint32_t sb = smem_u32(smem);

    const int row0 = blockIdx.y << 7, col0 = blockIdx.x << 7;
    const int nk = K >> 6;

    float acc[2][4][4];
    #pragma unroll
    for (int i = 0; i < 2; i++)
        #pragma unroll
        for (int j = 0; j < 4; j++)
            #pragma unroll
            for (int r = 0; r < 4; r++) acc[i][j][r] = 0.f;

    // per-lane ldmatrix bases within a 128x64 bf16 tile (128B rows)
    const uint32_t a_row  = (uint32_t)(lane & 15);
    const uint32_t a_koff = (uint32_t)((lane >> 4) << 4);
    const uint32_t b_row  = (uint32_t)(((lane >> 4) << 3) + (lane & 7));
    const uint32_t b_koff = (uint32_t)(((lane >> 3) & 1) << 4);

    // prologue: stages 0, 1
    load_tile(sb + 0,     Ah, row0, 0, K, tid);
    load_tile(sb + 16384, Al, row0, 0, K, tid);
    load_tile(sb + 32768, Bh, col0, 0, K, tid);
    load_tile(sb + 49152, Bl, col0, 0, K, tid);
    CP_COMMIT();
    if (nk > 1) {
        load_tile(sb + SMEM_STAGE + 0,     Ah, row0, 64, K, tid);
        load_tile(sb + SMEM_STAGE + 16384, Al, row0, 64, K, tid);
        load_tile(sb + SMEM_STAGE + 32768, Bh, col0, 64, K, tid);
        load_tile(sb + SMEM_STAGE + 49152, Bl, col0, 64, K, tid);
        CP_COMMIT();
    }

    int buf = 0;
    for (int kt = 0; kt < nk; kt++) {
        if (kt + 1 < nk) CP_WAIT(1); else CP_WAIT(0);
        __syncthreads();

        // issue loads for stage kt+2 (buffer freed by the sync above)
        if (kt + 2 < nk) {
            const int k0 = (kt + 2) << 6;
            int nbuf = buf + 2; if (nbuf >= 3) nbuf -= 3;
            const uint32_t st = sb + nbuf * SMEM_STAGE;
            load_tile(st + 0,     Ah, row0, k0, K, tid);
            load_tile(st + 16384, Al, row0, k0, K, tid);
            load_tile(st + 32768, Bh, col0, k0, K, tid);
            load_tile(st + 49152, Bl, col0, k0, K, tid);
            CP_COMMIT();
        }

        const uint32_t stA_h = sb + buf * SMEM_STAGE;
        const uint32_t stA_l = stA_h + 16384;
        const uint32_t stB_h = stA_h + 32768;
        const uint32_t stB_l = stA_h + 49152;

        #pragma unroll
        for (int ks = 0; ks < 4; ks++) {
            const uint32_t k0b = (uint32_t)(ks << 5);
            uint32_t ah[2][4], al[2][4], bh[2][4], bl[2][4];
            #pragma unroll
            for (int mt = 0; mt < 2; mt++) {
                uint32_t off = ((uint32_t)(wm * 32 + mt * 16) + a_row) * 128 + k0b + a_koff;
                uint32_t s = sw128(off);
                LDSM4(ah[mt], stA_h + s);
                LDSM4(al[mt], stA_l + s);
            }
            #pragma unroll
            for (int np = 0; np < 2; np++) {
                uint32_t off = ((uint32_t)(wn * 32 + np * 16) + b_row) * 128 + k0b + b_koff;
                uint32_t s = sw128(off);
                LDSM4(bh[np], stB_h + s);
                LDSM4(bl[np], stB_l + s);
            }
            // term-major: 8 independent MMAs per term; same-acc MMAs are
            // 8 instructions apart -> no accumulator RAW stalls.
            #pragma unroll
            for (int mt = 0; mt < 2; mt++)
                #pragma unroll
                for (int nt = 0; nt < 4; nt++) {
                    const int np = nt >> 1, pr = (nt & 1) << 1;
                    MMA_BF16(acc[mt][nt], ah[mt], bh[np][pr], bh[np][pr + 1]);
                }
            #pragma unroll
            for (int mt = 0; mt < 2; mt++)
                #pragma unroll
                for (int nt = 0; nt < 4; nt++) {
                    const int np = nt >> 1, pr = (nt & 1) << 1;
                    MMA_BF16(acc[mt][nt], ah[mt], bl[np][pr], bl[np][pr + 1]);
                }
            #pragma unroll
            for (int mt = 0; mt < 2; mt++)
                #pragma unroll
                for (int nt = 0; nt < 4; nt++) {
                    const int np = nt >> 1, pr = (nt & 1) << 1;
                    MMA_BF16(acc[mt][nt], al[mt], bh[np][pr], bh[np][pr + 1]);
                }
        }
        if (++buf == 3) buf = 0;
    }

    // epilogue: each warp owns 32x32 at (wm*32, wn*32)
    const int erow = row0 + wm * 32 + (lane >> 2);
    const int ecol = col0 + wn * 32 + ((lane & 3) << 1);
    #pragma unroll
    for (int mt = 0; mt < 2; mt++) {
        #pragma unroll
        for (int nt = 0; nt < 4; nt++) {
            const int r0 = erow + mt * 16;
            const int c  = ecol + nt * 8;
            float v0 = acc[mt][nt][0], v1 = acc[mt][nt][1];
            float v2 = acc[mt][nt][2], v3 = acc[mt][nt][3];
            if (BIASRELU) {
                float b0 = bias[c], b1 = bias[c + 1];
                v0 = fmaxf(v0 + b0, 0.f); v1 = fmaxf(v1 + b1, 0.f);
                v2 = fmaxf(v2 + b0, 0.f); v3 = fmaxf(v3 + b1, 0.f);
            }
            *reinterpret_cast<float2*>(C + (size_t)r0 * N + c)       = make_float2(v0, v1);
            *reinterpret_cast<float2*>(C + (size_t)(r0 + 8) * N + c) = make_float2(v2, v3);
        }
    }
}

// ---------------- fused prep: weight/cb transposes+splits, x split, norms ----
__global__ void __launch_bounds__(256) prep_kernel(
    const float* __restrict__ x,
    const float* __restrict__ ew1, const float* __restrict__ ew2,
    const float* __restrict__ dw1, const float* __restrict__ dw2,
    const float* __restrict__ cb)
{
    __shared__ float t[32][33];
    const int blk = blockIdx.x, tid = threadIdx.x;

    if (blk < 1536) {
        const float* in; __nv_bfloat16 *oh, *ol; int R, C, bx, by;
        if (blk < 1024) {
            int w = blk >> 8, idx = blk & 255;
            const float* ws[4] = {ew1, ew2, dw1, dw2};
            in = ws[w];
            oh = g_wh + (size_t)w * DDIM * DDIM;
            ol = g_wl + (size_t)w * DDIM * DDIM;
            R = DDIM; C = DDIM; bx = idx & 15; by = idx >> 4;
        } else {
            int idx = blk - 1024;
            in = cb; oh = g_cbth; ol = g_cbtl;
            R = KCB; C = DDIM; bx = idx & 15; by = idx >> 4;
        }
        const int txx = tid & 31, tyy = tid >> 5;
        #pragma unroll
        for (int i = tyy; i < 32; i += 8)
            t[i][txx] = in[(size_t)(by * 32 + i) * C + bx * 32 + txx];
        __syncthreads();
        #pragma unroll
        for (int i = tyy; i < 32; i += 8) {
            float v = t[txx][i];
            size_t o = (size_t)(bx * 32 + i) * R + by * 32 + txx;
            __nv_bfloat16 h = __float2bfloat16(v);
            oh[o] = h;
            ol[o] = __float2bfloat16(v - __bfloat162float(h));
        }
    } else if (blk < 2048) {
        int lb = blk - 1536;
        const int n = KCB * DDIM;
        for (int i = lb * 256 + tid; i < n; i += 512 * 256) {
            float v = cb[i];
            __nv_bfloat16 h = __float2bfloat16(v);
            g_cbh[i] = h;
            g_cbl[i] = __float2bfloat16(v - __bfloat162float(h));
        }
    } else if (blk < 4096) {
        int lb = blk - 2048;
        const int n = NTOK * DDIM;
        for (int i = lb * 256 + tid; i < n; i += 2048 * 256) {
            float v = x[i];
            __nv_bfloat16 h = __float2bfloat16(v);
            g_ah[i] = h;
            g_al[i] = __float2bfloat16(v - __bfloat162float(h));
        }
    } else {
        int lb = blk - 4096;
        int lane = tid & 31, wrp = tid >> 5;
        int gw = lb * 8 + wrp;
        for (int r = gw; r < KCB; r += 256) {
            const float* p = cb + (size_t)r * DDIM;
            float s = 0.f;
            for (int i = lane; i < DDIM; i += 32) { float v = p[i]; s += v * v; }
            #pragma unroll
            for (int o = 16; o; o >>= 1) s += __shfl_xor_sync(0xffffffffu, s, o);
            if (!lane) g_cc[r] = s;
        }
        int g = lb * 256 + tid;
        if (g < KCB) g_avgp[g] = 0.f;
        if (g == 0) { g_kldd = 0.0; g_kldc = 0.0; }
    }
}

// ---------------- LayerNorm (row 512) + optional fp32 out + bf16 splits ------
__global__ void __launch_bounds__(256) ln_kernel(
    const float* __restrict__ in, const float* __restrict__ g,
    const float* __restrict__ be, float* __restrict__ out,
    __nv_bfloat16* __restrict__ oh, __nv_bfloat16* __restrict__ ol,
    float* __restrict__ zz)
{
    __shared__ float sm[8];
    const int row = blockIdx.x, tid = threadIdx.x;
    const int lane = tid & 31, wrp = tid >> 5;
    const float* p = in + (size_t)row * DDIM;
    float x0 = p[tid], x1 = p[tid + 256];

    float s = x0 + x1;
    #pragma unroll
    for (int o = 16; o; o >>= 1) s += __shfl_xor_sync(0xffffffffu, s, o);
    if (!lane) sm[wrp] = s;
    __syncthreads();
    float mean = (sm[0] + sm[1] + sm[2] + sm[3] + sm[4] + sm[5] + sm[6] + sm[7]) * (1.f / DDIM);
    __syncthreads();

    float d0 = x0 - mean, d1 = x1 - mean;
    float v = d0 * d0 + d1 * d1;
    #pragma unroll
    for (int o = 16; o; o >>= 1) v += __shfl_xor_sync(0xffffffffu, v, o);
    if (!lane) sm[wrp] = v;
    __syncthreads();
    float rstd = rsqrtf((sm[0] + sm[1] + sm[2] + sm[3] + sm[4] + sm[5] + sm[6] + sm[7]) * (1.f / DDIM) + 1e-5f);

    float y0 = d0 * rstd * g[tid]       + be[tid];
    float y1 = d1 * rstd * g[tid + 256] + be[tid + 256];
    if (out) {
        float* q = out + (size_t)row * DDIM;
        q[tid] = y0; q[tid + 256] = y1;
    }
    if (oh) {
        size_t b = (size_t)row * DDIM;
        __nv_bfloat16 h0 = __float2bfloat16(y0);
        __nv_bfloat16 h1 = __float2bfloat16(y1);
        oh[b + tid]       = h0; ol[b + tid]       = __float2bfloat16(y0 - __bfloat162float(h0));
        oh[b + tid + 256] = h1; ol[b + tid + 256] = __float2bfloat16(y1 - __bfloat162float(h1));
    }
    if (zz) {
        float q = y0 * y0 + y1 * y1;
        #pragma unroll
        for (int o = 16; o; o >>= 1) q += __shfl_xor_sync(0xffffffffu, q, o);
        __syncthreads();
        if (!lane) sm[wrp] = q;
        __syncthreads();
        if (!tid) zz[row] = sm[0] + sm[1] + sm[2] + sm[3] + sm[4] + sm[5] + sm[6] + sm[7];
    }
}

// ---------------- quantizer: writes encodings as bf16 splits -----------------
__global__ void __launch_bounds__(256) quant_kernel(
    const float* __restrict__ gum, const float* __restrict__ lpq)
{
    __shared__ float s_cc[KCB];
    __shared__ float s_avg[8][KCB];
    const int tid = threadIdx.x, lane = tid & 31, wid = tid >> 5;
    const float w = 0.5f / fmaxf(__expf(lpq[0]), 1e-10f);

    for (int j = tid; j < KCB; j += 256) s_cc[j] = g_cc[j];
    for (int j = tid; j < 8 * KCB; j += 256) (&s_avg[0][0])[j] = 0.f;
    __syncthreads();

    double kd = 0.0;
    const int row0 = blockIdx.x * 64;
    for (int r = wid; r < 64; r += 8) {
        const int row = row0 + r;
        const float* dp = g_dot + (size_t)row * KCB;
        const float* up = gum   + (size_t)row * KCB;
        const float zzr = g_zz[row];

        float lg[32];
        float mx = -1e30f;
        #pragma unroll
        for (int q = 0; q < 32; q++) {
            int j = lane + (q << 5);
            float l = w * (2.f * dp[j] - zzr - s_cc[j]);
            lg[q] = l;
            mx = fmaxf(mx, l);
        }
        #pragma unroll
        for (int o = 16; o; o >>= 1) mx = fmaxf(mx, __shfl_xor_sync(0xffffffffu, mx, o));

        float se = 0.f;
        #pragma unroll
        for (int q = 0; q < 32; q++) se += __expf(lg[q] - mx);
        #pragma unroll
        for (int o = 16; o; o >>= 1) se += __shfl_xor_sync(0xffffffffu, se, o);
        const float lse = __logf(se);

        float pd = 0.f;
        #pragma unroll
        for (int q = 0; q < 32; q++) {
            int j = lane + (q << 5);
            float lp = lg[q] - mx - lse;
            float p = __expf(lp);
            pd += p * lp;
            s_avg[wid][j] += p;
        }
        #pragma unroll
        for (int o = 16; o; o >>= 1) pd += __shfl_xor_sync(0xffffffffu, pd, o);
        if (!lane) kd += (double)pd;

        float mx2 = -1e30f;
        #pragma unroll
        for (int q = 0; q < 32; q++) {
            int j = lane + (q << 5);
            float u = up[j];
            float gn = -__logf(-__logf(u + 1e-10f) + 1e-10f);
            float a = lg[q] + gn;
            lg[q] = a;
            mx2 = fmaxf(mx2, a);
        }
        #pragma unroll
        for (int o = 16; o; o >>= 1) mx2 = fmaxf(mx2, __shfl_xor_sync(0xffffffffu, mx2, o));

        float s2 = 0.f;
        #pragma unroll
        for (int q = 0; q < 32; q++) { float e = __expf(lg[q] - mx2); lg[q] = e; s2 += e; }
        #pragma unroll
        for (int o = 16; o; o >>= 1) s2 += __shfl_xor_sync(0xffffffffu, s2, o);
        const float inv = 1.f / s2;

        __nv_bfloat16* eph = g_ah + (size_t)row * KCB;
        __nv_bfloat16* epl = g_al + (size_t)row * KCB;
        #pragma unroll
        for (int q = 0; q < 32; q++) {
            int j = lane + (q << 5);
            float e = lg[q] * inv;
            __nv_bfloat16 h = __float2bfloat16(e);
            eph[j] = h;
            epl[j] = __float2bfloat16(e - __bfloat162float(h));
        }
    }
    __syncthreads();

    for (int j = tid; j < KCB; j += 256) {
        float s = 0.f;
        #pragma unroll
        for (int ww = 0; ww < 8; ww++) s += s_avg[ww][j];
        atomicAdd(&g_avgp[j], s);
    }
    if (!lane) atomicAdd(&g_kldd, kd);
}

// ---------------- sum((z - z_q)^2) + split z_q for decoder -------------------
__global__ void __launch_bounds__(256) sq_kernel()
{
    size_t gid = (size_t)blockIdx.x * 256 + threadIdx.x;
    size_t stride = (size_t)gridDim.x * 256;
    float acc = 0.f;
    for (size_t i = gid; i < (size_t)NTOK * DDIM; i += stride) {
        float qv = g_zq[i];
        float d = g_z[i] - qv;
        acc += d * d;
        __nv_bfloat16 h = __float2bfloat16(qv);
        g_ah[i] = h;
        g_al[i] = __float2bfloat16(qv - __bfloat162float(h));
    }
    #pragma unroll
    for (int o = 16; o; o >>= 1) acc += __shfl_xor_sync(0xffffffffu, acc, o);
    __shared__ double sred[8];
    int lane = threadIdx.x & 31, wid = threadIdx.x >> 5;
    if (!lane) sred[wid] = (double)acc;
    __syncthreads();
    if (threadIdx.x == 0) {
        double s = 0.0;
        #pragma unroll
        for (int i = 0; i < 8; i++) s += sred[i];
        atomicAdd(&g_kldc, s);
    }
}

// ---------------- finalize ----------------------------------------------------
__global__ void __launch_bounds__(256) fin_kernel(
    const float* __restrict__ lpq, float* __restrict__ out)
{
    __shared__ double red[256];
    const int tid = threadIdx.x;
    double h = 0.0;
    for (int j = tid; j < KCB; j += 256) {
        float a = g_avgp[j] * (1.f / NTOK);
        h += (double)(a * __logf(a + 1e-7f));
    }
    red[tid] = h; __syncthreads();
    #pragma unroll
    for (int o = 128; o; o >>= 1) { if (tid < o) red[tid] += red[tid + o]; __syncthreads(); }
    if (!tid) {
        float w = 0.5f / fmaxf(__expf(lpq[0]), 1e-10f);
        double loss = g_kldd / (double)NB + g_kldc * (double)w / (double)NB;
        out[(size_t)NTOK * DDIM]     = (float)loss;
        out[(size_t)NTOK * DDIM + 1] = __expf((float)(-red[0]));
    }
}

// ---------------- launch ------------------------------------------------------
extern "C" void kernel_launch(void* const* d_in, const int* in_sizes, int n_in,
                              void* d_out, int out_size)
{
    (void)in_sizes; (void)n_in; (void)out_size;
    const float* x    = (const float*)d_in[0];
    const float* gum  = (const float*)d_in[1];
    const float* ew1  = (const float*)d_in[2];  const float* eb1  = (const float*)d_in[3];
    const float* eg1  = (const float*)d_in[4];  const float* ebe1 = (const float*)d_in[5];
    const float* ew2  = (const float*)d_in[6];  const float* eb2  = (const float*)d_in[7];
    const float* eg2  = (const float*)d_in[8];  const float* ebe2 = (const float*)d_in[9];
    const float* dw1  = (const float*)d_in[10]; const float* db1  = (const float*)d_in[11];
    const float* dg1  = (const float*)d_in[12]; const float* dbe1 = (const float*)d_in[13];
    const float* dw2  = (const float*)d_in[14]; const float* db2  = (const float*)d_in[15];
    const float* dg2  = (const float*)d_in[16]; const float* dbe2 = (const float*)d_in[17];
    const float* cb   = (const float*)d_in[18];
    const float* lpq  = (const float*)d_in[19];
    float* out = (float*)d_out;

    float *p_h, *p_z, *p_zq, *p_dot, *p_zz;
    __nv_bfloat16 *p_ah, *p_al, *p_wh, *p_wl, *p_cbh, *p_cbl, *p_cbth, *p_cbtl;
    cudaGetSymbolAddress((void**)&p_h,    g_h);
    cudaGetSymbolAddress((void**)&p_z,    g_z);
    cudaGetSymbolAddress((void**)&p_zq,   g_zq);
    cudaGetSymbolAddress((void**)&p_dot,  g_dot);
    cudaGetSymbolAddress((void**)&p_zz,   g_zz);
    cudaGetSymbolAddress((void**)&p_ah,   g_ah);
    cudaGetSymbolAddress((void**)&p_al,   g_al);
    cudaGetSymbolAddress((void**)&p_wh,   g_wh);
    cudaGetSymbolAddress((void**)&p_wl,   g_wl);
    cudaGetSymbolAddress((void**)&p_cbh,  g_cbh);
    cudaGetSymbolAddress((void**)&p_cbl,  g_cbl);
    cudaGetSymbolAddress((void**)&p_cbth, g_cbth);
    cudaGetSymbolAddress((void**)&p_cbtl, g_cbtl);

    cudaFuncSetAttribute(mma_gemm<true>,  cudaFuncAttributeMaxDynamicSharedMemorySize, SMEM_GEMM);
    cudaFuncSetAttribute(mma_gemm<false>, cudaFuncAttributeMaxDynamicSharedMemorySize, SMEM_GEMM);

    const int WSZ = DDIM * DDIM;
    dim3 gD(DDIM / 128, NTOK / 128);   // (4, 128)
    dim3 gK(KCB  / 128, NTOK / 128);   // (8, 128)

    // 1: fused prep
    prep_kernel<<<4128, 256>>>(x, ew1, ew2, dw1, dw2, cb);

    // 2-5: encoder
    mma_gemm<true ><<<gD, 512, SMEM_GEMM>>>(p_ah, p_al, p_wh + 0 * WSZ, p_wl + 0 * WSZ, eb1, p_h, NTOK, DDIM, DDIM);
    ln_kernel<<<NTOK, 256>>>(p_h, eg1, ebe1, nullptr, p_ah, p_al, nullptr);
    mma_gemm<true ><<<gD, 512, SMEM_GEMM>>>(p_ah, p_al, p_wh + 1 * WSZ, p_wl + 1 * WSZ, eb2, p_h, NTOK, DDIM, DDIM);
    ln_kernel<<<NTOK, 256>>>(p_h, eg2, ebe2, p_z, p_ah, p_al, p_zz);

    // 6: quantizer logits GEMM  (launch #6 -> ncu -s 5 profiles this)
    mma_gemm<false><<<gK, 512, SMEM_GEMM>>>(p_ah, p_al, p_cbh, p_cbl, nullptr, p_dot, NTOK, KCB, DDIM);
    quant_kernel<<<256, 256>>>(gum, lpq);
    mma_gemm<false><<<gD, 512, SMEM_GEMM>>>(p_ah, p_al, p_cbth, p_cbtl, nullptr, p_zq, NTOK, DDIM, KCB);
    sq_kernel<<<512, 256>>>();

    // decoder
    mma_gemm<true ><<<gD, 512, SMEM_GEMM>>>(p_ah, p_al, p_wh + 2 * WSZ, p_wl + 2 * WSZ, db1, p_h, NTOK, DDIM, DDIM);
    ln_kernel<<<NTOK, 256>>>(p_h, dg1, dbe1, nullptr, p_ah, p_al, nullptr);
    mma_gemm<true ><<<gD, 512, SMEM_GEMM>>>(p_ah, p_al, p_wh + 3 * WSZ, p_wl + 3 * WSZ, db2, p_h, NTOK, DDIM, DDIM);
    ln_kernel<<<NTOK, 256>>>(p_h, dg2, dbe2, out, nullptr, nullptr, nullptr);

    fin_kernel<<<1, 256>>>(lpq, out);
}

// round 10
// speedup vs baseline: 1.1407x; 1.1382x over previous
#include <cuda_runtime.h>
#include <cuda_fp16.h>
#include <cstdint>
#include <cstddef>

#define NTOK 16384
#define DDIM 512
#define KCB  1024
#define NB   8

// ---------------- scratch (static device globals; no allocations) ----------
__device__ float g_h  [NTOK * DDIM];    // pre-LN MLP temp
__device__ float g_z  [NTOK * DDIM];    // encoder output (post-LN)
__device__ float g_zq [NTOK * DDIM];    // quantized
__device__ float g_dot[NTOK * KCB];     // z @ codebook^T
__device__ __align__(128) __half g_ah[NTOK * KCB];      // A-side split hi
__device__ __align__(128) __half g_al[NTOK * KCB];      // A-side split lo
__device__ __align__(128) __half g_wh[4 * DDIM * DDIM]; // transposed weights hi
__device__ __align__(128) __half g_wl[4 * DDIM * DDIM];
__device__ __align__(128) __half g_cbh [KCB * DDIM];    // codebook split (K-major rows)
__device__ __align__(128) __half g_cbl [KCB * DDIM];
__device__ __align__(128) __half g_cbth[DDIM * KCB];    // codebook^T split hi
__device__ __align__(128) __half g_cbtl[DDIM * KCB];
__device__ float  g_zz [NTOK];
__device__ float  g_cc [KCB];
__device__ float  g_avgp[KCB];
__device__ double g_kldd;
__device__ double g_kldc;

// ---------------- PTX helpers ----------------------------------------------
__device__ __forceinline__ uint32_t smem_u32(const void* p) {
    uint32_t a;
    asm("{ .reg .u64 t; cvta.to.shared.u64 t, %1; cvt.u32.u64 %0, t; }"
        : "=r"(a) : "l"(p));
    return a;
}

#define CP_ASYNC16(s, g) \
    asm volatile("cp.async.cg.shared.global [%0], [%1], 16;" :: "r"(s), "l"(g))
#define CP_COMMIT() asm volatile("cp.async.commit_group;" ::: "memory")
#define CP_WAIT(n)  asm volatile("cp.async.wait_group %0;" :: "n"(n) : "memory")

#define LDSM4(r, addr) \
    asm volatile("ldmatrix.sync.aligned.m8n8.x4.shared.b16 {%0,%1,%2,%3}, [%4];" \
        : "=r"((r)[0]), "=r"((r)[1]), "=r"((r)[2]), "=r"((r)[3]) : "r"(addr) : "memory")

#define MMA_F16(D, A, B0, B1) \
    asm volatile("mma.sync.aligned.m16n8k16.row.col.f32.f16.f16.f32 " \
        "{%0,%1,%2,%3}, {%4,%5,%6,%7}, {%8,%9}, {%0,%1,%2,%3};" \
        : "+f"((D)[0]), "+f"((D)[1]), "+f"((D)[2]), "+f"((D)[3]) \
        : "r"((A)[0]), "r"((A)[1]), "r"((A)[2]), "r"((A)[3]), "r"(B0), "r"(B1))

__device__ __forceinline__ uint32_t sw128(uint32_t off) {
    return off ^ ((off >> 3) & 0x70);
}

__device__ __forceinline__ void split2(float v, __half* oh, __half* ol) {
    __half h = __float2half(v);
    *oh = h;
    *ol = __float2half(v - __half2float(h));
}

// ---------------- tile loader: 128 rows x 64 fp16 cols, SW128 swizzled ------
// 256 threads: each thread loads 4 x 16B chunks per tile
__device__ __forceinline__ void load_tile(uint32_t tb, const __half* __restrict__ src,
                                          int r0, int k0, int K, int tid)
{
    #pragma unroll
    for (int i = 0; i < 4; i++) {
        int u = tid + (i << 8);
        int row = u >> 3, col8 = (u & 7) << 3;
        const __half* gp = src + (size_t)(r0 + row) * K + k0 + col8;
        uint32_t off = (uint32_t)((row << 7) + (col8 << 1));
        CP_ASYNC16(tb + sw128(off), gp);
    }
}

// ---------------- mma.sync fp16 GEMM: C = (Ah+Al)@(B...)^T ------------------
// TERMS==3: C = Ah*Bh + Ah*Bl + Al*Bh  (22-bit effective both sides)
// TERMS==2: C = Ah*Bh + Al*Bh          (B truncated to fp16, A 22-bit)
// 256 threads, 8 warps 2x4, warp tile 64x32. 3-stage cp.async pipeline,
// register double-buffered fragments.
template<bool BIASRELU, int TERMS>
__global__ void __launch_bounds__(256, 1) mma_gemm(
    const __half* __restrict__ Ah, const __half* __restrict__ Al,
    const __half* __restrict__ Bh, const __half* __restrict__ Bl,
    const float* __restrict__ bias, float* __restrict__ C,
    int M, int N, int K)
{
    constexpr int STAGE = (TERMS == 3) ? 65536 : 49152;
    extern __shared__ char smem[];
    const int tid  = threadIdx.x;
    const int wid  = tid >> 5, lane = tid & 31;
    const int wm   = wid & 1, wn = wid >> 1;      // 2x4 warp grid: 64x32 per warp
    const uint32_t sb = smem_u32(smem);

    const int row0 = blockIdx.y << 7, col0 = blockIdx.x << 7;
    const int nk = K >> 6;

    float acc[4][4][4];
    #pragma unroll
    for (int i = 0; i < 4; i++)
        #pragma unroll
        for (int j = 0; j < 4; j++)
            #pragma unroll
            for (int r = 0; r < 4; r++) acc[i][j][r] = 0.f;

    // per-lane ldmatrix bases within a 128x64 fp16 tile (128B rows)
    const uint32_t a_row  = (uint32_t)(lane & 15);
    const uint32_t a_koff = (uint32_t)((lane >> 4) << 4);
    const uint32_t b_row  = (uint32_t)(((lane >> 4) << 3) + (lane & 7));
    const uint32_t b_koff = (uint32_t)(((lane >> 3) & 1) << 4);

    // prologue: stages 0, 1
    load_tile(sb + 0,     Ah, row0, 0, K, tid);
    load_tile(sb + 16384, Al, row0, 0, K, tid);
    load_tile(sb + 32768, Bh, col0, 0, K, tid);
    if (TERMS == 3) load_tile(sb + 49152, Bl, col0, 0, K, tid);
    CP_COMMIT();
    if (nk > 1) {
        load_tile(sb + STAGE + 0,     Ah, row0, 64, K, tid);
        load_tile(sb + STAGE + 16384, Al, row0, 64, K, tid);
        load_tile(sb + STAGE + 32768, Bh, col0, 64, K, tid);
        if (TERMS == 3) load_tile(sb + STAGE + 49152, Bl, col0, 64, K, tid);
        CP_COMMIT();
    }

    uint32_t ah[2][4][4], al[2][4][4], bh[2][2][4], bl[2][2][4];

    int buf = 0;
    for (int kt = 0; kt < nk; kt++) {
        if (kt + 1 < nk) CP_WAIT(1); else CP_WAIT(0);
        __syncthreads();

        // issue loads for stage kt+2 (buffer freed by the sync above)
        if (kt + 2 < nk) {
            const int k0 = (kt + 2) << 6;
            int nbuf = buf + 2; if (nbuf >= 3) nbuf -= 3;
            const uint32_t st = sb + nbuf * STAGE;
            load_tile(st + 0,     Ah, row0, k0, K, tid);
            load_tile(st + 16384, Al, row0, k0, K, tid);
            load_tile(st + 32768, Bh, col0, k0, K, tid);
            if (TERMS == 3) load_tile(st + 49152, Bl, col0, k0, K, tid);
            CP_COMMIT();
        }

        const uint32_t stA_h = sb + buf * STAGE;
        const uint32_t stA_l = stA_h + 16384;
        const uint32_t stB_h = stA_h + 32768;
        const uint32_t stB_l = stA_h + 49152;

        // prefetch fragments for ks = 0
        {
            #pragma unroll
            for (int mt = 0; mt < 4; mt++) {
                uint32_t off = ((uint32_t)(wm * 64 + mt * 16) + a_row) * 128 + a_koff;
                uint32_t s = sw128(off);
                LDSM4(ah[0][mt], stA_h + s);
                LDSM4(al[0][mt], stA_l + s);
            }
            #pragma unroll
            for (int np = 0; np < 2; np++) {
                uint32_t off = ((uint32_t)(wn * 32 + np * 16) + b_row) * 128 + b_koff;
                uint32_t s = sw128(off);
                LDSM4(bh[0][np], stB_h + s);
                if (TERMS == 3) LDSM4(bl[0][np], stB_l + s);
            }
        }

        #pragma unroll
        for (int ks = 0; ks < 4; ks++) {
            const int cur = ks & 1, nxt = cur ^ 1;
            if (ks < 3) {
                const uint32_t k0b = (uint32_t)((ks + 1) << 5);
                #pragma unroll
                for (int mt = 0; mt < 4; mt++) {
                    uint32_t off = ((uint32_t)(wm * 64 + mt * 16) + a_row) * 128 + k0b + a_koff;
                    uint32_t s = sw128(off);
                    LDSM4(ah[nxt][mt], stA_h + s);
                    LDSM4(al[nxt][mt], stA_l + s);
                }
                #pragma unroll
                for (int np = 0; np < 2; np++) {
                    uint32_t off = ((uint32_t)(wn * 32 + np * 16) + b_row) * 128 + k0b + b_koff;
                    uint32_t s = sw128(off);
                    LDSM4(bh[nxt][np], stB_h + s);
                    if (TERMS == 3) LDSM4(bl[nxt][np], stB_l + s);
                }
            }
            #pragma unroll
            for (int mt = 0; mt < 4; mt++) {
                #pragma unroll
                for (int nt = 0; nt < 4; nt++) {
                    const int np = nt >> 1, pr = (nt & 1) << 1;
                    MMA_F16(acc[mt][nt], ah[cur][mt], bh[cur][np][pr], bh[cur][np][pr + 1]);
                    if (TERMS == 3)
                        MMA_F16(acc[mt][nt], ah[cur][mt], bl[cur][np][pr], bl[cur][np][pr + 1]);
                    MMA_F16(acc[mt][nt], al[cur][mt], bh[cur][np][pr], bh[cur][np][pr + 1]);
                }
            }
        }
        if (++buf == 3) buf = 0;
    }

    // epilogue
    const int erow = row0 + wm * 64 + (lane >> 2);
    const int ecol = col0 + wn * 32 + ((lane & 3) << 1);
    #pragma unroll
    for (int mt = 0; mt < 4; mt++) {
        #pragma unroll
        for (int nt = 0; nt < 4; nt++) {
            const int r0 = erow + mt * 16;
            const int c  = ecol + nt * 8;
            float v0 = acc[mt][nt][0], v1 = acc[mt][nt][1];
            float v2 = acc[mt][nt][2], v3 = acc[mt][nt][3];
            if (BIASRELU) {
                float b0 = bias[c], b1 = bias[c + 1];
                v0 = fmaxf(v0 + b0, 0.f); v1 = fmaxf(v1 + b1, 0.f);
                v2 = fmaxf(v2 + b0, 0.f); v3 = fmaxf(v3 + b1, 0.f);
            }
            *reinterpret_cast<float2*>(C + (size_t)r0 * N + c)       = make_float2(v0, v1);
            *reinterpret_cast<float2*>(C + (size_t)(r0 + 8) * N + c) = make_float2(v2, v3);
        }
    }
}

// ---------------- fused prep: weight/cb transposes+splits, x split, norms ----
__global__ void __launch_bounds__(256) prep_kernel(
    const float* __restrict__ x,
    const float* __restrict__ ew1, const float* __restrict__ ew2,
    const float* __restrict__ dw1, const float* __restrict__ dw2,
    const float* __restrict__ cb)
{
    __shared__ float t[32][33];
    const int blk = blockIdx.x, tid = threadIdx.x;

    if (blk < 1536) {
        const float* in; __half *oh, *ol; int R, C, bx, by;
        if (blk < 1024) {
            int w = blk >> 8, idx = blk & 255;
            const float* ws[4] = {ew1, ew2, dw1, dw2};
            in = ws[w];
            oh = g_wh + (size_t)w * DDIM * DDIM;
            ol = g_wl + (size_t)w * DDIM * DDIM;
            R = DDIM; C = DDIM; bx = idx & 15; by = idx >> 4;
        } else {
            int idx = blk - 1024;
            in = cb; oh = g_cbth; ol = g_cbtl;
            R = KCB; C = DDIM; bx = idx & 15; by = idx >> 4;
        }
        const int txx = tid & 31, tyy = tid >> 5;
        #pragma unroll
        for (int i = tyy; i < 32; i += 8)
            t[i][txx] = in[(size_t)(by * 32 + i) * C + bx * 32 + txx];
        __syncthreads();
        #pragma unroll
        for (int i = tyy; i < 32; i += 8) {
            float v = t[txx][i];
            size_t o = (size_t)(bx * 32 + i) * R + by * 32 + txx;
            split2(v, oh + o, ol + o);
        }
    } else if (blk < 2048) {
        int lb = blk - 1536;
        const int n = KCB * DDIM;
        for (int i = lb * 256 + tid; i < n; i += 512 * 256)
            split2(cb[i], g_cbh + i, g_cbl + i);
    } else if (blk < 4096) {
        int lb = blk - 2048;
        const int n = NTOK * DDIM;
        for (int i = lb * 256 + tid; i < n; i += 2048 * 256)
            split2(x[i], g_ah + i, g_al + i);
    } else {
        int lb = blk - 4096;
        int lane = tid & 31, wrp = tid >> 5;
        int gw = lb * 8 + wrp;
        for (int r = gw; r < KCB; r += 256) {
            const float* p = cb + (size_t)r * DDIM;
            float s = 0.f;
            for (int i = lane; i < DDIM; i += 32) { float v = p[i]; s += v * v; }
            #pragma unroll
            for (int o = 16; o; o >>= 1) s += __shfl_xor_sync(0xffffffffu, s, o);
            if (!lane) g_cc[r] = s;
        }
        int g = lb * 256 + tid;
        if (g < KCB) g_avgp[g] = 0.f;
        if (g == 0) { g_kldd = 0.0; g_kldc = 0.0; }
    }
}

// ---------------- LayerNorm (row 512) + optional fp32 out + fp16 splits ------
__global__ void __launch_bounds__(256) ln_kernel(
    const float* __restrict__ in, const float* __restrict__ g,
    const float* __restrict__ be, float* __restrict__ out,
    __half* __restrict__ oh, __half* __restrict__ ol,
    float* __restrict__ zz)
{
    __shared__ float sm[8];
    const int row = blockIdx.x, tid = threadIdx.x;
    const int lane = tid & 31, wrp = tid >> 5;
    const float* p = in + (size_t)row * DDIM;
    float x0 = p[tid], x1 = p[tid + 256];

    float s = x0 + x1;
    #pragma unroll
    for (int o = 16; o; o >>= 1) s += __shfl_xor_sync(0xffffffffu, s, o);
    if (!lane) sm[wrp] = s;
    __syncthreads();
    float mean = (sm[0] + sm[1] + sm[2] + sm[3] + sm[4] + sm[5] + sm[6] + sm[7]) * (1.f / DDIM);
    __syncthreads();

    float d0 = x0 - mean, d1 = x1 - mean;
    float v = d0 * d0 + d1 * d1;
    #pragma unroll
    for (int o = 16; o; o >>= 1) v += __shfl_xor_sync(0xffffffffu, v, o);
    if (!lane) sm[wrp] = v;
    __syncthreads();
    float rstd = rsqrtf((sm[0] + sm[1] + sm[2] + sm[3] + sm[4] + sm[5] + sm[6] + sm[7]) * (1.f / DDIM) + 1e-5f);

    float y0 = d0 * rstd * g[tid]       + be[tid];
    float y1 = d1 * rstd * g[tid + 256] + be[tid + 256];
    if (out) {
        float* q = out + (size_t)row * DDIM;
        q[tid] = y0; q[tid + 256] = y1;
    }
    if (oh) {
        size_t b = (size_t)row * DDIM;
        split2(y0, oh + b + tid,       ol + b + tid);
        split2(y1, oh + b + tid + 256, ol + b + tid + 256);
    }
    if (zz) {
        float q = y0 * y0 + y1 * y1;
        #pragma unroll
        for (int o = 16; o; o >>= 1) q += __shfl_xor_sync(0xffffffffu, q, o);
        __syncthreads();
        if (!lane) sm[wrp] = q;
        __syncthreads();
        if (!tid) zz[row] = sm[0] + sm[1] + sm[2] + sm[3] + sm[4] + sm[5] + sm[6] + sm[7];
    }
}

// ---------------- quantizer: writes encodings as fp16 splits -----------------
__global__ void __launch_bounds__(256) quant_kernel(
    const float* __restrict__ gum, const float* __restrict__ lpq)
{
    __shared__ float s_cc[KCB];
    __shared__ float s_avg[8][KCB];
    const int tid = threadIdx.x, lane = tid & 31, wid = tid >> 5;
    const float w = 0.5f / fmaxf(__expf(lpq[0]), 1e-10f);

    for (int j = tid; j < KCB; j += 256) s_cc[j] = g_cc[j];
    for (int j = tid; j < 8 * KCB; j += 256) (&s_avg[0][0])[j] = 0.f;
    __syncthreads();

    double kd = 0.0;
    const int row0 = blockIdx.x * 64;
    for (int r = wid; r < 64; r += 8) {
        const int row = row0 + r;
        const float* dp = g_dot + (size_t)row * KCB;
        const float* up = gum   + (size_t)row * KCB;
        const float zzr = g_zz[row];

        float lg[32];
        float mx = -1e30f;
        #pragma unroll
        for (int q = 0; q < 32; q++) {
            int j = lane + (q << 5);
            float l = w * (2.f * dp[j] - zzr - s_cc[j]);
            lg[q] = l;
            mx = fmaxf(mx, l);
        }
        #pragma unroll
        for (int o = 16; o; o >>= 1) mx = fmaxf(mx, __shfl_xor_sync(0xffffffffu, mx, o));

        float se = 0.f;
        #pragma unroll
        for (int q = 0; q < 32; q++) se += __expf(lg[q] - mx);
        #pragma unroll
        for (int o = 16; o; o >>= 1) se += __shfl_xor_sync(0xffffffffu, se, o);
        const float lse = __logf(se);

        float pd = 0.f;
        #pragma unroll
        for (int q = 0; q < 32; q++) {
            int j = lane + (q << 5);
            float lp = lg[q] - mx - lse;
            float p = __expf(lp);
            pd += p * lp;
            s_avg[wid][j] += p;
        }
        #pragma unroll
        for (int o = 16; o; o >>= 1) pd += __shfl_xor_sync(0xffffffffu, pd, o);
        if (!lane) kd += (double)pd;

        float mx2 = -1e30f;
        #pragma unroll
        for (int q = 0; q < 32; q++) {
            int j = lane + (q << 5);
            float u = up[j];
            float gn = -__logf(-__logf(u + 1e-10f) + 1e-10f);
            float a = lg[q] + gn;
            lg[q] = a;
            mx2 = fmaxf(mx2, a);
        }
        #pragma unroll
        for (int o = 16; o; o >>= 1) mx2 = fmaxf(mx2, __shfl_xor_sync(0xffffffffu, mx2, o));

        float s2 = 0.f;
        #pragma unroll
        for (int q = 0; q < 32; q++) { float e = __expf(lg[q] - mx2); lg[q] = e; s2 += e; }
        #pragma unroll
        for (int o = 16; o; o >>= 1) s2 += __shfl_xor_sync(0xffffffffu, s2, o);
        const float inv = 1.f / s2;

        __half* eph = g_ah + (size_t)row * KCB;
        __half* epl = g_al + (size_t)row * KCB;
        #pragma unroll
        for (int q = 0; q < 32; q++) {
            int j = lane + (q << 5);
            split2(lg[q] * inv, eph + j, epl + j);
        }
    }
    __syncthreads();

    for (int j = tid; j < KCB; j += 256) {
        float s = 0.f;
        #pragma unroll
        for (int ww = 0; ww < 8; ww++) s += s_avg[ww][j];
        atomicAdd(&g_avgp[j], s);
    }
    if (!lane) atomicAdd(&g_kldd, kd);
}

// ---------------- sum((z - z_q)^2) + split z_q for decoder -------------------
__global__ void __launch_bounds__(256) sq_kernel()
{
    size_t gid = (size_t)blockIdx.x * 256 + threadIdx.x;
    size_t stride = (size_t)gridDim.x * 256;
    float acc = 0.f;
    for (size_t i = gid; i < (size_t)NTOK * DDIM; i += stride) {
        float qv = g_zq[i];
        float d = g_z[i] - qv;
        acc += d * d;
        split2(qv, g_ah + i, g_al + i);
    }
    #pragma unroll
    for (int o = 16; o; o >>= 1) acc += __shfl_xor_sync(0xffffffffu, acc, o);
    __shared__ double sred[8];
    int lane = threadIdx.x & 31, wid = threadIdx.x >> 5;
    if (!lane) sred[wid] = (double)acc;
    __syncthreads();
    if (threadIdx.x == 0) {
        double s = 0.0;
        #pragma unroll
        for (int i = 0; i < 8; i++) s += sred[i];
        atomicAdd(&g_kldc, s);
    }
}

// ---------------- finalize ----------------------------------------------------
__global__ void __launch_bounds__(256) fin_kernel(
    const float* __restrict__ lpq, float* __restrict__ out)
{
    __shared__ double red[256];
    const int tid = threadIdx.x;
    double h = 0.0;
    for (int j = tid; j < KCB; j += 256) {
        float a = g_avgp[j] * (1.f / NTOK);
        h += (double)(a * __logf(a + 1e-7f));
    }
    red[tid] = h; __syncthreads();
    #pragma unroll
    for (int o = 128; o; o >>= 1) { if (tid < o) red[tid] += red[tid + o]; __syncthreads(); }
    if (!tid) {
        float w = 0.5f / fmaxf(__expf(lpq[0]), 1e-10f);
        double loss = g_kldd / (double)NB + g_kldc * (double)w / (double)NB;
        out[(size_t)NTOK * DDIM]     = (float)loss;
        out[(size_t)NTOK * DDIM + 1] = __expf((float)(-red[0]));
    }
}

// ---------------- launch ------------------------------------------------------
extern "C" void kernel_launch(void* const* d_in, const int* in_sizes, int n_in,
                              void* d_out, int out_size)
{
    (void)in_sizes; (void)n_in; (void)out_size;
    const float* x    = (const float*)d_in[0];
    const float* gum  = (const float*)d_in[1];
    const float* ew1  = (const float*)d_in[2];  const float* eb1  = (const float*)d_in[3];
    const float* eg1  = (const float*)d_in[4];  const float* ebe1 = (const float*)d_in[5];
    const float* ew2  = (const float*)d_in[6];  const float* eb2  = (const float*)d_in[7];
    const float* eg2  = (const float*)d_in[8];  const float* ebe2 = (const float*)d_in[9];
    const float* dw1  = (const float*)d_in[10]; const float* db1  = (const float*)d_in[11];
    const float* dg1  = (const float*)d_in[12]; const float* dbe1 = (const float*)d_in[13];
    const float* dw2  = (const float*)d_in[14]; const float* db2  = (const float*)d_in[15];
    const float* dg2  = (const float*)d_in[16]; const float* dbe2 = (const float*)d_in[17];
    const float* cb   = (const float*)d_in[18];
    const float* lpq  = (const float*)d_in[19];
    float* out = (float*)d_out;

    float *p_h, *p_z, *p_zq, *p_dot, *p_zz;
    __half *p_ah, *p_al, *p_wh, *p_wl, *p_cbh, *p_cbl, *p_cbth, *p_cbtl;
    cudaGetSymbolAddress((void**)&p_h,    g_h);
    cudaGetSymbolAddress((void**)&p_z,    g_z);
    cudaGetSymbolAddress((void**)&p_zq,   g_zq);
    cudaGetSymbolAddress((void**)&p_dot,  g_dot);
    cudaGetSymbolAddress((void**)&p_zz,   g_zz);
    cudaGetSymbolAddress((void**)&p_ah,   g_ah);
    cudaGetSymbolAddress((void**)&p_al,   g_al);
    cudaGetSymbolAddress((void**)&p_wh,   g_wh);
    cudaGetSymbolAddress((void**)&p_wl,   g_wl);
    cudaGetSymbolAddress((void**)&p_cbh,  g_cbh);
    cudaGetSymbolAddress((void**)&p_cbl,  g_cbl);
    cudaGetSymbolAddress((void**)&p_cbth, g_cbth);
    cudaGetSymbolAddress((void**)&p_cbtl, g_cbtl);

    const int SMEM3 = 3 * 65536;
    const int SMEM2 = 3 * 49152;
    cudaFuncSetAttribute(mma_gemm<true, 3>, cudaFuncAttributeMaxDynamicSharedMemorySize, SMEM3);
    cudaFuncSetAttribute(mma_gemm<false,3>, cudaFuncAttributeMaxDynamicSharedMemorySize, SMEM3);
    cudaFuncSetAttribute(mma_gemm<true, 2>, cudaFuncAttributeMaxDynamicSharedMemorySize, SMEM2);
    cudaFuncSetAttribute(mma_gemm<false,2>, cudaFuncAttributeMaxDynamicSharedMemorySize, SMEM2);

    const int WSZ = DDIM * DDIM;
    dim3 gD(DDIM / 128, NTOK / 128);   // (4, 128)
    dim3 gK(KCB  / 128, NTOK / 128);   // (8, 128)

    // 1: fused prep
    prep_kernel<<<4128, 256>>>(x, ew1, ew2, dw1, dw2, cb);

    // 2-5: encoder (3-term fp16 — feeds precision-critical logits)
    mma_gemm<true, 3><<<gD, 256, SMEM3>>>(p_ah, p_al, p_wh + 0 * WSZ, p_wl + 0 * WSZ, eb1, p_h, NTOK, DDIM, DDIM);
    ln_kernel<<<NTOK, 256>>>(p_h, eg1, ebe1, nullptr, p_ah, p_al, nullptr);
    mma_gemm<true, 3><<<gD, 256, SMEM3>>>(p_ah, p_al, p_wh + 1 * WSZ, p_wl + 1 * WSZ, eb2, p_h, NTOK, DDIM, DDIM);
    ln_kernel<<<NTOK, 256>>>(p_h, eg2, ebe2, p_z, p_ah, p_al, p_zz);

    // 6: quantizer logits GEMM (3-term; launch #6 -> ncu -s 5 profiles this)
    mma_gemm<false,3><<<gK, 256, SMEM3>>>(p_ah, p_al, p_cbh, p_cbl, nullptr, p_dot, NTOK, KCB, DDIM);
    quant_kernel<<<256, 256>>>(gum, lpq);
    // zq GEMM: 2-term (post-softmax, tolerance ~1e-3 allows fp16-truncated B)
    mma_gemm<false,2><<<gD, 256, SMEM2>>>(p_ah, p_al, p_cbth, p_cbtl, nullptr, p_zq, NTOK, DDIM, KCB);
    sq_kernel<<<512, 256>>>();

    // decoder: 2-term
    mma_gemm<true, 2><<<gD, 256, SMEM2>>>(p_ah, p_al, p_wh + 2 * WSZ, p_wl + 2 * WSZ, db1, p_h, NTOK, DDIM, DDIM);
    ln_kernel<<<NTOK, 256>>>(p_h, dg1, dbe1, nullptr, p_ah, p_al, nullptr);
    mma_gemm<true, 2><<<gD, 256, SMEM2>>>(p_ah, p_al, p_wh + 3 * WSZ, p_wl + 3 * WSZ, db2, p_h, NTOK, DDIM, DDIM);
    ln_kernel<<<NTOK, 256>>>(p_h, dg2, dbe2, out, nullptr, nullptr, nullptr);

    fin_kernel<<<1, 256>>>(lpq, out);
}

// round 12
// speedup vs baseline: 1.2311x; 1.0793x over previous
#include <cuda_runtime.h>
#include <cuda_fp16.h>
#include <cstdint>
#include <cstddef>

#define NTOK 16384
#define DDIM 512
#define KCB  1024
#define NB   8

// ---------------- scratch (static device globals; no allocations) ----------
__device__ float g_h  [NTOK * DDIM];    // pre-LN MLP temp
__device__ float g_z  [NTOK * DDIM];    // encoder output (post-LN)
__device__ float g_zq [NTOK * DDIM];    // quantized
__device__ float g_dot[NTOK * KCB];     // z @ codebook^T
__device__ __align__(128) __half g_ah[NTOK * KCB];      // A-side split hi
__device__ __align__(128) __half g_al[NTOK * KCB];      // A-side split lo
__device__ __align__(128) __half g_wh[4 * DDIM * DDIM]; // transposed weights hi
__device__ __align__(128) __half g_wl[4 * DDIM * DDIM];
__device__ __align__(128) __half g_cbh [KCB * DDIM];    // codebook split (K-major rows)
__device__ __align__(128) __half g_cbl [KCB * DDIM];
__device__ __align__(128) __half g_cbth[DDIM * KCB];    // codebook^T split hi
__device__ __align__(128) __half g_cbtl[DDIM * KCB];
__device__ float  g_zz [NTOK];
__device__ float  g_cc [KCB];
__device__ float  g_avgp[KCB];
__device__ double g_kldd;
__device__ double g_kldc;

// ---------------- PTX helpers ----------------------------------------------
__device__ __forceinline__ uint32_t smem_u32(const void* p) {
    uint32_t a;
    asm("{ .reg .u64 t; cvta.to.shared.u64 t, %1; cvt.u32.u64 %0, t; }"
        : "=r"(a) : "l"(p));
    return a;
}

#define CP_ASYNC16(s, g) \
    asm volatile("cp.async.cg.shared.global [%0], [%1], 16;" :: "r"(s), "l"(g))
#define CP_COMMIT() asm volatile("cp.async.commit_group;" ::: "memory")
#define CP_WAIT(n)  asm volatile("cp.async.wait_group %0;" :: "n"(n) : "memory")

#define LDSM4(r, addr) \
    asm volatile("ldmatrix.sync.aligned.m8n8.x4.shared.b16 {%0,%1,%2,%3}, [%4];" \
        : "=r"((r)[0]), "=r"((r)[1]), "=r"((r)[2]), "=r"((r)[3]) : "r"(addr) : "memory")

#define MMA_F16(D, A, B0, B1) \
    asm volatile("mma.sync.aligned.m16n8k16.row.col.f32.f16.f16.f32 " \
        "{%0,%1,%2,%3}, {%4,%5,%6,%7}, {%8,%9}, {%0,%1,%2,%3};" \
        : "+f"((D)[0]), "+f"((D)[1]), "+f"((D)[2]), "+f"((D)[3]) \
        : "r"((A)[0]), "r"((A)[1]), "r"((A)[2]), "r"((A)[3]), "r"(B0), "r"(B1))

__device__ __forceinline__ uint32_t sw128(uint32_t off) {
    return off ^ ((off >> 3) & 0x70);
}

__device__ __forceinline__ void split2(float v, __half* oh, __half* ol) {
    __half h = __float2half(v);
    *oh = h;
    *ol = __float2half(v - __half2float(h));
}

// ---------------- tile loaders (SW128 swizzled, 128B rows) -------------------
// A: 128 rows x 64 fp16 (16KB) — 256 threads x 4 chunks
__device__ __forceinline__ void load_tileA(uint32_t tb, const __half* __restrict__ src,
                                           int r0, int k0, int K, int tid)
{
    #pragma unroll
    for (int i = 0; i < 4; i++) {
        int u = tid + (i << 8);
        int row = u >> 3, col8 = (u & 7) << 3;
        const __half* gp = src + (size_t)(r0 + row) * K + k0 + col8;
        uint32_t off = (uint32_t)((row << 7) + (col8 << 1));
        CP_ASYNC16(tb + sw128(off), gp);
    }
}
// B: 64 rows x 64 fp16 (8KB) — 256 threads x 2 chunks
__device__ __forceinline__ void load_tileB(uint32_t tb, const __half* __restrict__ src,
                                           int r0, int k0, int K, int tid)
{
    #pragma unroll
    for (int i = 0; i < 2; i++) {
        int u = tid + (i << 8);
        int row = u >> 3, col8 = (u & 7) << 3;
        const __half* gp = src + (size_t)(r0 + row) * K + k0 + col8;
        uint32_t off = (uint32_t)((row << 7) + (col8 << 1));
        CP_ASYNC16(tb + sw128(off), gp);
    }
}

// ---------------- mma.sync fp16 GEMM: C = (Ah+Al)@(B...)^T ------------------
// Tile 128x64, 2 CTAs/SM, 2-stage cp.async pipeline (dynamic smem = 2*STAGE).
// 256 threads, 8 warps in 4x2, each warp 32x32.
// TERMS==3: Ah*Bh + Ah*Bl + Al*Bh.  TERMS==2: Ah*Bh + Al*Bh.
template<bool BIASRELU, int TERMS>
__global__ void __launch_bounds__(256, 2) mma_gemm(
    const __half* __restrict__ Ah, const __half* __restrict__ Al,
    const __half* __restrict__ Bh, const __half* __restrict__ Bl,
    const float* __restrict__ bias, float* __restrict__ C,
    int M, int N, int K)
{
    constexpr int STAGE = (TERMS == 3) ? 49152 : 40960;
    extern __shared__ char smem[];
    const int tid  = threadIdx.x;
    const int wid  = tid >> 5, lane = tid & 31;
    const int wm   = wid & 3, wn = wid >> 2;      // 4x2 warp grid: 32x32 per warp
    const uint32_t sb = smem_u32(smem);

    const int row0 = blockIdx.y << 7, col0 = blockIdx.x << 6;
    const int nk = K >> 6;

    float acc[2][4][4];
    #pragma unroll
    for (int i = 0; i < 2; i++)
        #pragma unroll
        for (int j = 0; j < 4; j++)
            #pragma unroll
            for (int r = 0; r < 4; r++) acc[i][j][r] = 0.f;

    // per-lane ldmatrix bases (128B rows)
    const uint32_t a_row  = (uint32_t)(lane & 15);
    const uint32_t a_koff = (uint32_t)((lane >> 4) << 4);
    const uint32_t b_row  = (uint32_t)(((lane >> 4) << 3) + (lane & 7));
    const uint32_t b_koff = (uint32_t)(((lane >> 3) & 1) << 4);

    // prologue: stage 0
    load_tileA(sb + 0,     Ah, row0, 0, K, tid);
    load_tileA(sb + 16384, Al, row0, 0, K, tid);
    load_tileB(sb + 32768, Bh, col0, 0, K, tid);
    if (TERMS == 3) load_tileB(sb + 40960, Bl, col0, 0, K, tid);
    CP_COMMIT();

    int buf = 0;
    for (int kt = 0; kt < nk; kt++) {
        // issue next-stage loads first, then wait for current stage
        if (kt + 1 < nk) {
            const int k0 = (kt + 1) << 6;
            const uint32_t st = sb + (buf ^ 1) * STAGE;
            load_tileA(st + 0,     Ah, row0, k0, K, tid);
            load_tileA(st + 16384, Al, row0, k0, K, tid);
            load_tileB(st + 32768, Bh, col0, k0, K, tid);
            if (TERMS == 3) load_tileB(st + 40960, Bl, col0, k0, K, tid);
            CP_COMMIT();
            CP_WAIT(1);
        } else {
            CP_WAIT(0);
        }
        __syncthreads();

        const uint32_t stA_h = sb + buf * STAGE;
        const uint32_t stA_l = stA_h + 16384;
        const uint32_t stB_h = stA_h + 32768;
        const uint32_t stB_l = stA_h + 40960;

        #pragma unroll
        for (int ks = 0; ks < 4; ks++) {
            const uint32_t k0b = (uint32_t)(ks << 5);
            uint32_t ah[2][4], al[2][4], bh[2][4], bl[2][4];
            #pragma unroll
            for (int mt = 0; mt < 2; mt++) {
                uint32_t off = ((uint32_t)(wm * 32 + mt * 16) + a_row) * 128 + k0b + a_koff;
                uint32_t s = sw128(off);
                LDSM4(ah[mt], stA_h + s);
                LDSM4(al[mt], stA_l + s);
            }
            #pragma unroll
            for (int np = 0; np < 2; np++) {
                uint32_t off = ((uint32_t)(wn * 32 + np * 16) + b_row) * 128 + k0b + b_koff;
                uint32_t s = sw128(off);
                LDSM4(bh[np], stB_h + s);
                if (TERMS == 3) LDSM4(bl[np], stB_l + s);
            }
            #pragma unroll
            for (int mt = 0; mt < 2; mt++) {
                #pragma unroll
                for (int nt = 0; nt < 4; nt++) {
                    const int np = nt >> 1, pr = (nt & 1) << 1;
                    MMA_F16(acc[mt][nt], ah[mt], bh[np][pr], bh[np][pr + 1]);
                    if (TERMS == 3)
                        MMA_F16(acc[mt][nt], ah[mt], bl[np][pr], bl[np][pr + 1]);
                    MMA_F16(acc[mt][nt], al[mt], bh[np][pr], bh[np][pr + 1]);
                }
            }
        }
        __syncthreads();    // all reads done before next iteration overwrites buf^1
        buf ^= 1;
    }

    // epilogue: each warp owns 32x32 at (wm*32, wn*32)
    const int erow = row0 + wm * 32 + (lane >> 2);
    const int ecol = col0 + wn * 32 + ((lane & 3) << 1);
    #pragma unroll
    for (int mt = 0; mt < 2; mt++) {
        #pragma unroll
        for (int nt = 0; nt < 4; nt++) {
            const int r0 = erow + mt * 16;
            const int c  = ecol + nt * 8;
            float v0 = acc[mt][nt][0], v1 = acc[mt][nt][1];
            float v2 = acc[mt][nt][2], v3 = acc[mt][nt][3];
            if (BIASRELU) {
                float b0 = bias[c], b1 = bias[c + 1];
                v0 = fmaxf(v0 + b0, 0.f); v1 = fmaxf(v1 + b1, 0.f);
                v2 = fmaxf(v2 + b0, 0.f); v3 = fmaxf(v3 + b1, 0.f);
            }
            *reinterpret_cast<float2*>(C + (size_t)r0 * N + c)       = make_float2(v0, v1);
            *reinterpret_cast<float2*>(C + (size_t)(r0 + 8) * N + c) = make_float2(v2, v3);
        }
    }
}

// ---------------- fused prep: weight/cb transposes+splits, x split, norms ----
__global__ void __launch_bounds__(256) prep_kernel(
    const float* __restrict__ x,
    const float* __restrict__ ew1, const float* __restrict__ ew2,
    const float* __restrict__ dw1, const float* __restrict__ dw2,
    const float* __restrict__ cb)
{
    __shared__ float t[32][33];
    const int blk = blockIdx.x, tid = threadIdx.x;

    if (blk < 1536) {
        const float* in; __half *oh, *ol; int R, C, bx, by;
        if (blk < 1024) {
            int w = blk >> 8, idx = blk & 255;
            const float* ws[4] = {ew1, ew2, dw1, dw2};
            in = ws[w];
            oh = g_wh + (size_t)w * DDIM * DDIM;
            ol = g_wl + (size_t)w * DDIM * DDIM;
            R = DDIM; C = DDIM; bx = idx & 15; by = idx >> 4;
        } else {
            int idx = blk - 1024;
            in = cb; oh = g_cbth; ol = g_cbtl;
            R = KCB; C = DDIM; bx = idx & 15; by = idx >> 4;
        }
        const int txx = tid & 31, tyy = tid >> 5;
        #pragma unroll
        for (int i = tyy; i < 32; i += 8)
            t[i][txx] = in[(size_t)(by * 32 + i) * C + bx * 32 + txx];
        __syncthreads();
        #pragma unroll
        for (int i = tyy; i < 32; i += 8) {
            float v = t[txx][i];
            size_t o = (size_t)(bx * 32 + i) * R + by * 32 + txx;
            split2(v, oh + o, ol + o);
        }
    } else if (blk < 2048) {
        int lb = blk - 1536;
        const int n = KCB * DDIM;
        for (int i = lb * 256 + tid; i < n; i += 512 * 256)
            split2(cb[i], g_cbh + i, g_cbl + i);
    } else if (blk < 4096) {
        int lb = blk - 2048;
        const int n = NTOK * DDIM;
        for (int i = lb * 256 + tid; i < n; i += 2048 * 256)
            split2(x[i], g_ah + i, g_al + i);
    } else {
        int lb = blk - 4096;
        int lane = tid & 31, wrp = tid >> 5;
        int gw = lb * 8 + wrp;
        for (int r = gw; r < KCB; r += 256) {
            const float* p = cb + (size_t)r * DDIM;
            float s = 0.f;
            for (int i = lane; i < DDIM; i += 32) { float v = p[i]; s += v * v; }
            #pragma unroll
            for (int o = 16; o; o >>= 1) s += __shfl_xor_sync(0xffffffffu, s, o);
            if (!lane) g_cc[r] = s;
        }
        int g = lb * 256 + tid;
        if (g < KCB) g_avgp[g] = 0.f;
        if (g == 0) { g_kldd = 0.0; g_kldc = 0.0; }
    }
}

// ---------------- LayerNorm (row 512) + optional fp32 out + fp16 splits ------
__global__ void __launch_bounds__(256) ln_kernel(
    const float* __restrict__ in, const float* __restrict__ g,
    const float* __restrict__ be, float* __restrict__ out,
    __half* __restrict__ oh, __half* __restrict__ ol,
    float* __restrict__ zz)
{
    __shared__ float sm[8];
    const int row = blockIdx.x, tid = threadIdx.x;
    const int lane = tid & 31, wrp = tid >> 5;
    const float* p = in + (size_t)row * DDIM;
    float x0 = p[tid], x1 = p[tid + 256];

    float s = x0 + x1;
    #pragma unroll
    for (int o = 16; o; o >>= 1) s += __shfl_xor_sync(0xffffffffu, s, o);
    if (!lane) sm[wrp] = s;
    __syncthreads();
    float mean = (sm[0] + sm[1] + sm[2] + sm[3] + sm[4] + sm[5] + sm[6] + sm[7]) * (1.f / DDIM);
    __syncthreads();

    float d0 = x0 - mean, d1 = x1 - mean;
    float v = d0 * d0 + d1 * d1;
    #pragma unroll
    for (int o = 16; o; o >>= 1) v += __shfl_xor_sync(0xffffffffu, v, o);
    if (!lane) sm[wrp] = v;
    __syncthreads();
    float rstd = rsqrtf((sm[0] + sm[1] + sm[2] + sm[3] + sm[4] + sm[5] + sm[6] + sm[7]) * (1.f / DDIM) + 1e-5f);

    float y0 = d0 * rstd * g[tid]       + be[tid];
    float y1 = d1 * rstd * g[tid + 256] + be[tid + 256];
    if (out) {
        float* q = out + (size_t)row * DDIM;
        q[tid] = y0; q[tid + 256] = y1;
    }
    if (oh) {
        size_t b = (size_t)row * DDIM;
        split2(y0, oh + b + tid,       ol + b + tid);
        split2(y1, oh + b + tid + 256, ol + b + tid + 256);
    }
    if (zz) {
        float q = y0 * y0 + y1 * y1;
        #pragma unroll
        for (int o = 16; o; o >>= 1) q += __shfl_xor_sync(0xffffffffu, q, o);
        __syncthreads();
        if (!lane) sm[wrp] = q;
        __syncthreads();
        if (!tid) zz[row] = sm[0] + sm[1] + sm[2] + sm[3] + sm[4] + sm[5] + sm[6] + sm[7];
    }
}

// ---------------- quantizer: writes encodings as fp16 splits -----------------
__global__ void __launch_bounds__(256) quant_kernel(
    const float* __restrict__ gum, const float* __restrict__ lpq)
{
    __shared__ float s_cc[KCB];
    __shared__ float s_avg[8][KCB];
    const int tid = threadIdx.x, lane = tid & 31, wid = tid >> 5;
    const float w = 0.5f / fmaxf(__expf(lpq[0]), 1e-10f);

    for (int j = tid; j < KCB; j += 256) s_cc[j] = g_cc[j];
    for (int j = tid; j < 8 * KCB; j += 256) (&s_avg[0][0])[j] = 0.f;
    __syncthreads();

    double kd = 0.0;
    const int row0 = blockIdx.x * 64;
    for (int r = wid; r < 64; r += 8) {
        const int row = row0 + r;
        const float* dp = g_dot + (size_t)row * KCB;
        const float* up = gum   + (size_t)row * KCB;
        const float zzr = g_zz[row];

        float lg[32];
        float mx = -1e30f;
        #pragma unroll
        for (int q = 0; q < 32; q++) {
            int j = lane + (q << 5);
            float l = w * (2.f * dp[j] - zzr - s_cc[j]);
            lg[q] = l;
            mx = fmaxf(mx, l);
        }
        #pragma unroll
        for (int o = 16; o; o >>= 1) mx = fmaxf(mx, __shfl_xor_sync(0xffffffffu, mx, o));

        float se = 0.f;
        #pragma unroll
        for (int q = 0; q < 32; q++) se += __expf(lg[q] - mx);
        #pragma unroll
        for (int o = 16; o; o >>= 1) se += __shfl_xor_sync(0xffffffffu, se, o);
        const float lse = __logf(se);

        float pd = 0.f;
        #pragma unroll
        for (int q = 0; q < 32; q++) {
            int j = lane + (q << 5);
            float lp = lg[q] - mx - lse;
            float p = __expf(lp);
            pd += p * lp;
            s_avg[wid][j] += p;
        }
        #pragma unroll
        for (int o = 16; o; o >>= 1) pd += __shfl_xor_sync(0xffffffffu, pd, o);
        if (!lane) kd += (double)pd;

        float mx2 = -1e30f;
        #pragma unroll
        for (int q = 0; q < 32; q++) {
            int j = lane + (q << 5);
            float u = up[j];
            float gn = -__logf(-__logf(u + 1e-10f) + 1e-10f);
            float a = lg[q] + gn;
            lg[q] = a;
            mx2 = fmaxf(mx2, a);
        }
        #pragma unroll
        for (int o = 16; o; o >>= 1) mx2 = fmaxf(mx2, __shfl_xor_sync(0xffffffffu, mx2, o));

        float s2 = 0.f;
        #pragma unroll
        for (int q = 0; q < 32; q++) { float e = __expf(lg[q] - mx2); lg[q] = e; s2 += e; }
        #pragma unroll
        for (int o = 16; o; o >>= 1) s2 += __shfl_xor_sync(0xffffffffu, s2, o);
        const float inv = 1.f / s2;

        __half* eph = g_ah + (size_t)row * KCB;
        __half* epl = g_al + (size_t)row * KCB;
        #pragma unroll
        for (int q = 0; q < 32; q++) {
            int j = lane + (q << 5);
            split2(lg[q] * inv, eph + j, epl + j);
        }
    }
    __syncthreads();

    for (int j = tid; j < KCB; j += 256) {
        float s = 0.f;
        #pragma unroll
        for (int ww = 0; ww < 8; ww++) s += s_avg[ww][j];
        atomicAdd(&g_avgp[j], s);
    }
    if (!lane) atomicAdd(&g_kldd, kd);
}

// ---------------- sum((z - z_q)^2) + split z_q for decoder -------------------
__global__ void __launch_bounds__(256) sq_kernel()
{
    size_t gid = (size_t)blockIdx.x * 256 + threadIdx.x;
    size_t stride = (size_t)gridDim.x * 256;
    float acc = 0.f;
    for (size_t i = gid; i < (size_t)NTOK * DDIM; i += stride) {
        float qv = g_zq[i];
        float d = g_z[i] - qv;
        acc += d * d;
        split2(qv, g_ah + i, g_al + i);
    }
    #pragma unroll
    for (int o = 16; o; o >>= 1) acc += __shfl_xor_sync(0xffffffffu, acc, o);
    __shared__ double sred[8];
    int lane = threadIdx.x & 31, wid = threadIdx.x >> 5;
    if (!lane) sred[wid] = (double)acc;
    __syncthreads();
    if (threadIdx.x == 0) {
        double s = 0.0;
        #pragma unroll
        for (int i = 0; i < 8; i++) s += sred[i];
        atomicAdd(&g_kldc, s);
    }
}

// ---------------- finalize ----------------------------------------------------
__global__ void __launch_bounds__(256) fin_kernel(
    const float* __restrict__ lpq, float* __restrict__ out)
{
    __shared__ double red[256];
    const int tid = threadIdx.x;
    double h = 0.0;
    for (int j = tid; j < KCB; j += 256) {
        float a = g_avgp[j] * (1.f / NTOK);
        h += (double)(a * __logf(a + 1e-7f));
    }
    red[tid] = h; __syncthreads();
    #pragma unroll
    for (int o = 128; o; o >>= 1) { if (tid < o) red[tid] += red[tid + o]; __syncthreads(); }
    if (!tid) {
        float w = 0.5f / fmaxf(__expf(lpq[0]), 1e-10f);
        double loss = g_kldd / (double)NB + g_kldc * (double)w / (double)NB;
        out[(size_t)NTOK * DDIM]     = (float)loss;
        out[(size_t)NTOK * DDIM + 1] = __expf((float)(-red[0]));
    }
}

// ---------------- launch ------------------------------------------------------
extern "C" void kernel_launch(void* const* d_in, const int* in_sizes, int n_in,
                              void* d_out, int out_size)
{
    (void)in_sizes; (void)n_in; (void)out_size;
    const float* x    = (const float*)d_in[0];
    const float* gum  = (const float*)d_in[1];
    const float* ew1  = (const float*)d_in[2];  const float* eb1  = (const float*)d_in[3];
    const float* eg1  = (const float*)d_in[4];  const float* ebe1 = (const float*)d_in[5];
    const float* ew2  = (const float*)d_in[6];  const float* eb2  = (const float*)d_in[7];
    const float* eg2  = (const float*)d_in[8];  const float* ebe2 = (const float*)d_in[9];
    const float* dw1  = (const float*)d_in[10]; const float* db1  = (const float*)d_in[11];
    const float* dg1  = (const float*)d_in[12]; const float* dbe1 = (const float*)d_in[13];
    const float* dw2  = (const float*)d_in[14]; const float* db2  = (const float*)d_in[15];
    const float* dg2  = (const float*)d_in[16]; const float* dbe2 = (const float*)d_in[17];
    const float* cb   = (const float*)d_in[18];
    const float* lpq  = (const float*)d_in[19];
    float* out = (float*)d_out;

    float *p_h, *p_z, *p_zq, *p_dot, *p_zz;
    __half *p_ah, *p_al, *p_wh, *p_wl, *p_cbh, *p_cbl, *p_cbth, *p_cbtl;
    cudaGetSymbolAddress((void**)&p_h,    g_h);
    cudaGetSymbolAddress((void**)&p_z,    g_z);
    cudaGetSymbolAddress((void**)&p_zq,   g_zq);
    cudaGetSymbolAddress((void**)&p_dot,  g_dot);
    cudaGetSymbolAddress((void**)&p_zz,   g_zz);
    cudaGetSymbolAddress((void**)&p_ah,   g_ah);
    cudaGetSymbolAddress((void**)&p_al,   g_al);
    cudaGetSymbolAddress((void**)&p_wh,   g_wh);
    cudaGetSymbolAddress((void**)&p_wl,   g_wl);
    cudaGetSymbolAddress((void**)&p_cbh,  g_cbh);
    cudaGetSymbolAddress((void**)&p_cbl,  g_cbl);
    cudaGetSymbolAddress((void**)&p_cbth, g_cbth);
    cudaGetSymbolAddress((void**)&p_cbtl, g_cbtl);

    const int SMEM3 = 2 * 49152;   // 96KB/CTA (2-stage) -> 2 CTAs/SM = 192KB
    const int SMEM2 = 2 * 40960;   // 80KB/CTA (2-stage) -> 2 CTAs/SM = 160KB
    cudaFuncSetAttribute(mma_gemm<true, 3>, cudaFuncAttributeMaxDynamicSharedMemorySize, SMEM3);
    cudaFuncSetAttribute(mma_gemm<false,3>, cudaFuncAttributeMaxDynamicSharedMemorySize, SMEM3);
    cudaFuncSetAttribute(mma_gemm<true, 2>, cudaFuncAttributeMaxDynamicSharedMemorySize, SMEM2);
    cudaFuncSetAttribute(mma_gemm<false,2>, cudaFuncAttributeMaxDynamicSharedMemorySize, SMEM2);

    const int WSZ = DDIM * DDIM;
    dim3 gD(DDIM / 64, NTOK / 128);   // (8, 128) = 1024 CTAs
    dim3 gK(KCB  / 64, NTOK / 128);   // (16, 128) = 2048 CTAs

    // 1: fused prep
    prep_kernel<<<4128, 256>>>(x, ew1, ew2, dw1, dw2, cb);

    // 2-5: encoder (3-term fp16 — feeds precision-critical logits)
    mma_gemm<true, 3><<<gD, 256, SMEM3>>>(p_ah, p_al, p_wh + 0 * WSZ, p_wl + 0 * WSZ, eb1, p_h, NTOK, DDIM, DDIM);
    ln_kernel<<<NTOK, 256>>>(p_h, eg1, ebe1, nullptr, p_ah, p_al, nullptr);
    mma_gemm<true, 3><<<gD, 256, SMEM3>>>(p_ah, p_al, p_wh + 1 * WSZ, p_wl + 1 * WSZ, eb2, p_h, NTOK, DDIM, DDIM);
    ln_kernel<<<NTOK, 256>>>(p_h, eg2, ebe2, p_z, p_ah, p_al, p_zz);

    // 6: quantizer logits GEMM (3-term; launch #6 -> ncu -s 5 profiles this)
    mma_gemm<false,3><<<gK, 256, SMEM3>>>(p_ah, p_al, p_cbh, p_cbl, nullptr, p_dot, NTOK, KCB, DDIM);
    quant_kernel<<<256, 256>>>(gum, lpq);
    // zq GEMM: 2-term (post-softmax tolerance allows fp16-truncated B)
    mma_gemm<false,2><<<gD, 256, SMEM2>>>(p_ah, p_al, p_cbth, p_cbtl, nullptr, p_zq, NTOK, DDIM, KCB);
    sq_kernel<<<512, 256>>>();

    // decoder: 2-term
    mma_gemm<true, 2><<<gD, 256, SMEM2>>>(p_ah, p_al, p_wh + 2 * WSZ, p_wl + 2 * WSZ, db1, p_h, NTOK, DDIM, DDIM);
    ln_kernel<<<NTOK, 256>>>(p_h, dg1, dbe1, nullptr, p_ah, p_al, nullptr);
    mma_gemm<true, 2><<<gD, 256, SMEM2>>>(p_ah, p_al, p_wh + 3 * WSZ, p_wl + 3 * WSZ, db2, p_h, NTOK, DDIM, DDIM);
    ln_kernel<<<NTOK, 256>>>(p_h, dg2, dbe2, out, nullptr, nullptr, nullptr);

    fin_kernel<<<1, 256>>>(lpq, out);
}

// round 13
// speedup vs baseline: 1.2433x; 1.0099x over previous
#include <cuda_runtime.h>
#include <cuda_fp16.h>
#include <cstdint>
#include <cstddef>

#define NTOK 16384
#define DDIM 512
#define KCB  1024
#define NB   8

// ---------------- scratch (static device globals; no allocations) ----------
__device__ float g_h  [NTOK * DDIM];    // pre-LN MLP temp
__device__ float g_z  [NTOK * DDIM];    // encoder output (post-LN)
__device__ float g_dot[NTOK * KCB];     // z @ codebook^T
__device__ __align__(128) __half g_ah[NTOK * KCB];      // A-side split hi
__device__ __align__(128) __half g_al[NTOK * KCB];      // A-side split lo
__device__ __align__(128) __half g_qh[NTOK * DDIM];     // z_q split hi (decoder input)
__device__ __align__(128) __half g_ql[NTOK * DDIM];     // z_q split lo
__device__ __align__(128) __half g_wh[4 * DDIM * DDIM]; // transposed weights hi
__device__ __align__(128) __half g_wl[4 * DDIM * DDIM];
__device__ __align__(128) __half g_cbh [KCB * DDIM];    // codebook split (K-major rows)
__device__ __align__(128) __half g_cbl [KCB * DDIM];
__device__ __align__(128) __half g_cbth[DDIM * KCB];    // codebook^T split hi
__device__ __align__(128) __half g_cbtl[DDIM * KCB];
__device__ float  g_zz [NTOK];
__device__ float  g_cc [KCB];
__device__ float  g_avgp[KCB];
__device__ double g_kldd;
__device__ double g_kldc;

// ---------------- PTX helpers ----------------------------------------------
__device__ __forceinline__ uint32_t smem_u32(const void* p) {
    uint32_t a;
    asm("{ .reg .u64 t; cvta.to.shared.u64 t, %1; cvt.u32.u64 %0, t; }"
        : "=r"(a) : "l"(p));
    return a;
}

#define CP_ASYNC16(s, g) \
    asm volatile("cp.async.cg.shared.global [%0], [%1], 16;" :: "r"(s), "l"(g))
#define CP_COMMIT() asm volatile("cp.async.commit_group;" ::: "memory")
#define CP_WAIT(n)  asm volatile("cp.async.wait_group %0;" :: "n"(n) : "memory")

#define LDSM4(r, addr) \
    asm volatile("ldmatrix.sync.aligned.m8n8.x4.shared.b16 {%0,%1,%2,%3}, [%4];" \
        : "=r"((r)[0]), "=r"((r)[1]), "=r"((r)[2]), "=r"((r)[3]) : "r"(addr) : "memory")

#define MMA_F16(D, A, B0, B1) \
    asm volatile("mma.sync.aligned.m16n8k16.row.col.f32.f16.f16.f32 " \
        "{%0,%1,%2,%3}, {%4,%5,%6,%7}, {%8,%9}, {%0,%1,%2,%3};" \
        : "+f"((D)[0]), "+f"((D)[1]), "+f"((D)[2]), "+f"((D)[3]) \
        : "r"((A)[0]), "r"((A)[1]), "r"((A)[2]), "r"((A)[3]), "r"(B0), "r"(B1))

__device__ __forceinline__ uint32_t sw128(uint32_t off) {
    return off ^ ((off >> 3) & 0x70);
}

__device__ __forceinline__ void split2(float v, __half* oh, __half* ol) {
    __half h = __float2half(v);
    *oh = h;
    *ol = __float2half(v - __half2float(h));
}

// ---------------- tile loaders (SW128 swizzled, 128B rows) -------------------
__device__ __forceinline__ void load_tileA(uint32_t tb, const __half* __restrict__ src,
                                           int r0, int k0, int K, int tid)
{
    #pragma unroll
    for (int i = 0; i < 4; i++) {
        int u = tid + (i << 8);
        int row = u >> 3, col8 = (u & 7) << 3;
        const __half* gp = src + (size_t)(r0 + row) * K + k0 + col8;
        uint32_t off = (uint32_t)((row << 7) + (col8 << 1));
        CP_ASYNC16(tb + sw128(off), gp);
    }
}
__device__ __forceinline__ void load_tileB(uint32_t tb, const __half* __restrict__ src,
                                           int r0, int k0, int K, int tid)
{
    #pragma unroll
    for (int i = 0; i < 2; i++) {
        int u = tid + (i << 8);
        int row = u >> 3, col8 = (u & 7) << 3;
        const __half* gp = src + (size_t)(r0 + row) * K + k0 + col8;
        uint32_t off = (uint32_t)((row << 7) + (col8 << 1));
        CP_ASYNC16(tb + sw128(off), gp);
    }
}

// ---------------- mma.sync fp16 GEMM -----------------------------------------
// Tile 128x64, 2 CTAs/SM, 2-stage pipeline. 8 warps 4x2, 32x32/warp.
// TERMS: 3 = Ah*Bh+Ah*Bl+Al*Bh, 2 = Ah*Bh+Al*Bh.
// MODE:  0 = plain fp32 store, 1 = bias+relu fp32 store,
//        2 = sq-epilogue: no C store; reads Z, accumulates sum((z-zq)^2)
//            into g_kldc, writes fp16 splits to Qh/Ql.
template<int TERMS, int MODE>
__global__ void __launch_bounds__(256, 2) mma_gemm(
    const __half* __restrict__ Ah, const __half* __restrict__ Al,
    const __half* __restrict__ Bh, const __half* __restrict__ Bl,
    const float* __restrict__ bias, float* __restrict__ C,
    const float* __restrict__ Z, __half* __restrict__ Qh, __half* __restrict__ Ql,
    int M, int N, int K)
{
    constexpr int STAGE = (TERMS == 3) ? 49152 : 40960;
    extern __shared__ char smem[];
    const int tid  = threadIdx.x;
    const int wid  = tid >> 5, lane = tid & 31;
    const int wm   = wid & 3, wn = wid >> 2;      // 4x2 warp grid: 32x32 per warp
    const uint32_t sb = smem_u32(smem);

    const int row0 = blockIdx.y << 7, col0 = blockIdx.x << 6;
    const int nk = K >> 6;

    float acc[2][4][4];
    #pragma unroll
    for (int i = 0; i < 2; i++)
        #pragma unroll
        for (int j = 0; j < 4; j++)
            #pragma unroll
            for (int r = 0; r < 4; r++) acc[i][j][r] = 0.f;

    const uint32_t a_row  = (uint32_t)(lane & 15);
    const uint32_t a_koff = (uint32_t)((lane >> 4) << 4);
    const uint32_t b_row  = (uint32_t)(((lane >> 4) << 3) + (lane & 7));
    const uint32_t b_koff = (uint32_t)(((lane >> 3) & 1) << 4);

    // prologue: stage 0
    load_tileA(sb + 0,     Ah, row0, 0, K, tid);
    load_tileA(sb + 16384, Al, row0, 0, K, tid);
    load_tileB(sb + 32768, Bh, col0, 0, K, tid);
    if (TERMS == 3) load_tileB(sb + 40960, Bl, col0, 0, K, tid);
    CP_COMMIT();

    int buf = 0;
    for (int kt = 0; kt < nk; kt++) {
        if (kt + 1 < nk) {
            const int k0 = (kt + 1) << 6;
            const uint32_t st = sb + (buf ^ 1) * STAGE;
            load_tileA(st + 0,     Ah, row0, k0, K, tid);
            load_tileA(st + 16384, Al, row0, k0, K, tid);
            load_tileB(st + 32768, Bh, col0, k0, K, tid);
            if (TERMS == 3) load_tileB(st + 40960, Bl, col0, k0, K, tid);
            CP_COMMIT();
            CP_WAIT(1);
        } else {
            CP_WAIT(0);
        }
        __syncthreads();

        const uint32_t stA_h = sb + buf * STAGE;
        const uint32_t stA_l = stA_h + 16384;
        const uint32_t stB_h = stA_h + 32768;
        const uint32_t stB_l = stA_h + 40960;

        #pragma unroll
        for (int ks = 0; ks < 4; ks++) {
            const uint32_t k0b = (uint32_t)(ks << 5);
            uint32_t ah[2][4], al[2][4], bh[2][4], bl[2][4];
            #pragma unroll
            for (int mt = 0; mt < 2; mt++) {
                uint32_t off = ((uint32_t)(wm * 32 + mt * 16) + a_row) * 128 + k0b + a_koff;
                uint32_t s = sw128(off);
                LDSM4(ah[mt], stA_h + s);
                LDSM4(al[mt], stA_l + s);
            }
            #pragma unroll
            for (int np = 0; np < 2; np++) {
                uint32_t off = ((uint32_t)(wn * 32 + np * 16) + b_row) * 128 + k0b + b_koff;
                uint32_t s = sw128(off);
                LDSM4(bh[np], stB_h + s);
                if (TERMS == 3) LDSM4(bl[np], stB_l + s);
            }
            #pragma unroll
            for (int mt = 0; mt < 2; mt++) {
                #pragma unroll
                for (int nt = 0; nt < 4; nt++) {
                    const int np = nt >> 1, pr = (nt & 1) << 1;
                    MMA_F16(acc[mt][nt], ah[mt], bh[np][pr], bh[np][pr + 1]);
                    if (TERMS == 3)
                        MMA_F16(acc[mt][nt], ah[mt], bl[np][pr], bl[np][pr + 1]);
                    MMA_F16(acc[mt][nt], al[mt], bh[np][pr], bh[np][pr + 1]);
                }
            }
        }
        __syncthreads();
        buf ^= 1;
    }

    // epilogue: each warp owns 32x32 at (wm*32, wn*32)
    const int erow = row0 + wm * 32 + (lane >> 2);
    const int ecol = col0 + wn * 32 + ((lane & 3) << 1);
    float sacc = 0.f;
    #pragma unroll
    for (int mt = 0; mt < 2; mt++) {
        #pragma unroll
        for (int nt = 0; nt < 4; nt++) {
            const int r0 = erow + mt * 16;
            const int c  = ecol + nt * 8;
            float v0 = acc[mt][nt][0], v1 = acc[mt][nt][1];
            float v2 = acc[mt][nt][2], v3 = acc[mt][nt][3];
            if (MODE == 1) {
                float b0 = bias[c], b1 = bias[c + 1];
                v0 = fmaxf(v0 + b0, 0.f); v1 = fmaxf(v1 + b1, 0.f);
                v2 = fmaxf(v2 + b0, 0.f); v3 = fmaxf(v3 + b1, 0.f);
            }
            if (MODE == 2) {
                size_t i0 = (size_t)r0 * N + c, i1 = (size_t)(r0 + 8) * N + c;
                float2 z0 = *reinterpret_cast<const float2*>(Z + i0);
                float2 z1 = *reinterpret_cast<const float2*>(Z + i1);
                float d0 = z0.x - v0, d1 = z0.y - v1;
                float d2 = z1.x - v2, d3 = z1.y - v3;
                sacc += d0 * d0 + d1 * d1 + d2 * d2 + d3 * d3;
                split2(v0, Qh + i0,     Ql + i0);
                split2(v1, Qh + i0 + 1, Ql + i0 + 1);
                split2(v2, Qh + i1,     Ql + i1);
                split2(v3, Qh + i1 + 1, Ql + i1 + 1);
            } else {
                *reinterpret_cast<float2*>(C + (size_t)r0 * N + c)       = make_float2(v0, v1);
                *reinterpret_cast<float2*>(C + (size_t)(r0 + 8) * N + c) = make_float2(v2, v3);
            }
        }
    }
    if (MODE == 2) {
        #pragma unroll
        for (int o = 16; o; o >>= 1) sacc += __shfl_xor_sync(0xffffffffu, sacc, o);
        if (!lane) atomicAdd(&g_kldc, (double)sacc);
    }
}

// ---------------- fused prep: weight/cb transposes+splits, x split, norms ----
__global__ void __launch_bounds__(256) prep_kernel(
    const float* __restrict__ x,
    const float* __restrict__ ew1, const float* __restrict__ ew2,
    const float* __restrict__ dw1, const float* __restrict__ dw2,
    const float* __restrict__ cb)
{
    __shared__ float t[32][33];
    const int blk = blockIdx.x, tid = threadIdx.x;

    if (blk < 1536) {
        const float* in; __half *oh, *ol; int R, C, bx, by;
        if (blk < 1024) {
            int w = blk >> 8, idx = blk & 255;
            const float* ws[4] = {ew1, ew2, dw1, dw2};
            in = ws[w];
            oh = g_wh + (size_t)w * DDIM * DDIM;
            ol = g_wl + (size_t)w * DDIM * DDIM;
            R = DDIM; C = DDIM; bx = idx & 15; by = idx >> 4;
        } else {
            int idx = blk - 1024;
            in = cb; oh = g_cbth; ol = g_cbtl;
            R = KCB; C = DDIM; bx = idx & 15; by = idx >> 4;
        }
        const int txx = tid & 31, tyy = tid >> 5;
        #pragma unroll
        for (int i = tyy; i < 32; i += 8)
            t[i][txx] = in[(size_t)(by * 32 + i) * C + bx * 32 + txx];
        __syncthreads();
        #pragma unroll
        for (int i = tyy; i < 32; i += 8) {
            float v = t[txx][i];
            size_t o = (size_t)(bx * 32 + i) * R + by * 32 + txx;
            split2(v, oh + o, ol + o);
        }
    } else if (blk < 2048) {
        int lb = blk - 1536;
        const int n = KCB * DDIM;
        for (int i = lb * 256 + tid; i < n; i += 512 * 256)
            split2(cb[i], g_cbh + i, g_cbl + i);
    } else if (blk < 4096) {
        int lb = blk - 2048;
        const int n = NTOK * DDIM;
        for (int i = lb * 256 + tid; i < n; i += 2048 * 256)
            split2(x[i], g_ah + i, g_al + i);
    } else {
        int lb = blk - 4096;
        int lane = tid & 31, wrp = tid >> 5;
        int gw = lb * 8 + wrp;
        for (int r = gw; r < KCB; r += 256) {
            const float* p = cb + (size_t)r * DDIM;
            float s = 0.f;
            for (int i = lane; i < DDIM; i += 32) { float v = p[i]; s += v * v; }
            #pragma unroll
            for (int o = 16; o; o >>= 1) s += __shfl_xor_sync(0xffffffffu, s, o);
            if (!lane) g_cc[r] = s;
        }
        int g = lb * 256 + tid;
        if (g < KCB) g_avgp[g] = 0.f;
        if (g == 0) { g_kldd = 0.0; g_kldc = 0.0; }
    }
}

// ---------------- LayerNorm (row 512) + optional fp32 out + fp16 splits ------
__global__ void __launch_bounds__(256) ln_kernel(
    const float* __restrict__ in, const float* __restrict__ g,
    const float* __restrict__ be, float* __restrict__ out,
    __half* __restrict__ oh, __half* __restrict__ ol,
    float* __restrict__ zz)
{
    __shared__ float sm[8];
    const int row = blockIdx.x, tid = threadIdx.x;
    const int lane = tid & 31, wrp = tid >> 5;
    const float* p = in + (size_t)row * DDIM;
    float x0 = p[tid], x1 = p[tid + 256];

    float s = x0 + x1;
    #pragma unroll
    for (int o = 16; o; o >>= 1) s += __shfl_xor_sync(0xffffffffu, s, o);
    if (!lane) sm[wrp] = s;
    __syncthreads();
    float mean = (sm[0] + sm[1] + sm[2] + sm[3] + sm[4] + sm[5] + sm[6] + sm[7]) * (1.f / DDIM);
    __syncthreads();

    float d0 = x0 - mean, d1 = x1 - mean;
    float v = d0 * d0 + d1 * d1;
    #pragma unroll
    for (int o = 16; o; o >>= 1) v += __shfl_xor_sync(0xffffffffu, v, o);
    if (!lane) sm[wrp] = v;
    __syncthreads();
    float rstd = rsqrtf((sm[0] + sm[1] + sm[2] + sm[3] + sm[4] + sm[5] + sm[6] + sm[7]) * (1.f / DDIM) + 1e-5f);

    float y0 = d0 * rstd * g[tid]       + be[tid];
    float y1 = d1 * rstd * g[tid + 256] + be[tid + 256];
    if (out) {
        float* q = out + (size_t)row * DDIM;
        q[tid] = y0; q[tid + 256] = y1;
    }
    if (oh) {
        size_t b = (size_t)row * DDIM;
        split2(y0, oh + b + tid,       ol + b + tid);
        split2(y1, oh + b + tid + 256, ol + b + tid + 256);
    }
    if (zz) {
        float q = y0 * y0 + y1 * y1;
        #pragma unroll
        for (int o = 16; o; o >>= 1) q += __shfl_xor_sync(0xffffffffu, q, o);
        __syncthreads();
        if (!lane) sm[wrp] = q;
        __syncthreads();
        if (!tid) zz[row] = sm[0] + sm[1] + sm[2] + sm[3] + sm[4] + sm[5] + sm[6] + sm[7];
    }
}

// ---------------- quantizer: 512 blocks x 32 rows ----------------------------
__global__ void __launch_bounds__(256) quant_kernel(
    const float* __restrict__ gum, const float* __restrict__ lpq)
{
    __shared__ float s_cc[KCB];
    __shared__ float s_avg[8][KCB];
    const int tid = threadIdx.x, lane = tid & 31, wid = tid >> 5;
    const float w = 0.5f / fmaxf(__expf(lpq[0]), 1e-10f);

    for (int j = tid; j < KCB; j += 256) s_cc[j] = g_cc[j];
    for (int j = tid; j < 8 * KCB; j += 256) (&s_avg[0][0])[j] = 0.f;
    __syncthreads();

    double kd = 0.0;
    const int row0 = blockIdx.x * 32;
    for (int r = wid; r < 32; r += 8) {
        const int row = row0 + r;
        const float* dp = g_dot + (size_t)row * KCB;
        const float* up = gum   + (size_t)row * KCB;
        const float zzr = g_zz[row];

        float lg[32];
        float mx = -1e30f;
        #pragma unroll
        for (int q = 0; q < 32; q++) {
            int j = lane + (q << 5);
            float l = w * (2.f * dp[j] - zzr - s_cc[j]);
            lg[q] = l;
            mx = fmaxf(mx, l);
        }
        #pragma unroll
        for (int o = 16; o; o >>= 1) mx = fmaxf(mx, __shfl_xor_sync(0xffffffffu, mx, o));

        float se = 0.f;
        #pragma unroll
        for (int q = 0; q < 32; q++) se += __expf(lg[q] - mx);
        #pragma unroll
        for (int o = 16; o; o >>= 1) se += __shfl_xor_sync(0xffffffffu, se, o);
        const float lse = __logf(se);

        float pd = 0.f;
        #pragma unroll
        for (int q = 0; q < 32; q++) {
            int j = lane + (q << 5);
            float lp = lg[q] - mx - lse;
            float p = __expf(lp);
            pd += p * lp;
            s_avg[wid][j] += p;
        }
        #pragma unroll
        for (int o = 16; o; o >>= 1) pd += __shfl_xor_sync(0xffffffffu, pd, o);
        if (!lane) kd += (double)pd;

        float mx2 = -1e30f;
        #pragma unroll
        for (int q = 0; q < 32; q++) {
            int j = lane + (q << 5);
            float u = up[j];
            float gn = -__logf(-__logf(u + 1e-10f) + 1e-10f);
            float a = lg[q] + gn;
            lg[q] = a;
            mx2 = fmaxf(mx2, a);
        }
        #pragma unroll
        for (int o = 16; o; o >>= 1) mx2 = fmaxf(mx2, __shfl_xor_sync(0xffffffffu, mx2, o));

        float s2 = 0.f;
        #pragma unroll
        for (int q = 0; q < 32; q++) { float e = __expf(lg[q] - mx2); lg[q] = e; s2 += e; }
        #pragma unroll
        for (int o = 16; o; o >>= 1) s2 += __shfl_xor_sync(0xffffffffu, s2, o);
        const float inv = 1.f / s2;

        __half* eph = g_ah + (size_t)row * KCB;
        __half* epl = g_al + (size_t)row * KCB;
        #pragma unroll
        for (int q = 0; q < 32; q++) {
            int j = lane + (q << 5);
            split2(lg[q] * inv, eph + j, epl + j);
        }
    }
    __syncthreads();

    for (int j = tid; j < KCB; j += 256) {
        float s = 0.f;
        #pragma unroll
        for (int ww = 0; ww < 8; ww++) s += s_avg[ww][j];
        atomicAdd(&g_avgp[j], s);
    }
    if (!lane) atomicAdd(&g_kldd, kd);
}

// ---------------- finalize ----------------------------------------------------
__global__ void __launch_bounds__(256) fin_kernel(
    const float* __restrict__ lpq, float* __restrict__ out)
{
    __shared__ double red[256];
    const int tid = threadIdx.x;
    double h = 0.0;
    for (int j = tid; j < KCB; j += 256) {
        float a = g_avgp[j] * (1.f / NTOK);
        h += (double)(a * __logf(a + 1e-7f));
    }
    red[tid] = h; __syncthreads();
    #pragma unroll
    for (int o = 128; o; o >>= 1) { if (tid < o) red[tid] += red[tid + o]; __syncthreads(); }
    if (!tid) {
        float w = 0.5f / fmaxf(__expf(lpq[0]), 1e-10f);
        double loss = g_kldd / (double)NB + g_kldc * (double)w / (double)NB;
        out[(size_t)NTOK * DDIM]     = (float)loss;
        out[(size_t)NTOK * DDIM + 1] = __expf((float)(-red[0]));
    }
}

// ---------------- launch ------------------------------------------------------
extern "C" void kernel_launch(void* const* d_in, const int* in_sizes, int n_in,
                              void* d_out, int out_size)
{
    (void)in_sizes; (void)n_in; (void)out_size;
    const float* x    = (const float*)d_in[0];
    const float* gum  = (const float*)d_in[1];
    const float* ew1  = (const float*)d_in[2];  const float* eb1  = (const float*)d_in[3];
    const float* eg1  = (const float*)d_in[4];  const float* ebe1 = (const float*)d_in[5];
    const float* ew2  = (const float*)d_in[6];  const float* eb2  = (const float*)d_in[7];
    const float* eg2  = (const float*)d_in[8];  const float* ebe2 = (const float*)d_in[9];
    const float* dw1  = (const float*)d_in[10]; const float* db1  = (const float*)d_in[11];
    const float* dg1  = (const float*)d_in[12]; const float* dbe1 = (const float*)d_in[13];
    const float* dw2  = (const float*)d_in[14]; const float* db2  = (const float*)d_in[15];
    const float* dg2  = (const float*)d_in[16]; const float* dbe2 = (const float*)d_in[17];
    const float* cb   = (const float*)d_in[18];
    const float* lpq  = (const float*)d_in[19];
    float* out = (float*)d_out;

    float *p_h, *p_z, *p_dot, *p_zz;
    __half *p_ah, *p_al, *p_qh, *p_ql, *p_wh, *p_wl, *p_cbh, *p_cbl, *p_cbth, *p_cbtl;
    cudaGetSymbolAddress((void**)&p_h,    g_h);
    cudaGetSymbolAddress((void**)&p_z,    g_z);
    cudaGetSymbolAddress((void**)&p_dot,  g_dot);
    cudaGetSymbolAddress((void**)&p_zz,   g_zz);
    cudaGetSymbolAddress((void**)&p_ah,   g_ah);
    cudaGetSymbolAddress((void**)&p_al,   g_al);
    cudaGetSymbolAddress((void**)&p_qh,   g_qh);
    cudaGetSymbolAddress((void**)&p_ql,   g_ql);
    cudaGetSymbolAddress((void**)&p_wh,   g_wh);
    cudaGetSymbolAddress((void**)&p_wl,   g_wl);
    cudaGetSymbolAddress((void**)&p_cbh,  g_cbh);
    cudaGetSymbolAddress((void**)&p_cbl,  g_cbl);
    cudaGetSymbolAddress((void**)&p_cbth, g_cbth);
    cudaGetSymbolAddress((void**)&p_cbtl, g_cbtl);

    const int SMEM3 = 2 * 49152;   // 96KB/CTA -> 2 CTAs/SM
    const int SMEM2 = 2 * 40960;   // 80KB/CTA -> 2 CTAs/SM
    cudaFuncSetAttribute(mma_gemm<3,1>, cudaFuncAttributeMaxDynamicSharedMemorySize, SMEM3);
    cudaFuncSetAttribute(mma_gemm<3,0>, cudaFuncAttributeMaxDynamicSharedMemorySize, SMEM3);
    cudaFuncSetAttribute(mma_gemm<2,1>, cudaFuncAttributeMaxDynamicSharedMemorySize, SMEM2);
    cudaFuncSetAttribute(mma_gemm<2,2>, cudaFuncAttributeMaxDynamicSharedMemorySize, SMEM2);

    const int WSZ = DDIM * DDIM;
    dim3 gD(DDIM / 64, NTOK / 128);   // (8, 128)
    dim3 gK(KCB  / 64, NTOK / 128);   // (16, 128)

    // 1: fused prep
    prep_kernel<<<4128, 256>>>(x, ew1, ew2, dw1, dw2, cb);

    // 2-5: encoder (3-term fp16)
    mma_gemm<3,1><<<gD, 256, SMEM3>>>(p_ah, p_al, p_wh + 0 * WSZ, p_wl + 0 * WSZ, eb1, p_h,
                                      nullptr, nullptr, nullptr, NTOK, DDIM, DDIM);
    ln_kernel<<<NTOK, 256>>>(p_h, eg1, ebe1, nullptr, p_ah, p_al, nullptr);
    mma_gemm<3,1><<<gD, 256, SMEM3>>>(p_ah, p_al, p_wh + 1 * WSZ, p_wl + 1 * WSZ, eb2, p_h,
                                      nullptr, nullptr, nullptr, NTOK, DDIM, DDIM);
    ln_kernel<<<NTOK, 256>>>(p_h, eg2, ebe2, p_z, p_ah, p_al, p_zz);

    // 6: quantizer logits GEMM (3-term; launch #6 -> ncu -s 5 profiles this)
    mma_gemm<3,0><<<gK, 256, SMEM3>>>(p_ah, p_al, p_cbh, p_cbl, nullptr, p_dot,
                                      nullptr, nullptr, nullptr, NTOK, KCB, DDIM);
    quant_kernel<<<512, 256>>>(gum, lpq);
    // 8: zq GEMM with fused sq epilogue: reads z, accumulates kldc, writes q splits
    mma_gemm<2,2><<<gD, 256, SMEM2>>>(p_ah, p_al, p_cbth, p_cbtl, nullptr, nullptr,
                                      p_z, p_qh, p_ql, NTOK, DDIM, KCB);

    // decoder: 2-term (A = zq splits)
    mma_gemm<2,1><<<gD, 256, SMEM2>>>(p_qh, p_ql, p_wh + 2 * WSZ, p_wl + 2 * WSZ, db1, p_h,
                                      nullptr, nullptr, nullptr, NTOK, DDIM, DDIM);
    ln_kernel<<<NTOK, 256>>>(p_h, dg1, dbe1, nullptr, p_ah, p_al, nullptr);
    mma_gemm<2,1><<<gD, 256, SMEM2>>>(p_ah, p_al, p_wh + 3 * WSZ, p_wl + 3 * WSZ, db2, p_h,
                                      nullptr, nullptr, nullptr, NTOK, DDIM, DDIM);
    ln_kernel<<<NTOK, 256>>>(p_h, dg2, dbe2, out, nullptr, nullptr, nullptr);

    fin_kernel<<<1, 256>>>(lpq, out);
}

// round 14
// speedup vs baseline: 1.3225x; 1.0637x over previous
#include <cuda_runtime.h>
#include <cuda_fp16.h>
#include <cstdint>
#include <cstddef>

#define NTOK 16384
#define DDIM 512
#define KCB  1024
#define NB   8

// ---------------- scratch (static device globals; no allocations) ----------
__device__ float g_h  [NTOK * DDIM];    // pre-LN MLP temp
__device__ float g_z  [NTOK * DDIM];    // encoder output (post-LN)
__device__ float g_dot[NTOK * KCB];     // z @ codebook^T
__device__ __align__(128) __half g_ah[NTOK * KCB];      // A-side split hi
__device__ __align__(128) __half g_al[NTOK * KCB];      // A-side split lo
__device__ __align__(128) __half g_qh[NTOK * DDIM];     // z_q split hi (decoder input)
__device__ __align__(128) __half g_ql[NTOK * DDIM];     // z_q split lo
__device__ __align__(128) __half g_wh[4 * DDIM * DDIM]; // transposed weights hi
__device__ __align__(128) __half g_wl[4 * DDIM * DDIM];
__device__ __align__(128) __half g_cbh [KCB * DDIM];    // codebook split (K-major rows)
__device__ __align__(128) __half g_cbl [KCB * DDIM];
__device__ __align__(128) __half g_cbth[DDIM * KCB];    // codebook^T split hi
__device__ __align__(128) __half g_cbtl[DDIM * KCB];
__device__ float  g_cc [KCB];
__device__ float  g_avgp[KCB];
__device__ double g_kldd;
__device__ double g_kldc;

// ---------------- PTX helpers ----------------------------------------------
__device__ __forceinline__ uint32_t smem_u32(const void* p) {
    uint32_t a;
    asm("{ .reg .u64 t; cvta.to.shared.u64 t, %1; cvt.u32.u64 %0, t; }"
        : "=r"(a) : "l"(p));
    return a;
}

#define CP_ASYNC16(s, g) \
    asm volatile("cp.async.cg.shared.global [%0], [%1], 16;" :: "r"(s), "l"(g))
#define CP_COMMIT() asm volatile("cp.async.commit_group;" ::: "memory")
#define CP_WAIT(n)  asm volatile("cp.async.wait_group %0;" :: "n"(n) : "memory")

#define LDSM4(r, addr) \
    asm volatile("ldmatrix.sync.aligned.m8n8.x4.shared.b16 {%0,%1,%2,%3}, [%4];" \
        : "=r"((r)[0]), "=r"((r)[1]), "=r"((r)[2]), "=r"((r)[3]) : "r"(addr) : "memory")

#define MMA_F16(D, A, B0, B1) \
    asm volatile("mma.sync.aligned.m16n8k16.row.col.f32.f16.f16.f32 " \
        "{%0,%1,%2,%3}, {%4,%5,%6,%7}, {%8,%9}, {%0,%1,%2,%3};" \
        : "+f"((D)[0]), "+f"((D)[1]), "+f"((D)[2]), "+f"((D)[3]) \
        : "r"((A)[0]), "r"((A)[1]), "r"((A)[2]), "r"((A)[3]), "r"(B0), "r"(B1))

__device__ __forceinline__ uint32_t sw128(uint32_t off) {
    return off ^ ((off >> 3) & 0x70);
}

__device__ __forceinline__ void split2(float v, __half* oh, __half* ol) {
    __half h = __float2half(v);
    *oh = h;
    *ol = __float2half(v - __half2float(h));
}
// split a float2 into packed half2 hi/lo
__device__ __forceinline__ void split2v(float2 v, __half2* oh, __half2* ol) {
    __half h0 = __float2half(v.x), h1 = __float2half(v.y);
    *oh = __halves2half2(h0, h1);
    *ol = __halves2half2(__float2half(v.x - __half2float(h0)),
                         __float2half(v.y - __half2float(h1)));
}

// ---------------- tile loaders (SW128 swizzled, 128B rows) -------------------
__device__ __forceinline__ void load_tileA(uint32_t tb, const __half* __restrict__ src,
                                           int r0, int k0, int K, int tid)
{
    #pragma unroll
    for (int i = 0; i < 4; i++) {
        int u = tid + (i << 8);
        int row = u >> 3, col8 = (u & 7) << 3;
        const __half* gp = src + (size_t)(r0 + row) * K + k0 + col8;
        uint32_t off = (uint32_t)((row << 7) + (col8 << 1));
        CP_ASYNC16(tb + sw128(off), gp);
    }
}
__device__ __forceinline__ void load_tileB(uint32_t tb, const __half* __restrict__ src,
                                           int r0, int k0, int K, int tid)
{
    #pragma unroll
    for (int i = 0; i < 2; i++) {
        int u = tid + (i << 8);
        int row = u >> 3, col8 = (u & 7) << 3;
        const __half* gp = src + (size_t)(r0 + row) * K + k0 + col8;
        uint32_t off = (uint32_t)((row << 7) + (col8 << 1));
        CP_ASYNC16(tb + sw128(off), gp);
    }
}

// ---------------- mma.sync fp16 GEMM -----------------------------------------
// Tile 128x64, 2 CTAs/SM, 2-stage pipeline. 8 warps 4x2, 32x32/warp.
// TERMS: 3 = Ah*Bh+Ah*Bl+Al*Bh, 2 = Ah*Bh+Al*Bh.
// MODE:  0 = plain fp32 store, 1 = bias+relu fp32 store,
//        2 = sq-epilogue: no C store; reads Z, accumulates sum((z-zq)^2),
//            writes fp16 splits to Qh/Ql.
template<int TERMS, int MODE>
__global__ void __launch_bounds__(256, 2) mma_gemm(
    const __half* __restrict__ Ah, const __half* __restrict__ Al,
    const __half* __restrict__ Bh, const __half* __restrict__ Bl,
    const float* __restrict__ bias, float* __restrict__ C,
    const float* __restrict__ Z, __half* __restrict__ Qh, __half* __restrict__ Ql,
    int M, int N, int K)
{
    constexpr int STAGE = (TERMS == 3) ? 49152 : 40960;
    extern __shared__ char smem[];
    const int tid  = threadIdx.x;
    const int wid  = tid >> 5, lane = tid & 31;
    const int wm   = wid & 3, wn = wid >> 2;
    const uint32_t sb = smem_u32(smem);

    const int row0 = blockIdx.y << 7, col0 = blockIdx.x << 6;
    const int nk = K >> 6;

    float acc[2][4][4];
    #pragma unroll
    for (int i = 0; i < 2; i++)
        #pragma unroll
        for (int j = 0; j < 4; j++)
            #pragma unroll
            for (int r = 0; r < 4; r++) acc[i][j][r] = 0.f;

    const uint32_t a_row  = (uint32_t)(lane & 15);
    const uint32_t a_koff = (uint32_t)((lane >> 4) << 4);
    const uint32_t b_row  = (uint32_t)(((lane >> 4) << 3) + (lane & 7));
    const uint32_t b_koff = (uint32_t)(((lane >> 3) & 1) << 4);

    load_tileA(sb + 0,     Ah, row0, 0, K, tid);
    load_tileA(sb + 16384, Al, row0, 0, K, tid);
    load_tileB(sb + 32768, Bh, col0, 0, K, tid);
    if (TERMS == 3) load_tileB(sb + 40960, Bl, col0, 0, K, tid);
    CP_COMMIT();

    int buf = 0;
    for (int kt = 0; kt < nk; kt++) {
        if (kt + 1 < nk) {
            const int k0 = (kt + 1) << 6;
            const uint32_t st = sb + (buf ^ 1) * STAGE;
            load_tileA(st + 0,     Ah, row0, k0, K, tid);
            load_tileA(st + 16384, Al, row0, k0, K, tid);
            load_tileB(st + 32768, Bh, col0, k0, K, tid);
            if (TERMS == 3) load_tileB(st + 40960, Bl, col0, k0, K, tid);
            CP_COMMIT();
            CP_WAIT(1);
        } else {
            CP_WAIT(0);
        }
        __syncthreads();

        const uint32_t stA_h = sb + buf * STAGE;
        const uint32_t stA_l = stA_h + 16384;
        const uint32_t stB_h = stA_h + 32768;
        const uint32_t stB_l = stA_h + 40960;

        #pragma unroll
        for (int ks = 0; ks < 4; ks++) {
            const uint32_t k0b = (uint32_t)(ks << 5);
            uint32_t ah[2][4], al[2][4], bh[2][4], bl[2][4];
            #pragma unroll
            for (int mt = 0; mt < 2; mt++) {
                uint32_t off = ((uint32_t)(wm * 32 + mt * 16) + a_row) * 128 + k0b + a_koff;
                uint32_t s = sw128(off);
                LDSM4(ah[mt], stA_h + s);
                LDSM4(al[mt], stA_l + s);
            }
            #pragma unroll
            for (int np = 0; np < 2; np++) {
                uint32_t off = ((uint32_t)(wn * 32 + np * 16) + b_row) * 128 + k0b + b_koff;
                uint32_t s = sw128(off);
                LDSM4(bh[np], stB_h + s);
                if (TERMS == 3) LDSM4(bl[np], stB_l + s);
            }
            #pragma unroll
            for (int mt = 0; mt < 2; mt++) {
                #pragma unroll
                for (int nt = 0; nt < 4; nt++) {
                    const int np = nt >> 1, pr = (nt & 1) << 1;
                    MMA_F16(acc[mt][nt], ah[mt], bh[np][pr], bh[np][pr + 1]);
                    if (TERMS == 3)
                        MMA_F16(acc[mt][nt], ah[mt], bl[np][pr], bl[np][pr + 1]);
                    MMA_F16(acc[mt][nt], al[mt], bh[np][pr], bh[np][pr + 1]);
                }
            }
        }
        __syncthreads();
        buf ^= 1;
    }

    // epilogue
    const int erow = row0 + wm * 32 + (lane >> 2);
    const int ecol = col0 + wn * 32 + ((lane & 3) << 1);
    float sacc = 0.f;
    #pragma unroll
    for (int mt = 0; mt < 2; mt++) {
        #pragma unroll
        for (int nt = 0; nt < 4; nt++) {
            const int r0 = erow + mt * 16;
            const int c  = ecol + nt * 8;
            float v0 = acc[mt][nt][0], v1 = acc[mt][nt][1];
            float v2 = acc[mt][nt][2], v3 = acc[mt][nt][3];
            if (MODE == 1) {
                float b0 = bias[c], b1 = bias[c + 1];
                v0 = fmaxf(v0 + b0, 0.f); v1 = fmaxf(v1 + b1, 0.f);
                v2 = fmaxf(v2 + b0, 0.f); v3 = fmaxf(v3 + b1, 0.f);
            }
            if (MODE == 2) {
                size_t i0 = (size_t)r0 * N + c, i1 = (size_t)(r0 + 8) * N + c;
                float2 z0 = *reinterpret_cast<const float2*>(Z + i0);
                float2 z1 = *reinterpret_cast<const float2*>(Z + i1);
                float d0 = z0.x - v0, d1 = z0.y - v1;
                float d2 = z1.x - v2, d3 = z1.y - v3;
                sacc += d0 * d0 + d1 * d1 + d2 * d2 + d3 * d3;
                split2v(make_float2(v0, v1),
                        reinterpret_cast<__half2*>(Qh + i0), reinterpret_cast<__half2*>(Ql + i0));
                split2v(make_float2(v2, v3),
                        reinterpret_cast<__half2*>(Qh + i1), reinterpret_cast<__half2*>(Ql + i1));
            } else {
                *reinterpret_cast<float2*>(C + (size_t)r0 * N + c)       = make_float2(v0, v1);
                *reinterpret_cast<float2*>(C + (size_t)(r0 + 8) * N + c) = make_float2(v2, v3);
            }
        }
    }
    if (MODE == 2) {
        #pragma unroll
        for (int o = 16; o; o >>= 1) sacc += __shfl_xor_sync(0xffffffffu, sacc, o);
        if (!lane) atomicAdd(&g_kldc, (double)sacc);
    }
}

// ---------------- fused prep: weight/cb transposes+splits, x split, norms ----
__global__ void __launch_bounds__(256) prep_kernel(
    const float* __restrict__ x,
    const float* __restrict__ ew1, const float* __restrict__ ew2,
    const float* __restrict__ dw1, const float* __restrict__ dw2,
    const float* __restrict__ cb)
{
    __shared__ float t[32][33];
    const int blk = blockIdx.x, tid = threadIdx.x;

    if (blk < 1536) {
        const float* in; __half *oh, *ol; int R, C, bx, by;
        if (blk < 1024) {
            int w = blk >> 8, idx = blk & 255;
            const float* ws[4] = {ew1, ew2, dw1, dw2};
            in = ws[w];
            oh = g_wh + (size_t)w * DDIM * DDIM;
            ol = g_wl + (size_t)w * DDIM * DDIM;
            R = DDIM; C = DDIM; bx = idx & 15; by = idx >> 4;
        } else {
            int idx = blk - 1024;
            in = cb; oh = g_cbth; ol = g_cbtl;
            R = KCB; C = DDIM; bx = idx & 15; by = idx >> 4;
        }
        const int txx = tid & 31, tyy = tid >> 5;
        #pragma unroll
        for (int i = tyy; i < 32; i += 8)
            t[i][txx] = in[(size_t)(by * 32 + i) * C + bx * 32 + txx];
        __syncthreads();
        #pragma unroll
        for (int i = tyy; i < 32; i += 8) {
            float v = t[txx][i];
            size_t o = (size_t)(bx * 32 + i) * R + by * 32 + txx;
            split2(v, oh + o, ol + o);
        }
    } else if (blk < 2048) {
        int lb = blk - 1536;
        const int n2 = (KCB * DDIM) >> 1;
        const float2* src = reinterpret_cast<const float2*>(cb);
        __half2* oh = reinterpret_cast<__half2*>(g_cbh);
        __half2* ol = reinterpret_cast<__half2*>(g_cbl);
        for (int i = lb * 256 + tid; i < n2; i += 512 * 256)
            split2v(src[i], oh + i, ol + i);
    } else if (blk < 4096) {
        int lb = blk - 2048;
        const int n2 = (NTOK * DDIM) >> 1;
        const float2* src = reinterpret_cast<const float2*>(x);
        __half2* oh = reinterpret_cast<__half2*>(g_ah);
        __half2* ol = reinterpret_cast<__half2*>(g_al);
        for (int i = lb * 256 + tid; i < n2; i += 2048 * 256)
            split2v(src[i], oh + i, ol + i);
    } else {
        int lb = blk - 4096;
        int lane = tid & 31, wrp = tid >> 5;
        int gw = lb * 8 + wrp;
        for (int r = gw; r < KCB; r += 256) {
            const float* p = cb + (size_t)r * DDIM;
            float s = 0.f;
            for (int i = lane; i < DDIM; i += 32) { float v = p[i]; s += v * v; }
            #pragma unroll
            for (int o = 16; o; o >>= 1) s += __shfl_xor_sync(0xffffffffu, s, o);
            if (!lane) g_cc[r] = s;
        }
        int g = lb * 256 + tid;
        if (g < KCB) g_avgp[g] = 0.f;
        if (g == 0) { g_kldd = 0.0; g_kldc = 0.0; }
    }
}

// ---------------- LayerNorm (row 512), vectorized ----------------------------
// thread t owns elements (2t, 2t+1): float2 loads, float2/half2 stores
__global__ void __launch_bounds__(256) ln_kernel(
    const float* __restrict__ in, const float* __restrict__ g,
    const float* __restrict__ be, float* __restrict__ out,
    __half* __restrict__ oh, __half* __restrict__ ol)
{
    __shared__ float sm[8];
    const int row = blockIdx.x, tid = threadIdx.x;
    const int lane = tid & 31, wrp = tid >> 5;
    const size_t base = (size_t)row * DDIM;
    float2 xv = *reinterpret_cast<const float2*>(in + base + 2 * tid);

    float s = xv.x + xv.y;
    #pragma unroll
    for (int o = 16; o; o >>= 1) s += __shfl_xor_sync(0xffffffffu, s, o);
    if (!lane) sm[wrp] = s;
    __syncthreads();
    float mean = (sm[0] + sm[1] + sm[2] + sm[3] + sm[4] + sm[5] + sm[6] + sm[7]) * (1.f / DDIM);
    __syncthreads();

    float d0 = xv.x - mean, d1 = xv.y - mean;
    float v = d0 * d0 + d1 * d1;
    #pragma unroll
    for (int o = 16; o; o >>= 1) v += __shfl_xor_sync(0xffffffffu, v, o);
    if (!lane) sm[wrp] = v;
    __syncthreads();
    float rstd = rsqrtf((sm[0] + sm[1] + sm[2] + sm[3] + sm[4] + sm[5] + sm[6] + sm[7]) * (1.f / DDIM) + 1e-5f);

    float2 gv  = *reinterpret_cast<const float2*>(g  + 2 * tid);
    float2 bev = *reinterpret_cast<const float2*>(be + 2 * tid);
    float y0 = d0 * rstd * gv.x + bev.x;
    float y1 = d1 * rstd * gv.y + bev.y;
    if (out)
        *reinterpret_cast<float2*>(out + base + 2 * tid) = make_float2(y0, y1);
    if (oh)
        split2v(make_float2(y0, y1),
                reinterpret_cast<__half2*>(oh + base + 2 * tid),
                reinterpret_cast<__half2*>(ol + base + 2 * tid));
}

// ---------------- quantizer: 512 blocks x 32 rows, vectorized ----------------
// thread lane owns elements j = 64*q + 2*lane + {0,1}, q = 0..15
__global__ void __launch_bounds__(256) quant_kernel(
    const float* __restrict__ gum, const float* __restrict__ lpq)
{
    __shared__ float s_cc[KCB];
    __shared__ float s_avg[8][KCB];
    const int tid = threadIdx.x, lane = tid & 31, wid = tid >> 5;
    const float w = 0.5f / fmaxf(__expf(lpq[0]), 1e-10f);

    for (int j = tid; j < KCB; j += 256) s_cc[j] = g_cc[j];
    for (int j = tid; j < 8 * KCB; j += 256) (&s_avg[0][0])[j] = 0.f;
    __syncthreads();

    double kd = 0.0;
    const int row0 = blockIdx.x * 32;
    for (int r = wid; r < 32; r += 8) {
        const int row = row0 + r;
        const float* dp = g_dot + (size_t)row * KCB;
        const float* up = gum   + (size_t)row * KCB;

        // logits (zz term dropped: row-constant shift cancels in softmax/logp)
        float lg[32];
        float mx = -1e30f;
        #pragma unroll
        for (int q = 0; q < 16; q++) {
            int j = (q << 6) + (lane << 1);
            float2 d2 = *reinterpret_cast<const float2*>(dp + j);
            float l0 = w * (2.f * d2.x - s_cc[j]);
            float l1 = w * (2.f * d2.y - s_cc[j + 1]);
            lg[2 * q] = l0; lg[2 * q + 1] = l1;
            mx = fmaxf(mx, fmaxf(l0, l1));
        }
        #pragma unroll
        for (int o = 16; o; o >>= 1) mx = fmaxf(mx, __shfl_xor_sync(0xffffffffu, mx, o));

        float se = 0.f;
        #pragma unroll
        for (int q = 0; q < 32; q++) se += __expf(lg[q] - mx);
        #pragma unroll
        for (int o = 16; o; o >>= 1) se += __shfl_xor_sync(0xffffffffu, se, o);
        const float lse = __logf(se);

        float pd = 0.f;
        #pragma unroll
        for (int q = 0; q < 16; q++) {
            int j = (q << 6) + (lane << 1);
            float lp0 = lg[2 * q]     - mx - lse;
            float lp1 = lg[2 * q + 1] - mx - lse;
            float p0 = __expf(lp0), p1 = __expf(lp1);
            pd += p0 * lp0 + p1 * lp1;
            s_avg[wid][j]     += p0;
            s_avg[wid][j + 1] += p1;
        }
        #pragma unroll
        for (int o = 16; o; o >>= 1) pd += __shfl_xor_sync(0xffffffffu, pd, o);
        if (!lane) kd += (double)pd;

        // gumbel-softmax
        float mx2 = -1e30f;
        #pragma unroll
        for (int q = 0; q < 16; q++) {
            int j = (q << 6) + (lane << 1);
            float2 u2 = *reinterpret_cast<const float2*>(up + j);
            float g0 = -__logf(-__logf(u2.x + 1e-10f) + 1e-10f);
            float g1 = -__logf(-__logf(u2.y + 1e-10f) + 1e-10f);
            float a0 = lg[2 * q] + g0, a1 = lg[2 * q + 1] + g1;
            lg[2 * q] = a0; lg[2 * q + 1] = a1;
            mx2 = fmaxf(mx2, fmaxf(a0, a1));
        }
        #pragma unroll
        for (int o = 16; o; o >>= 1) mx2 = fmaxf(mx2, __shfl_xor_sync(0xffffffffu, mx2, o));

        float s2 = 0.f;
        #pragma unroll
        for (int q = 0; q < 32; q++) { float e = __expf(lg[q] - mx2); lg[q] = e; s2 += e; }
        #pragma unroll
        for (int o = 16; o; o >>= 1) s2 += __shfl_xor_sync(0xffffffffu, s2, o);
        const float inv = 1.f / s2;

        __half* eph = g_ah + (size_t)row * KCB;
        __half* epl = g_al + (size_t)row * KCB;
        #pragma unroll
        for (int q = 0; q < 16; q++) {
            int j = (q << 6) + (lane << 1);
            split2v(make_float2(lg[2 * q] * inv, lg[2 * q + 1] * inv),
                    reinterpret_cast<__half2*>(eph + j),
                    reinterpret_cast<__half2*>(epl + j));
        }
    }
    __syncthreads();

    for (int j = tid; j < KCB; j += 256) {
        float s = 0.f;
        #pragma unroll
        for (int ww = 0; ww < 8; ww++) s += s_avg[ww][j];
        atomicAdd(&g_avgp[j], s);
    }
    if (!lane) atomicAdd(&g_kldd, kd);
}

// ---------------- finalize ----------------------------------------------------
__global__ void __launch_bounds__(256) fin_kernel(
    const float* __restrict__ lpq, float* __restrict__ out)
{
    __shared__ double red[256];
    const int tid = threadIdx.x;
    double h = 0.0;
    for (int j = tid; j < KCB; j += 256) {
        float a = g_avgp[j] * (1.f / NTOK);
        h += (double)(a * __logf(a + 1e-7f));
    }
    red[tid] = h; __syncthreads();
    #pragma unroll
    for (int o = 128; o; o >>= 1) { if (tid < o) red[tid] += red[tid + o]; __syncthreads(); }
    if (!tid) {
        float w = 0.5f / fmaxf(__expf(lpq[0]), 1e-10f);
        double loss = g_kldd / (double)NB + g_kldc * (double)w / (double)NB;
        out[(size_t)NTOK * DDIM]     = (float)loss;
        out[(size_t)NTOK * DDIM + 1] = __expf((float)(-red[0]));
    }
}

// ---------------- launch ------------------------------------------------------
extern "C" void kernel_launch(void* const* d_in, const int* in_sizes, int n_in,
                              void* d_out, int out_size)
{
    (void)in_sizes; (void)n_in; (void)out_size;
    const float* x    = (const float*)d_in[0];
    const float* gum  = (const float*)d_in[1];
    const float* ew1  = (const float*)d_in[2];  const float* eb1  = (const float*)d_in[3];
    const float* eg1  = (const float*)d_in[4];  const float* ebe1 = (const float*)d_in[5];
    const float* ew2  = (const float*)d_in[6];  const float* eb2  = (const float*)d_in[7];
    const float* eg2  = (const float*)d_in[8];  const float* ebe2 = (const float*)d_in[9];
    const float* dw1  = (const float*)d_in[10]; const float* db1  = (const float*)d_in[11];
    const float* dg1  = (const float*)d_in[12]; const float* dbe1 = (const float*)d_in[13];
    const float* dw2  = (const float*)d_in[14]; const float* db2  = (const float*)d_in[15];
    const float* dg2  = (const float*)d_in[16]; const float* dbe2 = (const float*)d_in[17];
    const float* cb   = (const float*)d_in[18];
    const float* lpq  = (const float*)d_in[19];
    float* out = (float*)d_out;

    float *p_h, *p_z, *p_dot;
    __half *p_ah, *p_al, *p_qh, *p_ql, *p_wh, *p_wl, *p_cbh, *p_cbl, *p_cbth, *p_cbtl;
    cudaGetSymbolAddress((void**)&p_h,    g_h);
    cudaGetSymbolAddress((void**)&p_z,    g_z);
    cudaGetSymbolAddress((void**)&p_dot,  g_dot);
    cudaGetSymbolAddress((void**)&p_ah,   g_ah);
    cudaGetSymbolAddress((void**)&p_al,   g_al);
    cudaGetSymbolAddress((void**)&p_qh,   g_qh);
    cudaGetSymbolAddress((void**)&p_ql,   g_ql);
    cudaGetSymbolAddress((void**)&p_wh,   g_wh);
    cudaGetSymbolAddress((void**)&p_wl,   g_wl);
    cudaGetSymbolAddress((void**)&p_cbh,  g_cbh);
    cudaGetSymbolAddress((void**)&p_cbl,  g_cbl);
    cudaGetSymbolAddress((void**)&p_cbth, g_cbth);
    cudaGetSymbolAddress((void**)&p_cbtl, g_cbtl);

    const int SMEM3 = 2 * 49152;
    const int SMEM2 = 2 * 40960;
    cudaFuncSetAttribute(mma_gemm<3,1>, cudaFuncAttributeMaxDynamicSharedMemorySize, SMEM3);
    cudaFuncSetAttribute(mma_gemm<3,0>, cudaFuncAttributeMaxDynamicSharedMemorySize, SMEM3);
    cudaFuncSetAttribute(mma_gemm<2,1>, cudaFuncAttributeMaxDynamicSharedMemorySize, SMEM2);
    cudaFuncSetAttribute(mma_gemm<2,2>, cudaFuncAttributeMaxDynamicSharedMemorySize, SMEM2);

    const int WSZ = DDIM * DDIM;
    dim3 gD(DDIM / 64, NTOK / 128);   // (8, 128)
    dim3 gK(KCB  / 64, NTOK / 128);   // (16, 128)

    // 1: fused prep
    prep_kernel<<<4128, 256>>>(x, ew1, ew2, dw1, dw2, cb);

    // 2-5: encoder (3-term fp16)
    mma_gemm<3,1><<<gD, 256, SMEM3>>>(p_ah, p_al, p_wh + 0 * WSZ, p_wl + 0 * WSZ, eb1, p_h,
                                      nullptr, nullptr, nullptr, NTOK, DDIM, DDIM);
    ln_kernel<<<NTOK, 256>>>(p_h, eg1, ebe1, nullptr, p_ah, p_al);
    mma_gemm<3,1><<<gD, 256, SMEM3>>>(p_ah, p_al, p_wh + 1 * WSZ, p_wl + 1 * WSZ, eb2, p_h,
                                      nullptr, nullptr, nullptr, NTOK, DDIM, DDIM);
    ln_kernel<<<NTOK, 256>>>(p_h, eg2, ebe2, p_z, p_ah, p_al);

    // 6: quantizer logits GEMM (3-term; launch #6 -> ncu -s 5 profiles this)
    mma_gemm<3,0><<<gK, 256, SMEM3>>>(p_ah, p_al, p_cbh, p_cbl, nullptr, p_dot,
                                      nullptr, nullptr, nullptr, NTOK, KCB, DDIM);
    quant_kernel<<<512, 256>>>(gum, lpq);
    // 8: zq GEMM with fused sq epilogue
    mma_gemm<2,2><<<gD, 256, SMEM2>>>(p_ah, p_al, p_cbth, p_cbtl, nullptr, nullptr,
                                      p_z, p_qh, p_ql, NTOK, DDIM, KCB);

    // decoder: 2-term (A = zq splits)
    mma_gemm<2,1><<<gD, 256, SMEM2>>>(p_qh, p_ql, p_wh + 2 * WSZ, p_wl + 2 * WSZ, db1, p_h,
                                      nullptr, nullptr, nullptr, NTOK, DDIM, DDIM);
    ln_kernel<<<NTOK, 256>>>(p_h, dg1, dbe1, nullptr, p_ah, p_al);
    mma_gemm<2,1><<<gD, 256, SMEM2>>>(p_ah, p_al, p_wh + 3 * WSZ, p_wl + 3 * WSZ, db2, p_h,
                                      nullptr, nullptr, nullptr, NTOK, DDIM, DDIM);
    ln_kernel<<<NTOK, 256>>>(p_h, dg2, dbe2, out, nullptr, nullptr);

    fin_kernel<<<1, 256>>>(lpq, out);
}

// round 15
// speedup vs baseline: 1.3555x; 1.0249x over previous
#include <cuda_runtime.h>
#include <cuda_fp16.h>
#include <cstdint>
#include <cstddef>

#define NTOK 16384
#define DDIM 512
#define KCB  1024
#define NB   8

// ---------------- scratch (static device globals; no allocations) ----------
__device__ float g_h  [NTOK * DDIM];    // pre-LN MLP temp
__device__ float g_z  [NTOK * DDIM];    // encoder output (post-LN)
__device__ float g_dot[NTOK * KCB];     // pre-scaled logits  w*(2 z.c - |c|^2)
__device__ __align__(128) __half g_ah[NTOK * KCB];      // A-side split hi
__device__ __align__(128) __half g_al[NTOK * KCB];      // A-side split lo
__device__ __align__(128) __half g_qh[NTOK * DDIM];     // z_q split hi (decoder input)
__device__ __align__(128) __half g_ql[NTOK * DDIM];     // z_q split lo
__device__ __align__(128) __half g_wh[4 * DDIM * DDIM]; // transposed weights hi
__device__ __align__(128) __half g_wl[4 * DDIM * DDIM];
__device__ __align__(128) __half g_cbh [KCB * DDIM];    // codebook split (K-major rows)
__device__ __align__(128) __half g_cbl [KCB * DDIM];
__device__ __align__(128) __half g_cbth[DDIM * KCB];    // codebook^T split hi
__device__ __align__(128) __half g_cbtl[DDIM * KCB];
__device__ float  g_cc [KCB];
__device__ float  g_avgp[KCB];
__device__ double g_kldd;
__device__ double g_kldc;

// ---------------- PTX helpers ----------------------------------------------
__device__ __forceinline__ uint32_t smem_u32(const void* p) {
    uint32_t a;
    asm("{ .reg .u64 t; cvta.to.shared.u64 t, %1; cvt.u32.u64 %0, t; }"
        : "=r"(a) : "l"(p));
    return a;
}

#define CP_ASYNC16(s, g) \
    asm volatile("cp.async.cg.shared.global [%0], [%1], 16;" :: "r"(s), "l"(g))
#define CP_COMMIT() asm volatile("cp.async.commit_group;" ::: "memory")
#define CP_WAIT(n)  asm volatile("cp.async.wait_group %0;" :: "n"(n) : "memory")

#define LDSM4(r, addr) \
    asm volatile("ldmatrix.sync.aligned.m8n8.x4.shared.b16 {%0,%1,%2,%3}, [%4];" \
        : "=r"((r)[0]), "=r"((r)[1]), "=r"((r)[2]), "=r"((r)[3]) : "r"(addr) : "memory")

#define MMA_F16(D, A, B0, B1) \
    asm volatile("mma.sync.aligned.m16n8k16.row.col.f32.f16.f16.f32 " \
        "{%0,%1,%2,%3}, {%4,%5,%6,%7}, {%8,%9}, {%0,%1,%2,%3};" \
        : "+f"((D)[0]), "+f"((D)[1]), "+f"((D)[2]), "+f"((D)[3]) \
        : "r"((A)[0]), "r"((A)[1]), "r"((A)[2]), "r"((A)[3]), "r"(B0), "r"(B1))

__device__ __forceinline__ uint32_t sw128(uint32_t off) {
    return off ^ ((off >> 3) & 0x70);
}

__device__ __forceinline__ void split2(float v, __half* oh, __half* ol) {
    __half h = __float2half(v);
    *oh = h;
    *ol = __float2half(v - __half2float(h));
}
__device__ __forceinline__ void split2v(float2 v, __half2* oh, __half2* ol) {
    __half h0 = __float2half(v.x), h1 = __float2half(v.y);
    *oh = __halves2half2(h0, h1);
    *ol = __halves2half2(__float2half(v.x - __half2float(h0)),
                         __float2half(v.y - __half2float(h1)));
}

// ---------------- tile loaders (SW128 swizzled, 128B rows) -------------------
__device__ __forceinline__ void load_tileA(uint32_t tb, const __half* __restrict__ src,
                                           int r0, int k0, int K, int tid)
{
    #pragma unroll
    for (int i = 0; i < 4; i++) {
        int u = tid + (i << 8);
        int row = u >> 3, col8 = (u & 7) << 3;
        const __half* gp = src + (size_t)(r0 + row) * K + k0 + col8;
        uint32_t off = (uint32_t)((row << 7) + (col8 << 1));
        CP_ASYNC16(tb + sw128(off), gp);
    }
}
__device__ __forceinline__ void load_tileB(uint32_t tb, const __half* __restrict__ src,
                                           int r0, int k0, int K, int tid)
{
    #pragma unroll
    for (int i = 0; i < 2; i++) {
        int u = tid + (i << 8);
        int row = u >> 3, col8 = (u & 7) << 3;
        const __half* gp = src + (size_t)(r0 + row) * K + k0 + col8;
        uint32_t off = (uint32_t)((row << 7) + (col8 << 1));
        CP_ASYNC16(tb + sw128(off), gp);
    }
}

// ---------------- mma.sync fp16 GEMM -----------------------------------------
// Tile 128x64, 2 CTAs/SM, 2-stage pipeline. 8 warps 4x2, 32x32/warp.
// TERMS: 3 = Ah*Bh+Ah*Bl+Al*Bh, 2 = Ah*Bh+Al*Bh.
// MODE:  0 = plain fp32 store, 1 = bias+relu fp32 store,
//        2 = sq-epilogue: no C store; reads Z, accumulates sum((z-zq)^2),
//            writes fp16 splits to Qh/Ql.
//        3 = logit epilogue: store 2w*v - w*cc[col]; bias = lpq (scalar ptr),
//            Z = cc (codebook row norms).
template<int TERMS, int MODE>
__global__ void __launch_bounds__(256, 2) mma_gemm(
    const __half* __restrict__ Ah, const __half* __restrict__ Al,
    const __half* __restrict__ Bh, const __half* __restrict__ Bl,
    const float* __restrict__ bias, float* __restrict__ C,
    const float* __restrict__ Z, __half* __restrict__ Qh, __half* __restrict__ Ql,
    int M, int N, int K)
{
    constexpr int STAGE = (TERMS == 3) ? 49152 : 40960;
    extern __shared__ char smem[];
    const int tid  = threadIdx.x;
    const int wid  = tid >> 5, lane = tid & 31;
    const int wm   = wid & 3, wn = wid >> 2;
    const uint32_t sb = smem_u32(smem);

    const int row0 = blockIdx.y << 7, col0 = blockIdx.x << 6;
    const int nk = K >> 6;

    float acc[2][4][4];
    #pragma unroll
    for (int i = 0; i < 2; i++)
        #pragma unroll
        for (int j = 0; j < 4; j++)
            #pragma unroll
            for (int r = 0; r < 4; r++) acc[i][j][r] = 0.f;

    const uint32_t a_row  = (uint32_t)(lane & 15);
    const uint32_t a_koff = (uint32_t)((lane >> 4) << 4);
    const uint32_t b_row  = (uint32_t)(((lane >> 4) << 3) + (lane & 7));
    const uint32_t b_koff = (uint32_t)(((lane >> 3) & 1) << 4);

    load_tileA(sb + 0,     Ah, row0, 0, K, tid);
    load_tileA(sb + 16384, Al, row0, 0, K, tid);
    load_tileB(sb + 32768, Bh, col0, 0, K, tid);
    if (TERMS == 3) load_tileB(sb + 40960, Bl, col0, 0, K, tid);
    CP_COMMIT();

    int buf = 0;
    for (int kt = 0; kt < nk; kt++) {
        if (kt + 1 < nk) {
            const int k0 = (kt + 1) << 6;
            const uint32_t st = sb + (buf ^ 1) * STAGE;
            load_tileA(st + 0,     Ah, row0, k0, K, tid);
            load_tileA(st + 16384, Al, row0, k0, K, tid);
            load_tileB(st + 32768, Bh, col0, k0, K, tid);
            if (TERMS == 3) load_tileB(st + 40960, Bl, col0, k0, K, tid);
            CP_COMMIT();
            CP_WAIT(1);
        } else {
            CP_WAIT(0);
        }
        __syncthreads();

        const uint32_t stA_h = sb + buf * STAGE;
        const uint32_t stA_l = stA_h + 16384;
        const uint32_t stB_h = stA_h + 32768;
        const uint32_t stB_l = stA_h + 40960;

        #pragma unroll
        for (int ks = 0; ks < 4; ks++) {
            const uint32_t k0b = (uint32_t)(ks << 5);
            uint32_t ah[2][4], al[2][4], bh[2][4], bl[2][4];
            #pragma unroll
            for (int mt = 0; mt < 2; mt++) {
                uint32_t off = ((uint32_t)(wm * 32 + mt * 16) + a_row) * 128 + k0b + a_koff;
                uint32_t s = sw128(off);
                LDSM4(ah[mt], stA_h + s);
                LDSM4(al[mt], stA_l + s);
            }
            #pragma unroll
            for (int np = 0; np < 2; np++) {
                uint32_t off = ((uint32_t)(wn * 32 + np * 16) + b_row) * 128 + k0b + b_koff;
                uint32_t s = sw128(off);
                LDSM4(bh[np], stB_h + s);
                if (TERMS == 3) LDSM4(bl[np], stB_l + s);
            }
            #pragma unroll
            for (int mt = 0; mt < 2; mt++) {
                #pragma unroll
                for (int nt = 0; nt < 4; nt++) {
                    const int np = nt >> 1, pr = (nt & 1) << 1;
                    MMA_F16(acc[mt][nt], ah[mt], bh[np][pr], bh[np][pr + 1]);
                    if (TERMS == 3)
                        MMA_F16(acc[mt][nt], ah[mt], bl[np][pr], bl[np][pr + 1]);
                    MMA_F16(acc[mt][nt], al[mt], bh[np][pr], bh[np][pr + 1]);
                }
            }
        }
        __syncthreads();
        buf ^= 1;
    }

    // epilogue
    const int erow = row0 + wm * 32 + (lane >> 2);
    const int ecol = col0 + wn * 32 + ((lane & 3) << 1);
    float sacc = 0.f;
    float wq = 0.f;
    if (MODE == 3) wq = 0.5f / fmaxf(__expf(bias[0]), 1e-10f);
    #pragma unroll
    for (int mt = 0; mt < 2; mt++) {
        #pragma unroll
        for (int nt = 0; nt < 4; nt++) {
            const int r0 = erow + mt * 16;
            const int c  = ecol + nt * 8;
            float v0 = acc[mt][nt][0], v1 = acc[mt][nt][1];
            float v2 = acc[mt][nt][2], v3 = acc[mt][nt][3];
            if (MODE == 1) {
                float b0 = bias[c], b1 = bias[c + 1];
                v0 = fmaxf(v0 + b0, 0.f); v1 = fmaxf(v1 + b1, 0.f);
                v2 = fmaxf(v2 + b0, 0.f); v3 = fmaxf(v3 + b1, 0.f);
            }
            if (MODE == 3) {
                float c0 = Z[c] * wq, c1 = Z[c + 1] * wq;
                float tw = 2.f * wq;
                v0 = tw * v0 - c0; v1 = tw * v1 - c1;
                v2 = tw * v2 - c0; v3 = tw * v3 - c1;
            }
            if (MODE == 2) {
                size_t i0 = (size_t)r0 * N + c, i1 = (size_t)(r0 + 8) * N + c;
                float2 z0 = *reinterpret_cast<const float2*>(Z + i0);
                float2 z1 = *reinterpret_cast<const float2*>(Z + i1);
                float d0 = z0.x - v0, d1 = z0.y - v1;
                float d2 = z1.x - v2, d3 = z1.y - v3;
                sacc += d0 * d0 + d1 * d1 + d2 * d2 + d3 * d3;
                split2v(make_float2(v0, v1),
                        reinterpret_cast<__half2*>(Qh + i0), reinterpret_cast<__half2*>(Ql + i0));
                split2v(make_float2(v2, v3),
                        reinterpret_cast<__half2*>(Qh + i1), reinterpret_cast<__half2*>(Ql + i1));
            } else {
                *reinterpret_cast<float2*>(C + (size_t)r0 * N + c)       = make_float2(v0, v1);
                *reinterpret_cast<float2*>(C + (size_t)(r0 + 8) * N + c) = make_float2(v2, v3);
            }
        }
    }
    if (MODE == 2) {
        #pragma unroll
        for (int o = 16; o; o >>= 1) sacc += __shfl_xor_sync(0xffffffffu, sacc, o);
        if (!lane) atomicAdd(&g_kldc, (double)sacc);
    }
}

// ---------------- fused prep: weight/cb transposes+splits, x split, norms ----
__global__ void __launch_bounds__(256) prep_kernel(
    const float* __restrict__ x,
    const float* __restrict__ ew1, const float* __restrict__ ew2,
    const float* __restrict__ dw1, const float* __restrict__ dw2,
    const float* __restrict__ cb)
{
    __shared__ float t[32][33];
    const int blk = blockIdx.x, tid = threadIdx.x;

    if (blk < 1536) {
        const float* in; __half *oh, *ol; int R, C, bx, by;
        if (blk < 1024) {
            int w = blk >> 8, idx = blk & 255;
            const float* ws[4] = {ew1, ew2, dw1, dw2};
            in = ws[w];
            oh = g_wh + (size_t)w * DDIM * DDIM;
            ol = g_wl + (size_t)w * DDIM * DDIM;
            R = DDIM; C = DDIM; bx = idx & 15; by = idx >> 4;
        } else {
            int idx = blk - 1024;
            in = cb; oh = g_cbth; ol = g_cbtl;
            R = KCB; C = DDIM; bx = idx & 15; by = idx >> 4;
        }
        const int txx = tid & 31, tyy = tid >> 5;
        #pragma unroll
        for (int i = tyy; i < 32; i += 8)
            t[i][txx] = in[(size_t)(by * 32 + i) * C + bx * 32 + txx];
        __syncthreads();
        #pragma unroll
        for (int i = tyy; i < 32; i += 8) {
            float v = t[txx][i];
            size_t o = (size_t)(bx * 32 + i) * R + by * 32 + txx;
            split2(v, oh + o, ol + o);
        }
    } else if (blk < 2048) {
        int lb = blk - 1536;
        const int n2 = (KCB * DDIM) >> 1;
        const float2* src = reinterpret_cast<const float2*>(cb);
        __half2* oh = reinterpret_cast<__half2*>(g_cbh);
        __half2* ol = reinterpret_cast<__half2*>(g_cbl);
        for (int i = lb * 256 + tid; i < n2; i += 512 * 256)
            split2v(src[i], oh + i, ol + i);
    } else if (blk < 4096) {
        int lb = blk - 2048;
        const int n2 = (NTOK * DDIM) >> 1;
        const float2* src = reinterpret_cast<const float2*>(x);
        __half2* oh = reinterpret_cast<__half2*>(g_ah);
        __half2* ol = reinterpret_cast<__half2*>(g_al);
        for (int i = lb * 256 + tid; i < n2; i += 2048 * 256)
            split2v(src[i], oh + i, ol + i);
    } else {
        int lb = blk - 4096;
        int lane = tid & 31, wrp = tid >> 5;
        int gw = lb * 8 + wrp;
        for (int r = gw; r < KCB; r += 256) {
            const float* p = cb + (size_t)r * DDIM;
            float s = 0.f;
            for (int i = lane; i < DDIM; i += 32) { float v = p[i]; s += v * v; }
            #pragma unroll
            for (int o = 16; o; o >>= 1) s += __shfl_xor_sync(0xffffffffu, s, o);
            if (!lane) g_cc[r] = s;
        }
        int g = lb * 256 + tid;
        if (g < KCB) g_avgp[g] = 0.f;
        if (g == 0) { g_kldd = 0.0; g_kldc = 0.0; }
    }
}

// ---------------- LayerNorm (row 512), vectorized ----------------------------
__global__ void __launch_bounds__(256) ln_kernel(
    const float* __restrict__ in, const float* __restrict__ g,
    const float* __restrict__ be, float* __restrict__ out,
    __half* __restrict__ oh, __half* __restrict__ ol)
{
    __shared__ float sm[8];
    const int row = blockIdx.x, tid = threadIdx.x;
    const int lane = tid & 31, wrp = tid >> 5;
    const size_t base = (size_t)row * DDIM;
    float2 xv = *reinterpret_cast<const float2*>(in + base + 2 * tid);

    float s = xv.x + xv.y;
    #pragma unroll
    for (int o = 16; o; o >>= 1) s += __shfl_xor_sync(0xffffffffu, s, o);
    if (!lane) sm[wrp] = s;
    __syncthreads();
    float mean = (sm[0] + sm[1] + sm[2] + sm[3] + sm[4] + sm[5] + sm[6] + sm[7]) * (1.f / DDIM);
    __syncthreads();

    float d0 = xv.x - mean, d1 = xv.y - mean;
    float v = d0 * d0 + d1 * d1;
    #pragma unroll
    for (int o = 16; o; o >>= 1) v += __shfl_xor_sync(0xffffffffu, v, o);
    if (!lane) sm[wrp] = v;
    __syncthreads();
    float rstd = rsqrtf((sm[0] + sm[1] + sm[2] + sm[3] + sm[4] + sm[5] + sm[6] + sm[7]) * (1.f / DDIM) + 1e-5f);

    float2 gv  = *reinterpret_cast<const float2*>(g  + 2 * tid);
    float2 bev = *reinterpret_cast<const float2*>(be + 2 * tid);
    float y0 = d0 * rstd * gv.x + bev.x;
    float y1 = d1 * rstd * gv.y + bev.y;
    if (out)
        *reinterpret_cast<float2*>(out + base + 2 * tid) = make_float2(y0, y1);
    if (oh)
        split2v(make_float2(y0, y1),
                reinterpret_cast<__half2*>(oh + base + 2 * tid),
                reinterpret_cast<__half2*>(ol + base + 2 * tid));
}

// ---------------- quantizer: 512 blocks x 32 rows, logits pre-scaled ---------
// kld term via closed form: sum(p*logp) = (sum e*t)/se - lse, t = lg - mx.
__global__ void __launch_bounds__(256) quant_kernel(const float* __restrict__ gum)
{
    __shared__ float s_avg[8][KCB];
    const int tid = threadIdx.x, lane = tid & 31, wid = tid >> 5;

    for (int j = tid; j < 8 * KCB; j += 256) (&s_avg[0][0])[j] = 0.f;
    __syncthreads();

    double kd = 0.0;
    const int row0 = blockIdx.x * 32;
    for (int r = wid; r < 32; r += 8) {
        const int row = row0 + r;
        const float* dp = g_dot + (size_t)row * KCB;
        const float* up = gum   + (size_t)row * KCB;

        // logits are final (pre-scaled in GEMM epilogue)
        float lg[32], e[32];
        float mx = -1e30f;
        #pragma unroll
        for (int q = 0; q < 16; q++) {
            int j = (q << 6) + (lane << 1);
            float2 d2 = *reinterpret_cast<const float2*>(dp + j);
            lg[2 * q] = d2.x; lg[2 * q + 1] = d2.y;
            mx = fmaxf(mx, fmaxf(d2.x, d2.y));
        }
        #pragma unroll
        for (int o = 16; o; o >>= 1) mx = fmaxf(mx, __shfl_xor_sync(0xffffffffu, mx, o));

        float se = 0.f, de = 0.f;
        #pragma unroll
        for (int q = 0; q < 32; q++) {
            float t = lg[q] - mx;
            float ee = __expf(t);
            e[q] = ee;
            se += ee;
            de += ee * t;
        }
        #pragma unroll
        for (int o = 16; o; o >>= 1) {
            se += __shfl_xor_sync(0xffffffffu, se, o);
            de += __shfl_xor_sync(0xffffffffu, de, o);
        }
        const float lse = __logf(se);
        const float inv = 1.f / se;
        if (!lane) kd += (double)(de * inv - lse);

        #pragma unroll
        for (int q = 0; q < 16; q++) {
            int j = (q << 6) + (lane << 1);
            s_avg[wid][j]     += e[2 * q]     * inv;
            s_avg[wid][j + 1] += e[2 * q + 1] * inv;
        }

        // gumbel-softmax
        float mx2 = -1e30f;
        #pragma unroll
        for (int q = 0; q < 16; q++) {
            int j = (q << 6) + (lane << 1);
            float2 u2 = *reinterpret_cast<const float2*>(up + j);
            float g0 = -__logf(-__logf(u2.x + 1e-10f) + 1e-10f);
            float g1 = -__logf(-__logf(u2.y + 1e-10f) + 1e-10f);
            float a0 = lg[2 * q] + g0, a1 = lg[2 * q + 1] + g1;
            lg[2 * q] = a0; lg[2 * q + 1] = a1;
            mx2 = fmaxf(mx2, fmaxf(a0, a1));
        }
        #pragma unroll
        for (int o = 16; o; o >>= 1) mx2 = fmaxf(mx2, __shfl_xor_sync(0xffffffffu, mx2, o));

        float s2 = 0.f;
        #pragma unroll
        for (int q = 0; q < 32; q++) { float ee = __expf(lg[q] - mx2); lg[q] = ee; s2 += ee; }
        #pragma unroll
        for (int o = 16; o; o >>= 1) s2 += __shfl_xor_sync(0xffffffffu, s2, o);
        const float inv2 = 1.f / s2;

        __half* eph = g_ah + (size_t)row * KCB;
        __half* epl = g_al + (size_t)row * KCB;
        #pragma unroll
        for (int q = 0; q < 16; q++) {
            int j = (q << 6) + (lane << 1);
            split2v(make_float2(lg[2 * q] * inv2, lg[2 * q + 1] * inv2),
                    reinterpret_cast<__half2*>(eph + j),
                    reinterpret_cast<__half2*>(epl + j));
        }
    }
    __syncthreads();

    for (int j = tid; j < KCB; j += 256) {
        float s = 0.f;
        #pragma unroll
        for (int ww = 0; ww < 8; ww++) s += s_avg[ww][j];
        atomicAdd(&g_avgp[j], s);
    }
    if (!lane) atomicAdd(&g_kldd, kd);
}

// ---------------- finalize ----------------------------------------------------
__global__ void __launch_bounds__(256) fin_kernel(
    const float* __restrict__ lpq, float* __restrict__ out)
{
    __shared__ double red[256];
    const int tid = threadIdx.x;
    double h = 0.0;
    for (int j = tid; j < KCB; j += 256) {
        float a = g_avgp[j] * (1.f / NTOK);
        h += (double)(a * __logf(a + 1e-7f));
    }
    red[tid] = h; __syncthreads();
    #pragma unroll
    for (int o = 128; o; o >>= 1) { if (tid < o) red[tid] += red[tid + o]; __syncthreads(); }
    if (!tid) {
        float w = 0.5f / fmaxf(__expf(lpq[0]), 1e-10f);
        double loss = g_kldd / (double)NB + g_kldc * (double)w / (double)NB;
        out[(size_t)NTOK * DDIM]     = (float)loss;
        out[(size_t)NTOK * DDIM + 1] = __expf((float)(-red[0]));
    }
}

// ---------------- launch ------------------------------------------------------
extern "C" void kernel_launch(void* const* d_in, const int* in_sizes, int n_in,
                              void* d_out, int out_size)
{
    (void)in_sizes; (void)n_in; (void)out_size;
    const float* x    = (const float*)d_in[0];
    const float* gum  = (const float*)d_in[1];
    const float* ew1  = (const float*)d_in[2];  const float* eb1  = (const float*)d_in[3];
    const float* eg1  = (const float*)d_in[4];  const float* ebe1 = (const float*)d_in[5];
    const float* ew2  = (const float*)d_in[6];  const float* eb2  = (const float*)d_in[7];
    const float* eg2  = (const float*)d_in[8];  const float* ebe2 = (const float*)d_in[9];
    const float* dw1  = (const float*)d_in[10]; const float* db1  = (const float*)d_in[11];
    const float* dg1  = (const float*)d_in[12]; const float* dbe1 = (const float*)d_in[13];
    const float* dw2  = (const float*)d_in[14]; const float* db2  = (const float*)d_in[15];
    const float* dg2  = (const float*)d_in[16]; const float* dbe2 = (const float*)d_in[17];
    const float* cb   = (const float*)d_in[18];
    const float* lpq  = (const float*)d_in[19];
    float* out = (float*)d_out;

    float *p_h, *p_z, *p_dot, *p_cc;
    __half *p_ah, *p_al, *p_qh, *p_ql, *p_wh, *p_wl, *p_cbh, *p_cbl, *p_cbth, *p_cbtl;
    cudaGetSymbolAddress((void**)&p_h,    g_h);
    cudaGetSymbolAddress((void**)&p_z,    g_z);
    cudaGetSymbolAddress((void**)&p_dot,  g_dot);
    cudaGetSymbolAddress((void**)&p_cc,   g_cc);
    cudaGetSymbolAddress((void**)&p_ah,   g_ah);
    cudaGetSymbolAddress((void**)&p_al,   g_al);
    cudaGetSymbolAddress((void**)&p_qh,   g_qh);
    cudaGetSymbolAddress((void**)&p_ql,   g_ql);
    cudaGetSymbolAddress((void**)&p_wh,   g_wh);
    cudaGetSymbolAddress((void**)&p_wl,   g_wl);
    cudaGetSymbolAddress((void**)&p_cbh,  g_cbh);
    cudaGetSymbolAddress((void**)&p_cbl,  g_cbl);
    cudaGetSymbolAddress((void**)&p_cbth, g_cbth);
    cudaGetSymbolAddress((void**)&p_cbtl, g_cbtl);

    const int SMEM3 = 2 * 49152;
    const int SMEM2 = 2 * 40960;
    cudaFuncSetAttribute(mma_gemm<3,1>, cudaFuncAttributeMaxDynamicSharedMemorySize, SMEM3);
    cudaFuncSetAttribute(mma_gemm<3,3>, cudaFuncAttributeMaxDynamicSharedMemorySize, SMEM3);
    cudaFuncSetAttribute(mma_gemm<2,1>, cudaFuncAttributeMaxDynamicSharedMemorySize, SMEM2);
    cudaFuncSetAttribute(mma_gemm<2,2>, cudaFuncAttributeMaxDynamicSharedMemorySize, SMEM2);

    const int WSZ = DDIM * DDIM;
    dim3 gD(DDIM / 64, NTOK / 128);   // (8, 128)
    dim3 gK(KCB  / 64, NTOK / 128);   // (16, 128)

    // 1: fused prep
    prep_kernel<<<4128, 256>>>(x, ew1, ew2, dw1, dw2, cb);

    // 2-5: encoder (3-term fp16)
    mma_gemm<3,1><<<gD, 256, SMEM3>>>(p_ah, p_al, p_wh + 0 * WSZ, p_wl + 0 * WSZ, eb1, p_h,
                                      nullptr, nullptr, nullptr, NTOK, DDIM, DDIM);
    ln_kernel<<<NTOK, 256>>>(p_h, eg1, ebe1, nullptr, p_ah, p_al);
    mma_gemm<3,1><<<gD, 256, SMEM3>>>(p_ah, p_al, p_wh + 1 * WSZ, p_wl + 1 * WSZ, eb2, p_h,
                                      nullptr, nullptr, nullptr, NTOK, DDIM, DDIM);
    ln_kernel<<<NTOK, 256>>>(p_h, eg2, ebe2, p_z, p_ah, p_al);

    // 6: quantizer logits GEMM (3-term, MODE 3: stores final scaled logits)
    mma_gemm<3,3><<<gK, 256, SMEM3>>>(p_ah, p_al, p_cbh, p_cbl, lpq, p_dot,
                                      p_cc, nullptr, nullptr, NTOK, KCB, DDIM);
    quant_kernel<<<512, 256>>>(gum);
    // 8: zq GEMM with fused sq epilogue
    mma_gemm<2,2><<<gD, 256, SMEM2>>>(p_ah, p_al, p_cbth, p_cbtl, nullptr, nullptr,
                                      p_z, p_qh, p_ql, NTOK, DDIM, KCB);

    // decoder: 2-term (A = zq splits)
    mma_gemm<2,1><<<gD, 256, SMEM2>>>(p_qh, p_ql, p_wh + 2 * WSZ, p_wl + 2 * WSZ, db1, p_h,
                                      nullptr, nullptr, nullptr, NTOK, DDIM, DDIM);
    ln_kernel<<<NTOK, 256>>>(p_h, dg1, dbe1, nullptr, p_ah, p_al);
    mma_gemm<2,1><<<gD, 256, SMEM2>>>(p_ah, p_al, p_wh + 3 * WSZ, p_wl + 3 * WSZ, db2, p_h,
                                      nullptr, nullptr, nullptr, NTOK, DDIM, DDIM);
    ln_kernel<<<NTOK, 256>>>(p_h, dg2, dbe2, out, nullptr, nullptr);

    fin_kernel<<<1, 256>>>(lpq, out);
}

// round 16
// speedup vs baseline: 1.3666x; 1.0082x over previous
#include <cuda_runtime.h>
#include <cuda_fp16.h>
#include <cstdint>
#include <cstddef>

#define NTOK 16384
#define DDIM 512
#define KCB  1024
#define NB   8

// ---------------- scratch (static device globals; no allocations) ----------
__device__ float g_h  [NTOK * DDIM];    // pre-LN MLP temp
__device__ float g_z  [NTOK * DDIM];    // encoder output (post-LN)
__device__ float g_dot[NTOK * KCB];     // pre-scaled logits  w*(2 z.c - |c|^2)
__device__ __align__(128) __half g_ah[NTOK * KCB];      // A-side split hi
__device__ __align__(128) __half g_al[NTOK * KCB];      // A-side split lo
__device__ __align__(128) __half g_qh[NTOK * DDIM];     // z_q split hi (decoder input)
__device__ __align__(128) __half g_ql[NTOK * DDIM];     // z_q split lo
__device__ __align__(128) __half g_wh[4 * DDIM * DDIM]; // transposed weights hi
__device__ __align__(128) __half g_wl[4 * DDIM * DDIM];
__device__ __align__(128) __half g_cbh [KCB * DDIM];    // codebook split (K-major rows)
__device__ __align__(128) __half g_cbl [KCB * DDIM];
__device__ __align__(128) __half g_cbth[DDIM * KCB];    // codebook^T split hi
__device__ __align__(128) __half g_cbtl[DDIM * KCB];
__device__ float  g_cc [KCB];
__device__ float  g_avgp[KCB];
__device__ double g_kldd;
__device__ double g_kldc;

// ---------------- PTX helpers ----------------------------------------------
__device__ __forceinline__ uint32_t smem_u32(const void* p) {
    uint32_t a;
    asm("{ .reg .u64 t; cvta.to.shared.u64 t, %1; cvt.u32.u64 %0, t; }"
        : "=r"(a) : "l"(p));
    return a;
}

#define CP_ASYNC16(s, g) \
    asm volatile("cp.async.cg.shared.global [%0], [%1], 16;" :: "r"(s), "l"(g))
#define CP_COMMIT() asm volatile("cp.async.commit_group;" ::: "memory")
#define CP_WAIT(n)  asm volatile("cp.async.wait_group %0;" :: "n"(n) : "memory")

#define LDSM4(r, addr) \
    asm volatile("ldmatrix.sync.aligned.m8n8.x4.shared.b16 {%0,%1,%2,%3}, [%4];" \
        : "=r"((r)[0]), "=r"((r)[1]), "=r"((r)[2]), "=r"((r)[3]) : "r"(addr) : "memory")

#define MMA_F16(D, A, B0, B1) \
    asm volatile("mma.sync.aligned.m16n8k16.row.col.f32.f16.f16.f32 " \
        "{%0,%1,%2,%3}, {%4,%5,%6,%7}, {%8,%9}, {%0,%1,%2,%3};" \
        : "+f"((D)[0]), "+f"((D)[1]), "+f"((D)[2]), "+f"((D)[3]) \
        : "r"((A)[0]), "r"((A)[1]), "r"((A)[2]), "r"((A)[3]), "r"(B0), "r"(B1))

__device__ __forceinline__ uint32_t sw128(uint32_t off) {
    return off ^ ((off >> 3) & 0x70);
}

__device__ __forceinline__ void split2(float v, __half* oh, __half* ol) {
    __half h = __float2half(v);
    *oh = h;
    *ol = __float2half(v - __half2float(h));
}
__device__ __forceinline__ void split2v(float2 v, __half2* oh, __half2* ol) {
    __half h0 = __float2half(v.x), h1 = __float2half(v.y);
    *oh = __halves2half2(h0, h1);
    *ol = __halves2half2(__float2half(v.x - __half2float(h0)),
                         __float2half(v.y - __half2float(h1)));
}

// ---------------- tile loaders (SW128 swizzled, 128B rows) -------------------
__device__ __forceinline__ void load_tileA(uint32_t tb, const __half* __restrict__ src,
                                           int r0, int k0, int K, int tid)
{
    #pragma unroll
    for (int i = 0; i < 4; i++) {
        int u = tid + (i << 8);
        int row = u >> 3, col8 = (u & 7) << 3;
        const __half* gp = src + (size_t)(r0 + row) * K + k0 + col8;
        uint32_t off = (uint32_t)((row << 7) + (col8 << 1));
        CP_ASYNC16(tb + sw128(off), gp);
    }
}
__device__ __forceinline__ void load_tileB(uint32_t tb, const __half* __restrict__ src,
                                           int r0, int k0, int K, int tid)
{
    #pragma unroll
    for (int i = 0; i < 2; i++) {
        int u = tid + (i << 8);
        int row = u >> 3, col8 = (u & 7) << 3;
        const __half* gp = src + (size_t)(r0 + row) * K + k0 + col8;
        uint32_t off = (uint32_t)((row << 7) + (col8 << 1));
        CP_ASYNC16(tb + sw128(off), gp);
    }
}

// ---------------- mma.sync fp16 GEMM -----------------------------------------
// Tile 128x64, 2 CTAs/SM, 2-stage pipeline. 8 warps 4x2, 32x32/warp.
// TERMS: 3 = Ah*Bh+Ah*Bl+Al*Bh, 2 = Ah*Bh+Al*Bh.
// MODE:  0 = plain fp32 store, 1 = bias+relu fp32 store,
//        2 = sq-epilogue (reads Z, accumulates sum((z-zq)^2), writes splits),
//        3 = logit epilogue (stores 2w*v - w*cc[col]; bias=lpq, Z=cc).
template<int TERMS, int MODE>
__global__ void __launch_bounds__(256, 2) mma_gemm(
    const __half* __restrict__ Ah, const __half* __restrict__ Al,
    const __half* __restrict__ Bh, const __half* __restrict__ Bl,
    const float* __restrict__ bias, float* __restrict__ C,
    const float* __restrict__ Z, __half* __restrict__ Qh, __half* __restrict__ Ql,
    int M, int N, int K)
{
    constexpr int STAGE = (TERMS == 3) ? 49152 : 40960;
    extern __shared__ char smem[];
    const int tid  = threadIdx.x;
    const int wid  = tid >> 5, lane = tid & 31;
    const int wm   = wid & 3, wn = wid >> 2;
    const uint32_t sb = smem_u32(smem);

    const int row0 = blockIdx.y << 7, col0 = blockIdx.x << 6;
    const int nk = K >> 6;

    float acc[2][4][4];
    #pragma unroll
    for (int i = 0; i < 2; i++)
        #pragma unroll
        for (int j = 0; j < 4; j++)
            #pragma unroll
            for (int r = 0; r < 4; r++) acc[i][j][r] = 0.f;

    const uint32_t a_row  = (uint32_t)(lane & 15);
    const uint32_t a_koff = (uint32_t)((lane >> 4) << 4);
    const uint32_t b_row  = (uint32_t)(((lane >> 4) << 3) + (lane & 7));
    const uint32_t b_koff = (uint32_t)(((lane >> 3) & 1) << 4);

    load_tileA(sb + 0,     Ah, row0, 0, K, tid);
    load_tileA(sb + 16384, Al, row0, 0, K, tid);
    load_tileB(sb + 32768, Bh, col0, 0, K, tid);
    if (TERMS == 3) load_tileB(sb + 40960, Bl, col0, 0, K, tid);
    CP_COMMIT();

    int buf = 0;
    for (int kt = 0; kt < nk; kt++) {
        if (kt + 1 < nk) {
            const int k0 = (kt + 1) << 6;
            const uint32_t st = sb + (buf ^ 1) * STAGE;
            load_tileA(st + 0,     Ah, row0, k0, K, tid);
            load_tileA(st + 16384, Al, row0, k0, K, tid);
            load_tileB(st + 32768, Bh, col0, k0, K, tid);
            if (TERMS == 3) load_tileB(st + 40960, Bl, col0, k0, K, tid);
            CP_COMMIT();
            CP_WAIT(1);
        } else {
            CP_WAIT(0);
        }
        __syncthreads();

        const uint32_t stA_h = sb + buf * STAGE;
        const uint32_t stA_l = stA_h + 16384;
        const uint32_t stB_h = stA_h + 32768;
        const uint32_t stB_l = stA_h + 40960;

        #pragma unroll
        for (int ks = 0; ks < 4; ks++) {
            const uint32_t k0b = (uint32_t)(ks << 5);
            uint32_t ah[2][4], al[2][4], bh[2][4], bl[2][4];
            #pragma unroll
            for (int mt = 0; mt < 2; mt++) {
                uint32_t off = ((uint32_t)(wm * 32 + mt * 16) + a_row) * 128 + k0b + a_koff;
                uint32_t s = sw128(off);
                LDSM4(ah[mt], stA_h + s);
                LDSM4(al[mt], stA_l + s);
            }
            #pragma unroll
            for (int np = 0; np < 2; np++) {
                uint32_t off = ((uint32_t)(wn * 32 + np * 16) + b_row) * 128 + k0b + b_koff;
                uint32_t s = sw128(off);
                LDSM4(bh[np], stB_h + s);
                if (TERMS == 3) LDSM4(bl[np], stB_l + s);
            }
            #pragma unroll
            for (int mt = 0; mt < 2; mt++) {
                #pragma unroll
                for (int nt = 0; nt < 4; nt++) {
                    const int np = nt >> 1, pr = (nt & 1) << 1;
                    MMA_F16(acc[mt][nt], ah[mt], bh[np][pr], bh[np][pr + 1]);
                    if (TERMS == 3)
                        MMA_F16(acc[mt][nt], ah[mt], bl[np][pr], bl[np][pr + 1]);
                    MMA_F16(acc[mt][nt], al[mt], bh[np][pr], bh[np][pr + 1]);
                }
            }
        }
        __syncthreads();
        buf ^= 1;
    }

    // epilogue
    const int erow = row0 + wm * 32 + (lane >> 2);
    const int ecol = col0 + wn * 32 + ((lane & 3) << 1);
    float sacc = 0.f;
    float wq = 0.f;
    if (MODE == 3) wq = 0.5f / fmaxf(__expf(bias[0]), 1e-10f);
    #pragma unroll
    for (int mt = 0; mt < 2; mt++) {
        #pragma unroll
        for (int nt = 0; nt < 4; nt++) {
            const int r0 = erow + mt * 16;
            const int c  = ecol + nt * 8;
            float v0 = acc[mt][nt][0], v1 = acc[mt][nt][1];
            float v2 = acc[mt][nt][2], v3 = acc[mt][nt][3];
            if (MODE == 1) {
                float b0 = bias[c], b1 = bias[c + 1];
                v0 = fmaxf(v0 + b0, 0.f); v1 = fmaxf(v1 + b1, 0.f);
                v2 = fmaxf(v2 + b0, 0.f); v3 = fmaxf(v3 + b1, 0.f);
            }
            if (MODE == 3) {
                float c0 = Z[c] * wq, c1 = Z[c + 1] * wq;
                float tw = 2.f * wq;
                v0 = tw * v0 - c0; v1 = tw * v1 - c1;
                v2 = tw * v2 - c0; v3 = tw * v3 - c1;
            }
            if (MODE == 2) {
                size_t i0 = (size_t)r0 * N + c, i1 = (size_t)(r0 + 8) * N + c;
                float2 z0 = *reinterpret_cast<const float2*>(Z + i0);
                float2 z1 = *reinterpret_cast<const float2*>(Z + i1);
                float d0 = z0.x - v0, d1 = z0.y - v1;
                float d2 = z1.x - v2, d3 = z1.y - v3;
                sacc += d0 * d0 + d1 * d1 + d2 * d2 + d3 * d3;
                split2v(make_float2(v0, v1),
                        reinterpret_cast<__half2*>(Qh + i0), reinterpret_cast<__half2*>(Ql + i0));
                split2v(make_float2(v2, v3),
                        reinterpret_cast<__half2*>(Qh + i1), reinterpret_cast<__half2*>(Ql + i1));
            } else {
                *reinterpret_cast<float2*>(C + (size_t)r0 * N + c)       = make_float2(v0, v1);
                *reinterpret_cast<float2*>(C + (size_t)(r0 + 8) * N + c) = make_float2(v2, v3);
            }
        }
    }
    if (MODE == 2) {
        #pragma unroll
        for (int o = 16; o; o >>= 1) sacc += __shfl_xor_sync(0xffffffffu, sacc, o);
        if (!lane) atomicAdd(&g_kldc, (double)sacc);
    }
}

// ---------------- fused prep: weight/cb transposes+splits, x split, norms ----
__global__ void __launch_bounds__(256) prep_kernel(
    const float* __restrict__ x,
    const float* __restrict__ ew1, const float* __restrict__ ew2,
    const float* __restrict__ dw1, const float* __restrict__ dw2,
    const float* __restrict__ cb)
{
    __shared__ float t[32][33];
    const int blk = blockIdx.x, tid = threadIdx.x;

    if (blk < 1536) {
        const float* in; __half *oh, *ol; int R, C, bx, by;
        if (blk < 1024) {
            int w = blk >> 8, idx = blk & 255;
            const float* ws[4] = {ew1, ew2, dw1, dw2};
            in = ws[w];
            oh = g_wh + (size_t)w * DDIM * DDIM;
            ol = g_wl + (size_t)w * DDIM * DDIM;
            R = DDIM; C = DDIM; bx = idx & 15; by = idx >> 4;
        } else {
            int idx = blk - 1024;
            in = cb; oh = g_cbth; ol = g_cbtl;
            R = KCB; C = DDIM; bx = idx & 15; by = idx >> 4;
        }
        const int txx = tid & 31, tyy = tid >> 5;
        #pragma unroll
        for (int i = tyy; i < 32; i += 8)
            t[i][txx] = in[(size_t)(by * 32 + i) * C + bx * 32 + txx];
        __syncthreads();
        #pragma unroll
        for (int i = tyy; i < 32; i += 8) {
            float v = t[txx][i];
            size_t o = (size_t)(bx * 32 + i) * R + by * 32 + txx;
            split2(v, oh + o, ol + o);
        }
    } else if (blk < 2048) {
        int lb = blk - 1536;
        const int n2 = (KCB * DDIM) >> 1;
        const float2* src = reinterpret_cast<const float2*>(cb);
        __half2* oh = reinterpret_cast<__half2*>(g_cbh);
        __half2* ol = reinterpret_cast<__half2*>(g_cbl);
        for (int i = lb * 256 + tid; i < n2; i += 512 * 256)
            split2v(src[i], oh + i, ol + i);
    } else if (blk < 4096) {
        int lb = blk - 2048;
        const int n2 = (NTOK * DDIM) >> 1;
        const float2* src = reinterpret_cast<const float2*>(x);
        __half2* oh = reinterpret_cast<__half2*>(g_ah);
        __half2* ol = reinterpret_cast<__half2*>(g_al);
        for (int i = lb * 256 + tid; i < n2; i += 2048 * 256)
            split2v(src[i], oh + i, ol + i);
    } else {
        int lb = blk - 4096;
        int lane = tid & 31, wrp = tid >> 5;
        int gw = lb * 8 + wrp;
        for (int r = gw; r < KCB; r += 256) {
            const float* p = cb + (size_t)r * DDIM;
            float s = 0.f;
            for (int i = lane; i < DDIM; i += 32) { float v = p[i]; s += v * v; }
            #pragma unroll
            for (int o = 16; o; o >>= 1) s += __shfl_xor_sync(0xffffffffu, s, o);
            if (!lane) g_cc[r] = s;
        }
        int g = lb * 256 + tid;
        if (g < KCB) g_avgp[g] = 0.f;
        if (g == 0) { g_kldd = 0.0; g_kldc = 0.0; }
    }
}

// ---------------- LayerNorm (row 512), vectorized ----------------------------
__global__ void __launch_bounds__(256) ln_kernel(
    const float* __restrict__ in, const float* __restrict__ g,
    const float* __restrict__ be, float* __restrict__ out,
    __half* __restrict__ oh, __half* __restrict__ ol)
{
    __shared__ float sm[8];
    const int row = blockIdx.x, tid = threadIdx.x;
    const int lane = tid & 31, wrp = tid >> 5;
    const size_t base = (size_t)row * DDIM;
    float2 xv = *reinterpret_cast<const float2*>(in + base + 2 * tid);

    float s = xv.x + xv.y;
    #pragma unroll
    for (int o = 16; o; o >>= 1) s += __shfl_xor_sync(0xffffffffu, s, o);
    if (!lane) sm[wrp] = s;
    __syncthreads();
    float mean = (sm[0] + sm[1] + sm[2] + sm[3] + sm[4] + sm[5] + sm[6] + sm[7]) * (1.f / DDIM);
    __syncthreads();

    float d0 = xv.x - mean, d1 = xv.y - mean;
    float v = d0 * d0 + d1 * d1;
    #pragma unroll
    for (int o = 16; o; o >>= 1) v += __shfl_xor_sync(0xffffffffu, v, o);
    if (!lane) sm[wrp] = v;
    __syncthreads();
    float rstd = rsqrtf((sm[0] + sm[1] + sm[2] + sm[3] + sm[4] + sm[5] + sm[6] + sm[7]) * (1.f / DDIM) + 1e-5f);

    float2 gv  = *reinterpret_cast<const float2*>(g  + 2 * tid);
    float2 bev = *reinterpret_cast<const float2*>(be + 2 * tid);
    float y0 = d0 * rstd * gv.x + bev.x;
    float y1 = d1 * rstd * gv.y + bev.y;
    if (out)
        *reinterpret_cast<float2*>(out + base + 2 * tid) = make_float2(y0, y1);
    if (oh)
        split2v(make_float2(y0, y1),
                reinterpret_cast<__half2*>(oh + base + 2 * tid),
                reinterpret_cast<__half2*>(ol + base + 2 * tid));
}

// ---------------- quantizer: 512 blocks x 32 rows ----------------------------
// kld term closed form: sum(p*logp) = (sum e*t)/se - lse, t = lg - mx.
// gumbel-softmax via identity exp(gn) = 1/(-log u):
//   encodings = normalize( e[q] / (-log(u+eps)+eps) )   (no 2nd exp/max pass)
__global__ void __launch_bounds__(256) quant_kernel(const float* __restrict__ gum)
{
    __shared__ float s_avg[8][KCB];
    const int tid = threadIdx.x, lane = tid & 31, wid = tid >> 5;

    for (int j = tid; j < 8 * KCB; j += 256) (&s_avg[0][0])[j] = 0.f;
    __syncthreads();

    double kd = 0.0;
    const int row0 = blockIdx.x * 32;
    for (int r = wid; r < 32; r += 8) {
        const int row = row0 + r;
        const float* dp = g_dot + (size_t)row * KCB;
        const float* up = gum   + (size_t)row * KCB;

        float lg[32];
        float mx = -1e30f;
        #pragma unroll
        for (int q = 0; q < 16; q++) {
            int j = (q << 6) + (lane << 1);
            float2 d2 = *reinterpret_cast<const float2*>(dp + j);
            lg[2 * q] = d2.x; lg[2 * q + 1] = d2.y;
            mx = fmaxf(mx, fmaxf(d2.x, d2.y));
        }
        #pragma unroll
        for (int o = 16; o; o >>= 1) mx = fmaxf(mx, __shfl_xor_sync(0xffffffffu, mx, o));

        float se = 0.f, de = 0.f;
        #pragma unroll
        for (int q = 0; q < 32; q++) {
            float t = lg[q] - mx;
            float ee = __expf(t);
            lg[q] = ee;                 // lg[] now holds e
            se += ee;
            de += ee * t;
        }
        #pragma unroll
        for (int o = 16; o; o >>= 1) {
            se += __shfl_xor_sync(0xffffffffu, se, o);
            de += __shfl_xor_sync(0xffffffffu, de, o);
        }
        const float lse = __logf(se);
        const float inv = 1.f / se;
        if (!lane) kd += (double)(de * inv - lse);

        #pragma unroll
        for (int q = 0; q < 16; q++) {
            int j = (q << 6) + (lane << 1);
            s_avg[wid][j]     += lg[2 * q]     * inv;
            s_avg[wid][j + 1] += lg[2 * q + 1] * inv;
        }

        // gumbel weights: num = e / (-log(u+eps)+eps)
        float s2 = 0.f;
        #pragma unroll
        for (int q = 0; q < 16; q++) {
            int j = (q << 6) + (lane << 1);
            float2 u2 = *reinterpret_cast<const float2*>(up + j);
            float w0 = -__logf(u2.x + 1e-10f) + 1e-10f;
            float w1 = -__logf(u2.y + 1e-10f) + 1e-10f;
            float n0 = __fdividef(lg[2 * q],     w0);
            float n1 = __fdividef(lg[2 * q + 1], w1);
            lg[2 * q] = n0; lg[2 * q + 1] = n1;
            s2 += n0 + n1;
        }
        #pragma unroll
        for (int o = 16; o; o >>= 1) s2 += __shfl_xor_sync(0xffffffffu, s2, o);
        const float inv2 = 1.f / s2;

        __half* eph = g_ah + (size_t)row * KCB;
        __half* epl = g_al + (size_t)row * KCB;
        #pragma unroll
        for (int q = 0; q < 16; q++) {
            int j = (q << 6) + (lane << 1);
            split2v(make_float2(lg[2 * q] * inv2, lg[2 * q + 1] * inv2),
                    reinterpret_cast<__half2*>(eph + j),
                    reinterpret_cast<__half2*>(epl + j));
        }
    }
    __syncthreads();

    for (int j = tid; j < KCB; j += 256) {
        float s = 0.f;
        #pragma unroll
        for (int ww = 0; ww < 8; ww++) s += s_avg[ww][j];
        atomicAdd(&g_avgp[j], s);
    }
    if (!lane) atomicAdd(&g_kldd, kd);
}

// ---------------- finalize ----------------------------------------------------
__global__ void __launch_bounds__(256) fin_kernel(
    const float* __restrict__ lpq, float* __restrict__ out)
{
    __shared__ double red[256];
    const int tid = threadIdx.x;
    double h = 0.0;
    for (int j = tid; j < KCB; j += 256) {
        float a = g_avgp[j] * (1.f / NTOK);
        h += (double)(a * __logf(a + 1e-7f));
    }
    red[tid] = h; __syncthreads();
    #pragma unroll
    for (int o = 128; o; o >>= 1) { if (tid < o) red[tid] += red[tid + o]; __syncthreads(); }
    if (!tid) {
        float w = 0.5f / fmaxf(__expf(lpq[0]), 1e-10f);
        double loss = g_kldd / (double)NB + g_kldc * (double)w / (double)NB;
        out[(size_t)NTOK * DDIM]     = (float)loss;
        out[(size_t)NTOK * DDIM + 1] = __expf((float)(-red[0]));
    }
}

// ---------------- launch ------------------------------------------------------
extern "C" void kernel_launch(void* const* d_in, const int* in_sizes, int n_in,
                              void* d_out, int out_size)
{
    (void)in_sizes; (void)n_in; (void)out_size;
    const float* x    = (const float*)d_in[0];
    const float* gum  = (const float*)d_in[1];
    const float* ew1  = (const float*)d_in[2];  const float* eb1  = (const float*)d_in[3];
    const float* eg1  = (const float*)d_in[4];  const float* ebe1 = (const float*)d_in[5];
    const float* ew2  = (const float*)d_in[6];  const float* eb2  = (const float*)d_in[7];
    const float* eg2  = (const float*)d_in[8];  const float* ebe2 = (const float*)d_in[9];
    const float* dw1  = (const float*)d_in[10]; const float* db1  = (const float*)d_in[11];
    const float* dg1  = (const float*)d_in[12]; const float* dbe1 = (const float*)d_in[13];
    const float* dw2  = (const float*)d_in[14]; const float* db2  = (const float*)d_in[15];
    const float* dg2  = (const float*)d_in[16]; const float* dbe2 = (const float*)d_in[17];
    const float* cb   = (const float*)d_in[18];
    const float* lpq  = (const float*)d_in[19];
    float* out = (float*)d_out;

    float *p_h, *p_z, *p_dot, *p_cc;
    __half *p_ah, *p_al, *p_qh, *p_ql, *p_wh, *p_wl, *p_cbh, *p_cbl, *p_cbth, *p_cbtl;
    cudaGetSymbolAddress((void**)&p_h,    g_h);
    cudaGetSymbolAddress((void**)&p_z,    g_z);
    cudaGetSymbolAddress((void**)&p_dot,  g_dot);
    cudaGetSymbolAddress((void**)&p_cc,   g_cc);
    cudaGetSymbolAddress((void**)&p_ah,   g_ah);
    cudaGetSymbolAddress((void**)&p_al,   g_al);
    cudaGetSymbolAddress((void**)&p_qh,   g_qh);
    cudaGetSymbolAddress((void**)&p_ql,   g_ql);
    cudaGetSymbolAddress((void**)&p_wh,   g_wh);
    cudaGetSymbolAddress((void**)&p_wl,   g_wl);
    cudaGetSymbolAddress((void**)&p_cbh,  g_cbh);
    cudaGetSymbolAddress((void**)&p_cbl,  g_cbl);
    cudaGetSymbolAddress((void**)&p_cbth, g_cbth);
    cudaGetSymbolAddress((void**)&p_cbtl, g_cbtl);

    const int SMEM3 = 2 * 49152;
    const int SMEM2 = 2 * 40960;
    cudaFuncSetAttribute(mma_gemm<3,1>, cudaFuncAttributeMaxDynamicSharedMemorySize, SMEM3);
    cudaFuncSetAttribute(mma_gemm<3,3>, cudaFuncAttributeMaxDynamicSharedMemorySize, SMEM3);
    cudaFuncSetAttribute(mma_gemm<2,1>, cudaFuncAttributeMaxDynamicSharedMemorySize, SMEM2);
    cudaFuncSetAttribute(mma_gemm<2,2>, cudaFuncAttributeMaxDynamicSharedMemorySize, SMEM2);

    const int WSZ = DDIM * DDIM;
    dim3 gD(DDIM / 64, NTOK / 128);   // (8, 128)
    dim3 gK(KCB  / 64, NTOK / 128);   // (16, 128)

    // 1: fused prep
    prep_kernel<<<4128, 256>>>(x, ew1, ew2, dw1, dw2, cb);

    // 2-5: encoder (3-term fp16)
    mma_gemm<3,1><<<gD, 256, SMEM3>>>(p_ah, p_al, p_wh + 0 * WSZ, p_wl + 0 * WSZ, eb1, p_h,
                                      nullptr, nullptr, nullptr, NTOK, DDIM, DDIM);
    ln_kernel<<<NTOK, 256>>>(p_h, eg1, ebe1, nullptr, p_ah, p_al);
    mma_gemm<3,1><<<gD, 256, SMEM3>>>(p_ah, p_al, p_wh + 1 * WSZ, p_wl + 1 * WSZ, eb2, p_h,
                                      nullptr, nullptr, nullptr, NTOK, DDIM, DDIM);
    ln_kernel<<<NTOK, 256>>>(p_h, eg2, ebe2, p_z, p_ah, p_al);

    // 6: quantizer logits GEMM (3-term, MODE 3: stores final scaled logits)
    mma_gemm<3,3><<<gK, 256, SMEM3>>>(p_ah, p_al, p_cbh, p_cbl, lpq, p_dot,
                                      p_cc, nullptr, nullptr, NTOK, KCB, DDIM);
    quant_kernel<<<512, 256>>>(gum);
    // 8: zq GEMM with fused sq epilogue
    mma_gemm<2,2><<<gD, 256, SMEM2>>>(p_ah, p_al, p_cbth, p_cbtl, nullptr, nullptr,
                                      p_z, p_qh, p_ql, NTOK, DDIM, KCB);

    // decoder: 2-term (A = zq splits)
    mma_gemm<2,1><<<gD, 256, SMEM2>>>(p_qh, p_ql, p_wh + 2 * WSZ, p_wl + 2 * WSZ, db1, p_h,
                                      nullptr, nullptr, nullptr, NTOK, DDIM, DDIM);
    ln_kernel<<<NTOK, 256>>>(p_h, dg1, dbe1, nullptr, p_ah, p_al);
    mma_gemm<2,1><<<gD, 256, SMEM2>>>(p_ah, p_al, p_wh + 3 * WSZ, p_wl + 3 * WSZ, db2, p_h,
                                      nullptr, nullptr, nullptr, NTOK, DDIM, DDIM);
    ln_kernel<<<NTOK, 256>>>(p_h, dg2, dbe2, out, nullptr, nullptr);

    fin_kernel<<<1, 256>>>(lpq, out);
}

// round 17
// speedup vs baseline: 1.4400x; 1.0537x over previous
#include <cuda_runtime.h>
#include <cuda_fp16.h>
#include <cstdint>
#include <cstddef>

#define NTOK 16384
#define DDIM 512
#define KCB  1024
#define NB   8

// ---------------- scratch (static device globals; no allocations) ----------
__device__ float g_h  [NTOK * DDIM];    // pre-LN MLP temp
__device__ float g_z  [NTOK * DDIM];    // encoder output (post-LN)
__device__ float g_dot[NTOK * KCB];     // pre-scaled logits  w*(2 z.c - |c|^2)
__device__ __align__(128) __half g_ah[NTOK * KCB];      // A-side split hi
__device__ __align__(128) __half g_al[NTOK * KCB];      // A-side split lo
__device__ __align__(128) __half g_qh[NTOK * DDIM];     // z_q split hi (decoder input)
__device__ __align__(128) __half g_ql[NTOK * DDIM];     // z_q split lo
__device__ __align__(128) __half g_wh[4 * DDIM * DDIM]; // transposed weights hi
__device__ __align__(128) __half g_wl[4 * DDIM * DDIM];
__device__ __align__(128) __half g_cbh [KCB * DDIM];    // codebook split (K-major rows)
__device__ __align__(128) __half g_cbl [KCB * DDIM];
__device__ __align__(128) __half g_cbth[DDIM * KCB];    // codebook^T split hi
__device__ __align__(128) __half g_cbtl[DDIM * KCB];
__device__ float  g_cc [KCB];
__device__ float  g_avgp[KCB];
__device__ double g_kldd;
__device__ double g_kldc;

// ---------------- PTX helpers ----------------------------------------------
__device__ __forceinline__ uint32_t smem_u32(const void* p) {
    uint32_t a;
    asm("{ .reg .u64 t; cvta.to.shared.u64 t, %1; cvt.u32.u64 %0, t; }"
        : "=r"(a) : "l"(p));
    return a;
}

#define CP_ASYNC16(s, g) \
    asm volatile("cp.async.cg.shared.global [%0], [%1], 16;" :: "r"(s), "l"(g))
#define CP_COMMIT() asm volatile("cp.async.commit_group;" ::: "memory")
#define CP_WAIT(n)  asm volatile("cp.async.wait_group %0;" :: "n"(n) : "memory")

#define LDSM4(r, addr) \
    asm volatile("ldmatrix.sync.aligned.m8n8.x4.shared.b16 {%0,%1,%2,%3}, [%4];" \
        : "=r"((r)[0]), "=r"((r)[1]), "=r"((r)[2]), "=r"((r)[3]) : "r"(addr) : "memory")

#define MMA_F16(D, A, B0, B1) \
    asm volatile("mma.sync.aligned.m16n8k16.row.col.f32.f16.f16.f32 " \
        "{%0,%1,%2,%3}, {%4,%5,%6,%7}, {%8,%9}, {%0,%1,%2,%3};" \
        : "+f"((D)[0]), "+f"((D)[1]), "+f"((D)[2]), "+f"((D)[3]) \
        : "r"((A)[0]), "r"((A)[1]), "r"((A)[2]), "r"((A)[3]), "r"(B0), "r"(B1))

__device__ __forceinline__ uint32_t sw128(uint32_t off) {
    return off ^ ((off >> 3) & 0x70);
}

__device__ __forceinline__ void split2(float v, __half* oh, __half* ol) {
    __half h = __float2half(v);
    *oh = h;
    *ol = __float2half(v - __half2float(h));
}
__device__ __forceinline__ void split2v(float2 v, __half2* oh, __half2* ol) {
    __half h0 = __float2half(v.x), h1 = __float2half(v.y);
    *oh = __halves2half2(h0, h1);
    *ol = __halves2half2(__float2half(v.x - __half2float(h0)),
                         __float2half(v.y - __half2float(h1)));
}

// ---------------- tile loaders (SW128 swizzled, 128B rows) -------------------
__device__ __forceinline__ void load_tileA(uint32_t tb, const __half* __restrict__ src,
                                           int r0, int k0, int K, int tid)
{
    #pragma unroll
    for (int i = 0; i < 4; i++) {
        int u = tid + (i << 8);
        int row = u >> 3, col8 = (u & 7) << 3;
        const __half* gp = src + (size_t)(r0 + row) * K + k0 + col8;
        uint32_t off = (uint32_t)((row << 7) + (col8 << 1));
        CP_ASYNC16(tb + sw128(off), gp);
    }
}
__device__ __forceinline__ void load_tileB(uint32_t tb, const __half* __restrict__ src,
                                           int r0, int k0, int K, int tid)
{
    #pragma unroll
    for (int i = 0; i < 2; i++) {
        int u = tid + (i << 8);
        int row = u >> 3, col8 = (u & 7) << 3;
        const __half* gp = src + (size_t)(r0 + row) * K + k0 + col8;
        uint32_t off = (uint32_t)((row << 7) + (col8 << 1));
        CP_ASYNC16(tb + sw128(off), gp);
    }
}

// ---------------- mma.sync fp16 GEMM -----------------------------------------
// Tile 128x64, 2 CTAs/SM, 2-stage pipeline. 8 warps 4x2, 32x32/warp.
// TERMS: 3 = Ah*Bh+Ah*Bl+Al*Bh, 2 = Ah*Bh+Al*Bh.
// MODE:  0 = plain fp32 store, 1 = bias+relu fp32 store,
//        2 = sq-epilogue (reads Z, accumulates sum((z-zq)^2), writes splits),
//        3 = logit epilogue (stores 2w*v - w*cc[col]; bias=lpq, Z=cc).
template<int TERMS, int MODE>
__global__ void __launch_bounds__(256, 2) mma_gemm(
    const __half* __restrict__ Ah, const __half* __restrict__ Al,
    const __half* __restrict__ Bh, const __half* __restrict__ Bl,
    const float* __restrict__ bias, float* __restrict__ C,
    const float* __restrict__ Z, __half* __restrict__ Qh, __half* __restrict__ Ql,
    int M, int N, int K)
{
    constexpr int STAGE = (TERMS == 3) ? 49152 : 40960;
    extern __shared__ char smem[];
    const int tid  = threadIdx.x;
    const int wid  = tid >> 5, lane = tid & 31;
    const int wm   = wid & 3, wn = wid >> 2;
    const uint32_t sb = smem_u32(smem);

    const int row0 = blockIdx.y << 7, col0 = blockIdx.x << 6;
    const int nk = K >> 6;

    float acc[2][4][4];
    #pragma unroll
    for (int i = 0; i < 2; i++)
        #pragma unroll
        for (int j = 0; j < 4; j++)
            #pragma unroll
            for (int r = 0; r < 4; r++) acc[i][j][r] = 0.f;

    const uint32_t a_row  = (uint32_t)(lane & 15);
    const uint32_t a_koff = (uint32_t)((lane >> 4) << 4);
    const uint32_t b_row  = (uint32_t)(((lane >> 4) << 3) + (lane & 7));
    const uint32_t b_koff = (uint32_t)(((lane >> 3) & 1) << 4);

    load_tileA(sb + 0,     Ah, row0, 0, K, tid);
    load_tileA(sb + 16384, Al, row0, 0, K, tid);
    load_tileB(sb + 32768, Bh, col0, 0, K, tid);
    if (TERMS == 3) load_tileB(sb + 40960, Bl, col0, 0, K, tid);
    CP_COMMIT();

    int buf = 0;
    for (int kt = 0; kt < nk; kt++) {
        if (kt + 1 < nk) {
            const int k0 = (kt + 1) << 6;
            const uint32_t st = sb + (buf ^ 1) * STAGE;
            load_tileA(st + 0,     Ah, row0, k0, K, tid);
            load_tileA(st + 16384, Al, row0, k0, K, tid);
            load_tileB(st + 32768, Bh, col0, k0, K, tid);
            if (TERMS == 3) load_tileB(st + 40960, Bl, col0, k0, K, tid);
            CP_COMMIT();
            CP_WAIT(1);
        } else {
            CP_WAIT(0);
        }
        __syncthreads();

        const uint32_t stA_h = sb + buf * STAGE;
        const uint32_t stA_l = stA_h + 16384;
        const uint32_t stB_h = stA_h + 32768;
        const uint32_t stB_l = stA_h + 40960;

        #pragma unroll
        for (int ks = 0; ks < 4; ks++) {
            const uint32_t k0b = (uint32_t)(ks << 5);
            uint32_t ah[2][4], al[2][4], bh[2][4], bl[2][4];
            #pragma unroll
            for (int mt = 0; mt < 2; mt++) {
                uint32_t off = ((uint32_t)(wm * 32 + mt * 16) + a_row) * 128 + k0b + a_koff;
                uint32_t s = sw128(off);
                LDSM4(ah[mt], stA_h + s);
                LDSM4(al[mt], stA_l + s);
            }
            #pragma unroll
            for (int np = 0; np < 2; np++) {
                uint32_t off = ((uint32_t)(wn * 32 + np * 16) + b_row) * 128 + k0b + b_koff;
                uint32_t s = sw128(off);
                LDSM4(bh[np], stB_h + s);
                if (TERMS == 3) LDSM4(bl[np], stB_l + s);
            }
            #pragma unroll
            for (int mt = 0; mt < 2; mt++) {
                #pragma unroll
                for (int nt = 0; nt < 4; nt++) {
                    const int np = nt >> 1, pr = (nt & 1) << 1;
                    MMA_F16(acc[mt][nt], ah[mt], bh[np][pr], bh[np][pr + 1]);
                    if (TERMS == 3)
                        MMA_F16(acc[mt][nt], ah[mt], bl[np][pr], bl[np][pr + 1]);
                    MMA_F16(acc[mt][nt], al[mt], bh[np][pr], bh[np][pr + 1]);
                }
            }
        }
        __syncthreads();
        buf ^= 1;
    }

    // epilogue
    const int erow = row0 + wm * 32 + (lane >> 2);
    const int ecol = col0 + wn * 32 + ((lane & 3) << 1);
    float sacc = 0.f;
    float wq = 0.f;
    if (MODE == 3) wq = 0.5f / fmaxf(__expf(bias[0]), 1e-10f);
    #pragma unroll
    for (int mt = 0; mt < 2; mt++) {
        #pragma unroll
        for (int nt = 0; nt < 4; nt++) {
            const int r0 = erow + mt * 16;
            const int c  = ecol + nt * 8;
            float v0 = acc[mt][nt][0], v1 = acc[mt][nt][1];
            float v2 = acc[mt][nt][2], v3 = acc[mt][nt][3];
            if (MODE == 1) {
                float b0 = bias[c], b1 = bias[c + 1];
                v0 = fmaxf(v0 + b0, 0.f); v1 = fmaxf(v1 + b1, 0.f);
                v2 = fmaxf(v2 + b0, 0.f); v3 = fmaxf(v3 + b1, 0.f);
            }
            if (MODE == 3) {
                float c0 = Z[c] * wq, c1 = Z[c + 1] * wq;
                float tw = 2.f * wq;
                v0 = tw * v0 - c0; v1 = tw * v1 - c1;
                v2 = tw * v2 - c0; v3 = tw * v3 - c1;
            }
            if (MODE == 2) {
                size_t i0 = (size_t)r0 * N + c, i1 = (size_t)(r0 + 8) * N + c;
                float2 z0 = *reinterpret_cast<const float2*>(Z + i0);
                float2 z1 = *reinterpret_cast<const float2*>(Z + i1);
                float d0 = z0.x - v0, d1 = z0.y - v1;
                float d2 = z1.x - v2, d3 = z1.y - v3;
                sacc += d0 * d0 + d1 * d1 + d2 * d2 + d3 * d3;
                split2v(make_float2(v0, v1),
                        reinterpret_cast<__half2*>(Qh + i0), reinterpret_cast<__half2*>(Ql + i0));
                split2v(make_float2(v2, v3),
                        reinterpret_cast<__half2*>(Qh + i1), reinterpret_cast<__half2*>(Ql + i1));
            } else {
                *reinterpret_cast<float2*>(C + (size_t)r0 * N + c)       = make_float2(v0, v1);
                *reinterpret_cast<float2*>(C + (size_t)(r0 + 8) * N + c) = make_float2(v2, v3);
            }
        }
    }
    if (MODE == 2) {
        #pragma unroll
        for (int o = 16; o; o >>= 1) sacc += __shfl_xor_sync(0xffffffffu, sacc, o);
        if (!lane) atomicAdd(&g_kldc, (double)sacc);
    }
}

// ---------------- fused prep: weight/cb transposes+splits, x split, norms ----
__global__ void __launch_bounds__(256) prep_kernel(
    const float* __restrict__ x,
    const float* __restrict__ ew1, const float* __restrict__ ew2,
    const float* __restrict__ dw1, const float* __restrict__ dw2,
    const float* __restrict__ cb)
{
    __shared__ float t[32][33];
    const int blk = blockIdx.x, tid = threadIdx.x;

    if (blk < 1536) {
        const float* in; __half *oh, *ol; int R, C, bx, by;
        if (blk < 1024) {
            int w = blk >> 8, idx = blk & 255;
            const float* ws[4] = {ew1, ew2, dw1, dw2};
            in = ws[w];
            oh = g_wh + (size_t)w * DDIM * DDIM;
            ol = g_wl + (size_t)w * DDIM * DDIM;
            R = DDIM; C = DDIM; bx = idx & 15; by = idx >> 4;
        } else {
            int idx = blk - 1024;
            in = cb; oh = g_cbth; ol = g_cbtl;
            R = KCB; C = DDIM; bx = idx & 15; by = idx >> 4;
        }
        const int txx = tid & 31, tyy = tid >> 5;
        #pragma unroll
        for (int i = tyy; i < 32; i += 8)
            t[i][txx] = in[(size_t)(by * 32 + i) * C + bx * 32 + txx];
        __syncthreads();
        #pragma unroll
        for (int i = tyy; i < 32; i += 8) {
            float v = t[txx][i];
            size_t o = (size_t)(bx * 32 + i) * R + by * 32 + txx;
            split2(v, oh + o, ol + o);
        }
    } else if (blk < 2048) {
        int lb = blk - 1536;
        const int n2 = (KCB * DDIM) >> 1;
        const float2* src = reinterpret_cast<const float2*>(cb);
        __half2* oh = reinterpret_cast<__half2*>(g_cbh);
        __half2* ol = reinterpret_cast<__half2*>(g_cbl);
        for (int i = lb * 256 + tid; i < n2; i += 512 * 256)
            split2v(src[i], oh + i, ol + i);
    } else if (blk < 4096) {
        int lb = blk - 2048;
        const int n2 = (NTOK * DDIM) >> 1;
        const float2* src = reinterpret_cast<const float2*>(x);
        __half2* oh = reinterpret_cast<__half2*>(g_ah);
        __half2* ol = reinterpret_cast<__half2*>(g_al);
        for (int i = lb * 256 + tid; i < n2; i += 2048 * 256)
            split2v(src[i], oh + i, ol + i);
    } else {
        int lb = blk - 4096;
        int lane = tid & 31, wrp = tid >> 5;
        int gw = lb * 8 + wrp;
        for (int r = gw; r < KCB; r += 256) {
            const float* p = cb + (size_t)r * DDIM;
            float s = 0.f;
            for (int i = lane; i < DDIM; i += 32) { float v = p[i]; s += v * v; }
            #pragma unroll
            for (int o = 16; o; o >>= 1) s += __shfl_xor_sync(0xffffffffu, s, o);
            if (!lane) g_cc[r] = s;
        }
        int g = lb * 256 + tid;
        if (g < KCB) g_avgp[g] = 0.f;
        if (g == 0) { g_kldd = 0.0; g_kldc = 0.0; }
    }
}

// ---------------- LayerNorm: 2 rows/block, float4, fused sum/sumsq -----------
// 256 threads: threads [0,128) handle row 2b, [128,256) row 2b+1.
// Each thread owns 4 consecutive elements (float4). var = E[x^2] - mean^2.
__global__ void __launch_bounds__(256) ln_kernel(
    const float* __restrict__ in, const float* __restrict__ g,
    const float* __restrict__ be, float* __restrict__ out,
    __half* __restrict__ oh, __half* __restrict__ ol)
{
    __shared__ float sm[2][4][2];   // [row-half][warp-in-group][sum, sumsq]
    const int tid = threadIdx.x;
    const int half = tid >> 7, t = tid & 127;
    const int lane = tid & 31, wg = (tid >> 5) & 3;
    const int row = blockIdx.x * 2 + half;
    const size_t base = (size_t)row * DDIM;

    float4 xv = *reinterpret_cast<const float4*>(in + base + 4 * t);

    float s  = xv.x + xv.y + xv.z + xv.w;
    float sq = xv.x * xv.x + xv.y * xv.y + xv.z * xv.z + xv.w * xv.w;
    #pragma unroll
    for (int o = 16; o; o >>= 1) {
        s  += __shfl_xor_sync(0xffffffffu, s,  o);
        sq += __shfl_xor_sync(0xffffffffu, sq, o);
    }
    if (!lane) { sm[half][wg][0] = s; sm[half][wg][1] = sq; }
    __syncthreads();
    float ts  = sm[half][0][0] + sm[half][1][0] + sm[half][2][0] + sm[half][3][0];
    float tsq = sm[half][0][1] + sm[half][1][1] + sm[half][2][1] + sm[half][3][1];
    float mean = ts * (1.f / DDIM);
    float var  = tsq * (1.f / DDIM) - mean * mean;
    float rstd = rsqrtf(var + 1e-5f);

    float4 gv  = *reinterpret_cast<const float4*>(g  + 4 * t);
    float4 bev = *reinterpret_cast<const float4*>(be + 4 * t);
    float y0 = (xv.x - mean) * rstd * gv.x + bev.x;
    float y1 = (xv.y - mean) * rstd * gv.y + bev.y;
    float y2 = (xv.z - mean) * rstd * gv.z + bev.z;
    float y3 = (xv.w - mean) * rstd * gv.w + bev.w;

    if (out)
        *reinterpret_cast<float4*>(out + base + 4 * t) = make_float4(y0, y1, y2, y3);
    if (oh) {
        __half2 h0, l0, h1, l1;
        split2v(make_float2(y0, y1), &h0, &l0);
        split2v(make_float2(y2, y3), &h1, &l1);
        *reinterpret_cast<__half2*>(oh + base + 4 * t)     = h0;
        *reinterpret_cast<__half2*>(oh + base + 4 * t + 2) = h1;
        *reinterpret_cast<__half2*>(ol + base + 4 * t)     = l0;
        *reinterpret_cast<__half2*>(ol + base + 4 * t + 2) = l1;
    }
}

// ---------------- quantizer: 512 blocks x 32 rows ----------------------------
// kld closed form: sum(p*logp) = (sum e*t)/se - lse;  gumbel via exp(gn)=1/(-log u)
__global__ void __launch_bounds__(256) quant_kernel(const float* __restrict__ gum)
{
    __shared__ float s_avg[8][KCB];
    const int tid = threadIdx.x, lane = tid & 31, wid = tid >> 5;

    for (int j = tid; j < 8 * KCB; j += 256) (&s_avg[0][0])[j] = 0.f;
    __syncthreads();

    double kd = 0.0;
    const int row0 = blockIdx.x * 32;
    for (int r = wid; r < 32; r += 8) {
        const int row = row0 + r;
        const float* dp = g_dot + (size_t)row * KCB;
        const float* up = gum   + (size_t)row * KCB;

        float lg[32];
        float mx = -1e30f;
        #pragma unroll
        for (int q = 0; q < 16; q++) {
            int j = (q << 6) + (lane << 1);
            float2 d2 = *reinterpret_cast<const float2*>(dp + j);
            lg[2 * q] = d2.x; lg[2 * q + 1] = d2.y;
            mx = fmaxf(mx, fmaxf(d2.x, d2.y));
        }
        #pragma unroll
        for (int o = 16; o; o >>= 1) mx = fmaxf(mx, __shfl_xor_sync(0xffffffffu, mx, o));

        float se = 0.f, de = 0.f;
        #pragma unroll
        for (int q = 0; q < 32; q++) {
            float t = lg[q] - mx;
            float ee = __expf(t);
            lg[q] = ee;
            se += ee;
            de += ee * t;
        }
        #pragma unroll
        for (int o = 16; o; o >>= 1) {
            se += __shfl_xor_sync(0xffffffffu, se, o);
            de += __shfl_xor_sync(0xffffffffu, de, o);
        }
        const float lse = __logf(se);
        const float inv = 1.f / se;
        if (!lane) kd += (double)(de * inv - lse);

        #pragma unroll
        for (int q = 0; q < 16; q++) {
            int j = (q << 6) + (lane << 1);
            s_avg[wid][j]     += lg[2 * q]     * inv;
            s_avg[wid][j + 1] += lg[2 * q + 1] * inv;
        }

        float s2 = 0.f;
        #pragma unroll
        for (int q = 0; q < 16; q++) {
            int j = (q << 6) + (lane << 1);
            float2 u2 = *reinterpret_cast<const float2*>(up + j);
            float w0 = -__logf(u2.x + 1e-10f) + 1e-10f;
            float w1 = -__logf(u2.y + 1e-10f) + 1e-10f;
            float n0 = __fdividef(lg[2 * q],     w0);
            float n1 = __fdividef(lg[2 * q + 1], w1);
            lg[2 * q] = n0; lg[2 * q + 1] = n1;
            s2 += n0 + n1;
        }
        #pragma unroll
        for (int o = 16; o; o >>= 1) s2 += __shfl_xor_sync(0xffffffffu, s2, o);
        const float inv2 = 1.f / s2;

        __half* eph = g_ah + (size_t)row * KCB;
        __half* epl = g_al + (size_t)row * KCB;
        #pragma unroll
        for (int q = 0; q < 16; q++) {
            int j = (q << 6) + (lane << 1);
            split2v(make_float2(lg[2 * q] * inv2, lg[2 * q + 1] * inv2),
                    reinterpret_cast<__half2*>(eph + j),
                    reinterpret_cast<__half2*>(epl + j));
        }
    }
    __syncthreads();

    for (int j = tid; j < KCB; j += 256) {
        float s = 0.f;
        #pragma unroll
        for (int ww = 0; ww < 8; ww++) s += s_avg[ww][j];
        atomicAdd(&g_avgp[j], s);
    }
    if (!lane) atomicAdd(&g_kldd, kd);
}

// ---------------- finalize ----------------------------------------------------
__global__ void __launch_bounds__(256) fin_kernel(
    const float* __restrict__ lpq, float* __restrict__ out)
{
    __shared__ double red[256];
    const int tid = threadIdx.x;
    double h = 0.0;
    for (int j = tid; j < KCB; j += 256) {
        float a = g_avgp[j] * (1.f / NTOK);
        h += (double)(a * __logf(a + 1e-7f));
    }
    red[tid] = h; __syncthreads();
    #pragma unroll
    for (int o = 128; o; o >>= 1) { if (tid < o) red[tid] += red[tid + o]; __syncthreads(); }
    if (!tid) {
        float w = 0.5f / fmaxf(__expf(lpq[0]), 1e-10f);
        double loss = g_kldd / (double)NB + g_kldc * (double)w / (double)NB;
        out[(size_t)NTOK * DDIM]     = (float)loss;
        out[(size_t)NTOK * DDIM + 1] = __expf((float)(-red[0]));
    }
}

// ---------------- launch ------------------------------------------------------
extern "C" void kernel_launch(void* const* d_in, const int* in_sizes, int n_in,
                              void* d_out, int out_size)
{
    (void)in_sizes; (void)n_in; (void)out_size;
    const float* x    = (const float*)d_in[0];
    const float* gum  = (const float*)d_in[1];
    const float* ew1  = (const float*)d_in[2];  const float* eb1  = (const float*)d_in[3];
    const float* eg1  = (const float*)d_in[4];  const float* ebe1 = (const float*)d_in[5];
    const float* ew2  = (const float*)d_in[6];  const float* eb2  = (const float*)d_in[7];
    const float* eg2  = (const float*)d_in[8];  const float* ebe2 = (const float*)d_in[9];
    const float* dw1  = (const float*)d_in[10]; const float* db1  = (const float*)d_in[11];
    const float* dg1  = (const float*)d_in[12]; const float* dbe1 = (const float*)d_in[13];
    const float* dw2  = (const float*)d_in[14]; const float* db2  = (const float*)d_in[15];
    const float* dg2  = (const float*)d_in[16]; const float* dbe2 = (const float*)d_in[17];
    const float* cb   = (const float*)d_in[18];
    const float* lpq  = (const float*)d_in[19];
    float* out = (float*)d_out;

    float *p_h, *p_z, *p_dot, *p_cc;
    __half *p_ah, *p_al, *p_qh, *p_ql, *p_wh, *p_wl, *p_cbh, *p_cbl, *p_cbth, *p_cbtl;
    cudaGetSymbolAddress((void**)&p_h,    g_h);
    cudaGetSymbolAddress((void**)&p_z,    g_z);
    cudaGetSymbolAddress((void**)&p_dot,  g_dot);
    cudaGetSymbolAddress((void**)&p_cc,   g_cc);
    cudaGetSymbolAddress((void**)&p_ah,   g_ah);
    cudaGetSymbolAddress((void**)&p_al,   g_al);
    cudaGetSymbolAddress((void**)&p_qh,   g_qh);
    cudaGetSymbolAddress((void**)&p_ql,   g_ql);
    cudaGetSymbolAddress((void**)&p_wh,   g_wh);
    cudaGetSymbolAddress((void**)&p_wl,   g_wl);
    cudaGetSymbolAddress((void**)&p_cbh,  g_cbh);
    cudaGetSymbolAddress((void**)&p_cbl,  g_cbl);
    cudaGetSymbolAddress((void**)&p_cbth, g_cbth);
    cudaGetSymbolAddress((void**)&p_cbtl, g_cbtl);

    const int SMEM3 = 2 * 49152;
    const int SMEM2 = 2 * 40960;
    cudaFuncSetAttribute(mma_gemm<3,1>, cudaFuncAttributeMaxDynamicSharedMemorySize, SMEM3);
    cudaFuncSetAttribute(mma_gemm<3,3>, cudaFuncAttributeMaxDynamicSharedMemorySize, SMEM3);
    cudaFuncSetAttribute(mma_gemm<2,1>, cudaFuncAttributeMaxDynamicSharedMemorySize, SMEM2);
    cudaFuncSetAttribute(mma_gemm<2,2>, cudaFuncAttributeMaxDynamicSharedMemorySize, SMEM2);

    const int WSZ = DDIM * DDIM;
    dim3 gD(DDIM / 64, NTOK / 128);   // (8, 128)
    dim3 gK(KCB  / 64, NTOK / 128);   // (16, 128)

    // 1: fused prep
    prep_kernel<<<4128, 256>>>(x, ew1, ew2, dw1, dw2, cb);

    // 2-5: encoder (3-term fp16)
    mma_gemm<3,1><<<gD, 256, SMEM3>>>(p_ah, p_al, p_wh + 0 * WSZ, p_wl + 0 * WSZ, eb1, p_h,
                                      nullptr, nullptr, nullptr, NTOK, DDIM, DDIM);
    ln_kernel<<<NTOK / 2, 256>>>(p_h, eg1, ebe1, nullptr, p_ah, p_al);
    mma_gemm<3,1><<<gD, 256, SMEM3>>>(p_ah, p_al, p_wh + 1 * WSZ, p_wl + 1 * WSZ, eb2, p_h,
                                      nullptr, nullptr, nullptr, NTOK, DDIM, DDIM);
    ln_kernel<<<NTOK / 2, 256>>>(p_h, eg2, ebe2, p_z, p_ah, p_al);

    // 6: quantizer logits GEMM (3-term, MODE 3: stores final scaled logits)
    mma_gemm<3,3><<<gK, 256, SMEM3>>>(p_ah, p_al, p_cbh, p_cbl, lpq, p_dot,
                                      p_cc, nullptr, nullptr, NTOK, KCB, DDIM);
    quant_kernel<<<512, 256>>>(gum);
    // 8: zq GEMM with fused sq epilogue
    mma_gemm<2,2><<<gD, 256, SMEM2>>>(p_ah, p_al, p_cbth, p_cbtl, nullptr, nullptr,
                                      p_z, p_qh, p_ql, NTOK, DDIM, KCB);

    // decoder: 2-term (A = zq splits)
    mma_gemm<2,1><<<gD, 256, SMEM2>>>(p_qh, p_ql, p_wh + 2 * WSZ, p_wl + 2 * WSZ, db1, p_h,
                                      nullptr, nullptr, nullptr, NTOK, DDIM, DDIM);
    ln_kernel<<<NTOK / 2, 256>>>(p_h, dg1, dbe1, nullptr, p_ah, p_al);
    mma_gemm<2,1><<<gD, 256, SMEM2>>>(p_ah, p_al, p_wh + 3 * WSZ, p_wl + 3 * WSZ, db2, p_h,
                                      nullptr, nullptr, nullptr, NTOK, DDIM, DDIM);
    ln_kernel<<<NTOK / 2, 256>>>(p_h, dg2, dbe2, out, nullptr, nullptr);

    fin_kernel<<<1, 256>>>(lpq, out);
}